// round 1
// baseline (speedup 1.0000x reference)
#include <cuda_runtime.h>
#include <math.h>

#define Bq 2
#define Lq 4096
#define Dq 1024
#define Hq 16
#define HDq 64
#define NCH 32
#define CH 128
#define BHL (Bq*Hq*Lq)

// ---------------- device scratch (no allocations allowed) ----------------
__device__ float g_q[Bq*Hq*Lq*HDq];
__device__ float g_k[Bq*Hq*Lq*HDq];
__device__ float g_v[Bq*Hq*Lq*HDq];
__device__ float g_beta[BHL];
__device__ float g_fd[BHL];
__device__ float g_sd[BHL];
__device__ float g_fg[BHL];
__device__ float g_sg[BHL];
__device__ float g_psi[BHL];
__device__ float g_sur[BHL];
__device__ float g_fdm[BHL];
__device__ float g_sdm[BHL];
__device__ float g_gf[Bq*Hq*NCH];
__device__ float g_gs[Bq*Hq*NCH];
__device__ float g_Af[Bq*Hq*NCH*HDq*HDq];
__device__ float g_As[Bq*Hq*NCH*HDq*HDq];
__device__ float g_omix[Bq*Lq*Dq];

__device__ __forceinline__ float sigm(float x) { return 1.f / (1.f + expf(-x)); }

// ---------------- K1/K7: 128x128x8 SIMT SGEMM ----------------
// A: [M,K] rm, W: [K,N] rm. doSilu: y*sigmoid(y). headOut: write [b,h,l,hd].
__global__ __launch_bounds__(256) void sgemm_kernel(
    const float* __restrict__ A, const float* __restrict__ W,
    float* __restrict__ C, int M, int N, int K, int doSilu, int headOut)
{
    __shared__ float As[8][128];
    __shared__ float Bs[8][128];
    const int tid = threadIdx.x;
    const int tx = tid & 15;
    const int ty = tid >> 4;
    const int bn = blockIdx.x * 128;
    const int bm = blockIdx.y * 128;

    float acc[8][8];
#pragma unroll
    for (int i = 0; i < 8; i++)
#pragma unroll
        for (int j = 0; j < 8; j++) acc[i][j] = 0.f;

    const int arow = tid >> 1;
    const int acol = (tid & 1) * 4;
    const int brow = tid >> 5;
    const int bcol = (tid & 31) * 4;

    const float* Ab = A + (size_t)bm * K;
    const float* Wb2 = W + bn;

    for (int k0 = 0; k0 < K; k0 += 8) {
        float4 a4 = *(const float4*)(Ab + (size_t)arow * K + k0 + acol);
        As[acol + 0][arow] = a4.x;
        As[acol + 1][arow] = a4.y;
        As[acol + 2][arow] = a4.z;
        As[acol + 3][arow] = a4.w;
        float4 b4 = *(const float4*)(Wb2 + (size_t)(k0 + brow) * N + bcol);
        *(float4*)(&Bs[brow][bcol]) = b4;
        __syncthreads();
#pragma unroll
        for (int kk = 0; kk < 8; kk++) {
            float4 a0 = *(float4*)(&As[kk][ty * 8]);
            float4 a1 = *(float4*)(&As[kk][ty * 8 + 4]);
            float4 b0 = *(float4*)(&Bs[kk][tx * 8]);
            float4 b1 = *(float4*)(&Bs[kk][tx * 8 + 4]);
            float a[8] = {a0.x, a0.y, a0.z, a0.w, a1.x, a1.y, a1.z, a1.w};
            float b[8] = {b0.x, b0.y, b0.z, b0.w, b1.x, b1.y, b1.z, b1.w};
#pragma unroll
            for (int i = 0; i < 8; i++)
#pragma unroll
                for (int j = 0; j < 8; j++) acc[i][j] += a[i] * b[j];
        }
        __syncthreads();
    }

#pragma unroll
    for (int i = 0; i < 8; i++) {
        int m = bm + ty * 8 + i;
        int bb = m >> 12;       // m / 4096
        int l = m & 4095;
#pragma unroll
        for (int j = 0; j < 8; j++) {
            int n = bn + tx * 8 + j;
            float v = acc[i][j];
            if (doSilu) v = v * (1.f / (1.f + expf(-v)));
            if (headOut) {
                int h = n >> 6, hd = n & 63;
                C[(((size_t)(bb * Hq + h) * Lq + l) * HDq) + hd] = v;
            } else {
                C[(size_t)m * N + n] = v;
            }
        }
    }
}

// ---------------- K2: small projections (5 x [D,16], m-tiled) ----------------
__global__ __launch_bounds__(256) void smallproj_kernel(
    const float* __restrict__ x,
    const float* __restrict__ Wbm, const float* __restrict__ Wfd,
    const float* __restrict__ fdb, const float* __restrict__ Wsd,
    const float* __restrict__ sdb, const float* __restrict__ Wfg,
    const float* __restrict__ Wsg)
{
    __shared__ float xs[32][128];
    __shared__ float Ws[32][80];
    const int tid = threadIdx.x;
    const int tx = tid & 15;
    const int ty = tid >> 4;
    const int m0 = blockIdx.x * 128;

    float acc[8][5];
#pragma unroll
    for (int i = 0; i < 8; i++)
#pragma unroll
        for (int j = 0; j < 5; j++) acc[i][j] = 0.f;

    for (int k0 = 0; k0 < 1024; k0 += 32) {
#pragma unroll
        for (int rr = 0; rr < 4; rr++) {
            int a = rr * 32 + (tid >> 3);
            int bcol = (tid & 7) * 4;
            float4 x4 = *(const float4*)(x + (size_t)(m0 + a) * 1024 + k0 + bcol);
            xs[bcol + 0][a] = x4.x;
            xs[bcol + 1][a] = x4.y;
            xs[bcol + 2][a] = x4.z;
            xs[bcol + 3][a] = x4.w;
        }
        for (int idx = tid; idx < 32 * 80; idx += 256) {
            int kk = idx / 80, n = idx % 80;
            int which = n >> 4, h = n & 15;
            const float* Wp = (which == 0) ? Wbm : (which == 1) ? Wfd
                             : (which == 2) ? Wsd : (which == 3) ? Wfg : Wsg;
            Ws[kk][n] = Wp[(k0 + kk) * 16 + h];
        }
        __syncthreads();
#pragma unroll
        for (int kk = 0; kk < 32; kk++) {
            float4 a0 = *(float4*)(&xs[kk][ty * 8]);
            float4 a1 = *(float4*)(&xs[kk][ty * 8 + 4]);
            float a[8] = {a0.x, a0.y, a0.z, a0.w, a1.x, a1.y, a1.z, a1.w};
            float b[5];
#pragma unroll
            for (int j = 0; j < 5; j++) b[j] = Ws[kk][tx * 5 + j];
#pragma unroll
            for (int i = 0; i < 8; i++)
#pragma unroll
                for (int j = 0; j < 5; j++) acc[i][j] += a[i] * b[j];
        }
        __syncthreads();
    }

#pragma unroll
    for (int i = 0; i < 8; i++) {
        int m = m0 + ty * 8 + i;
        int bb = m >> 12, l = m & 4095;
#pragma unroll
        for (int j = 0; j < 5; j++) {
            int n = tx * 5 + j;
            int which = n >> 4, h = n & 15;
            float s = acc[i][j];
            if (which == 1) s += fdb[h];
            if (which == 2) s += sdb[h];
            float val = sigm(s);
            float* dst = (which == 0) ? g_beta : (which == 1) ? g_fd
                        : (which == 2) ? g_sd : (which == 3) ? g_fg : g_sg;
            dst[(bb * Hq + h) * Lq + l] = val;
        }
    }
}

// ---------------- K3: per-position prep (beta scale, psi, surprise, decays) --
__global__ void prep_kernel()
{
    int gw = (blockIdx.x * blockDim.x + threadIdx.x) >> 5;
    int lane = threadIdx.x & 31;
    if (gw >= BHL) return;
    int p = gw;
    float beta = g_beta[p];
    float2 k2 = ((float2*)g_k)[p * 32 + lane];
    float2 v2 = ((float2*)g_v)[p * 32 + lane];
    k2.x *= beta; k2.y *= beta;
    v2.x *= beta; v2.y *= beta;
    float kk = k2.x * k2.x + k2.y * k2.y;
    float vv = v2.x * v2.x + v2.y * v2.y;
    float kv = k2.x * v2.x + k2.y * v2.y;
#pragma unroll
    for (int off = 16; off; off >>= 1) {
        kk += __shfl_xor_sync(0xffffffffu, kk, off);
        vv += __shfl_xor_sync(0xffffffffu, vv, off);
        kv += __shfl_xor_sync(0xffffffffu, kv, off);
    }
    ((float2*)g_k)[p * 32 + lane] = k2;
    ((float2*)g_v)[p * 32 + lane] = v2;
    if (lane == 0) {
        float kn = sqrtf(kk) + 1e-8f;
        float vn = sqrtf(vv) + 1e-8f;
        float praw = fabsf(kv) / (kn * vn);
        float psi = sigm(3.f * praw);
        float sur = sigm((psi - 0.5f) * 10.f);
        g_psi[p] = psi;
        g_sur[p] = sur;
        g_fdm[p] = g_fd[p] * (1.f - 0.1f * psi);
        g_sdm[p] = g_sd[p] * (1.f - 0.05f * psi);
    }
}

// ---------------- K3b: per-chunk decay means -> g = mean^128 ----------------
__global__ void chunkdecay_kernel()
{
    __shared__ float sf[4], ss[4];
    int bhn = blockIdx.x;
    int t = threadIdx.x;
    int base = (bhn / NCH) * Lq + (bhn % NCH) * CH;
    float f = g_fdm[base + t];
    float s = g_sdm[base + t];
#pragma unroll
    for (int off = 16; off; off >>= 1) {
        f += __shfl_xor_sync(0xffffffffu, f, off);
        s += __shfl_xor_sync(0xffffffffu, s, off);
    }
    int lane = t & 31, wid = t >> 5;
    if (lane == 0) { sf[wid] = f; ss[wid] = s; }
    __syncthreads();
    if (t == 0) {
        float mf = (sf[0] + sf[1] + sf[2] + sf[3]) * (1.f / 128.f);
        float ms = (ss[0] + ss[1] + ss[2] + ss[3]) * (1.f / 128.f);
        float gf = mf, gs = ms;
#pragma unroll
        for (int i = 0; i < 7; i++) { gf *= gf; gs *= gs; }   // mean^128 exact
        g_gf[bhn] = gf;
        g_gs[bhn] = gs;
    }
}

// ---------------- K4: per-chunk outer products (fast + slow fused) ----------
__global__ __launch_bounds__(256) void outer_kernel()
{
    __shared__ float Ks[64 * 64];
    __shared__ float Vs[64 * 64];
    __shared__ float S2[64];
    const int bhn = blockIdx.x;
    const int bh = bhn / NCH, n = bhn % NCH;
    const int t = threadIdx.x;
    const int d0 = (t & 15) * 4;
    const int e0 = (t >> 4) * 4;

    float af[4][4], as_[4][4];
#pragma unroll
    for (int i = 0; i < 4; i++)
#pragma unroll
        for (int j = 0; j < 4; j++) { af[i][j] = 0.f; as_[i][j] = 0.f; }

    for (int half = 0; half < 2; half++) {
        size_t base = ((size_t)bh * Lq + n * CH + half * 64) * HDq;
        for (int i = t; i < 1024; i += 256) {
            ((float4*)Ks)[i] = ((const float4*)(g_k + base))[i];
            ((float4*)Vs)[i] = ((const float4*)(g_v + base))[i];
        }
        if (t < 64) {
            float su = g_sur[bh * Lq + n * CH + half * 64 + t];
            S2[t] = su * su;
        }
        __syncthreads();
#pragma unroll 4
        for (int l = 0; l < 64; l++) {
            float4 vv = *(float4*)&Vs[l * 64 + d0];
            float4 kk = *(float4*)&Ks[l * 64 + e0];
            float s2 = S2[l];
            float v[4] = {vv.x, vv.y, vv.z, vv.w};
            float k[4] = {kk.x, kk.y, kk.z, kk.w};
            float vs[4] = {v[0] * s2, v[1] * s2, v[2] * s2, v[3] * s2};
#pragma unroll
            for (int i = 0; i < 4; i++)
#pragma unroll
                for (int j = 0; j < 4; j++) {
                    af[i][j] += v[i] * k[j];
                    as_[i][j] += vs[i] * k[j];
                }
        }
        __syncthreads();
    }

    size_t abase = (size_t)bhn * 4096;
#pragma unroll
    for (int i = 0; i < 4; i++) {
        *(float4*)&g_Af[abase + (d0 + i) * 64 + e0] =
            make_float4(af[i][0], af[i][1], af[i][2], af[i][3]);
        *(float4*)&g_As[abase + (d0 + i) * 64 + e0] =
            make_float4(as_[i][0], as_[i][1], as_[i][2], as_[i][3]);
    }
}

// ---------------- K5: decayed prefix scan over chunks (in-place) ------------
__global__ void scan_kernel()
{
    int bh = blockIdx.x >> 4;
    int eb = blockIdx.x & 15;
    int entry = eb * 256 + threadIdx.x;
    float sfv = 0.f, ssv = 0.f;
#pragma unroll 1
    for (int n = 0; n < NCH; n++) {
        int bhn = bh * NCH + n;
        float gf = g_gf[bhn], gs = g_gs[bhn];
        size_t idx = (size_t)bhn * 4096 + entry;
        sfv = sfv * gf + g_Af[idx]; g_Af[idx] = sfv;
        ssv = ssv * gs + g_As[idx]; g_As[idx] = ssv;
    }
}

// ---------------- K6: O = Q @ S (fast+slow), gate/alpha mix -> omix ---------
__global__ __launch_bounds__(256) void outmix_kernel()
{
    __shared__ float Sf[4096];
    __shared__ float Ss[4096];
    __shared__ float Qs[32 * 64];
    __shared__ float gA[32], gB[32];
    const int bhn = blockIdx.x;
    const int bh = bhn / NCH, n = bhn % NCH;
    const int b = bh >> 4, h = bh & 15;
    const int t = threadIdx.x;

    size_t abase = (size_t)bhn * 4096;
    for (int i = t; i < 1024; i += 256) {
        ((float4*)Sf)[i] = ((const float4*)(g_Af + abase))[i];
        ((float4*)Ss)[i] = ((const float4*)(g_As + abase))[i];
    }

    const int d = t & 63;
    const int lb = (t >> 6) * 8;

    for (int pass = 0; pass < 4; pass++) {
        int l0 = pass * 32;
        size_t qbase = ((size_t)bh * Lq + n * CH + l0) * HDq;
        for (int i = t; i < 512; i += 256)
            ((float4*)Qs)[i] = ((const float4*)(g_q + qbase))[i];
        if (t < 32) {
            int p = bh * Lq + n * CH + l0 + t;
            float psi = g_psi[p];
            float alpha = 0.5f + 0.3f * psi;
            gA[t] = alpha * g_fg[p];
            gB[t] = (1.f - alpha) * g_sg[p];
        }
        __syncthreads();

        float accf[8], accs[8];
#pragma unroll
        for (int l = 0; l < 8; l++) { accf[l] = 0.f; accs[l] = 0.f; }
#pragma unroll 8
        for (int e = 0; e < 64; e += 2) {
            float sf0 = Sf[e * 64 + d];
            float sf1 = Sf[(e + 1) * 64 + d];
            float ss0 = Ss[e * 64 + d];
            float ss1 = Ss[(e + 1) * 64 + d];
#pragma unroll
            for (int l = 0; l < 8; l++) {
                float2 q2 = *(float2*)&Qs[(lb + l) * 64 + e];
                accf[l] += q2.x * sf0 + q2.y * sf1;
                accs[l] += q2.x * ss0 + q2.y * ss1;
            }
        }
#pragma unroll
        for (int l = 0; l < 8; l++) {
            int ll = lb + l;
            float val = gA[ll] * accf[l] + gB[ll] * accs[l];
            int lglob = n * CH + l0 + ll;
            g_omix[((size_t)b * Lq + lglob) * Dq + h * HDq + d] = val;
        }
        __syncthreads();
    }
}

// ---------------- launch ----------------
extern "C" void kernel_launch(void* const* d_in, const int* in_sizes, int n_in,
                              void* d_out, int out_size)
{
    const float* x   = (const float*)d_in[0];
    const float* Wq  = (const float*)d_in[1];
    const float* Wk  = (const float*)d_in[2];
    const float* Wv  = (const float*)d_in[3];
    const float* Wb  = (const float*)d_in[4];
    const float* Wfd = (const float*)d_in[5];
    const float* fdb = (const float*)d_in[6];
    const float* Wsd = (const float*)d_in[7];
    const float* sdb = (const float*)d_in[8];
    const float* Wfg = (const float*)d_in[9];
    const float* Wsg = (const float*)d_in[10];
    const float* Wo  = (const float*)d_in[11];
    float* out = (float*)d_out;

    void* p_q = nullptr; void* p_k = nullptr; void* p_v = nullptr; void* p_omix = nullptr;
    cudaGetSymbolAddress(&p_q, g_q);
    cudaGetSymbolAddress(&p_k, g_k);
    cudaGetSymbolAddress(&p_v, g_v);
    cudaGetSymbolAddress(&p_omix, g_omix);

    const int M = Bq * Lq;           // 8192
    dim3 gemmGrid(Dq / 128, M / 128);  // (8, 64)

    // K1: q, k, v projections (silu, head layout)
    sgemm_kernel<<<gemmGrid, 256>>>(x, Wq, (float*)p_q, M, Dq, Dq, 1, 1);
    sgemm_kernel<<<gemmGrid, 256>>>(x, Wk, (float*)p_k, M, Dq, Dq, 1, 1);
    sgemm_kernel<<<gemmGrid, 256>>>(x, Wv, (float*)p_v, M, Dq, Dq, 1, 1);

    // K2: gate projections
    smallproj_kernel<<<M / 128, 256>>>(x, Wb, Wfd, fdb, Wsd, sdb, Wfg, Wsg);

    // K3: beta scaling + psi/surprise/decay-mod
    prep_kernel<<<(BHL * 32) / 256, 256>>>();

    // K3b: per-chunk decay factors
    chunkdecay_kernel<<<Bq * Hq * NCH, 128>>>();

    // K4: per-chunk outer products (fast + slow)
    outer_kernel<<<Bq * Hq * NCH, 256>>>();

    // K5: decayed scan across chunks
    scan_kernel<<<Bq * Hq * 16, 256>>>();

    // K6: per-chunk output + gate mixing
    outmix_kernel<<<Bq * Hq * NCH, 256>>>();

    // K7: output projection
    sgemm_kernel<<<gemmGrid, 256>>>((const float*)p_omix, Wo, out, M, Dq, Dq, 0, 0);
}

// round 2
// speedup vs baseline: 2.0575x; 2.0575x over previous
#include <cuda_runtime.h>
#include <math.h>
#include <stdint.h>

#define Bq 2
#define Lq 4096
#define Dq 1024
#define Hq 16
#define HDq 64
#define NCH 32
#define CH 128
#define BHL (Bq*Hq*Lq)

// ---------------- device scratch (no allocations allowed) ----------------
__device__ float g_q[Bq*Hq*Lq*HDq];
__device__ float g_k[Bq*Hq*Lq*HDq];
__device__ float g_v[Bq*Hq*Lq*HDq];
__device__ float g_beta[BHL];
__device__ float g_fd[BHL];
__device__ float g_sd[BHL];
__device__ float g_fg[BHL];
__device__ float g_sg[BHL];
__device__ float g_psi[BHL];
__device__ float g_sur[BHL];
__device__ float g_fdm[BHL];
__device__ float g_sdm[BHL];
__device__ float g_gf[Bq*Hq*NCH];
__device__ float g_gs[Bq*Hq*NCH];
__device__ float g_Af[Bq*Hq*NCH*HDq*HDq];
__device__ float g_As[Bq*Hq*NCH*HDq*HDq];
__device__ float g_omix[Bq*Lq*Dq];

__device__ __forceinline__ float sigm(float x) { return 1.f / (1.f + expf(-x)); }

__device__ __forceinline__ float to_tf32(float x) {
    uint32_t u;
    asm("cvt.rna.tf32.f32 %0, %1;" : "=r"(u) : "f"(x));
    return __uint_as_float(u);
}

__device__ __forceinline__ void mma_tf32(
    float& c0, float& c1, float& c2, float& c3,
    uint32_t a0, uint32_t a1, uint32_t a2, uint32_t a3,
    uint32_t b0, uint32_t b1)
{
    asm volatile(
        "mma.sync.aligned.m16n8k8.row.col.f32.tf32.tf32.f32 "
        "{%0,%1,%2,%3}, {%4,%5,%6,%7}, {%8,%9}, {%0,%1,%2,%3};"
        : "+f"(c0), "+f"(c1), "+f"(c2), "+f"(c3)
        : "r"(a0), "r"(a1), "r"(a2), "r"(a3), "r"(b0), "r"(b1));
}

// ---------------- K1/K7: TF32 tensor-core GEMM, 128x128 tile, K-step 32 -----
// A: [M,1024] rm, W: [1024,1024] rm. doSilu: y*sigmoid(y). headOut: [b,h,l,hd].
__global__ __launch_bounds__(256) void sgemm_tf32_kernel(
    const float* __restrict__ A, const float* __restrict__ W,
    float* __restrict__ C, int doSilu, int headOut)
{
    __shared__ float As[32][136];   // [k][m], tf32 values
    __shared__ float Bs[32][136];   // [k][n], tf32 values
    const int tid = threadIdx.x;
    const int lane = tid & 31;
    const int wid = tid >> 5;
    const int gid = lane >> 2;      // 0..7
    const int tig = lane & 3;       // 0..3
    const int warpM = (wid & 3) * 32;
    const int warpN = (wid >> 2) * 64;
    const int bn = blockIdx.x * 128;
    const int bm = blockIdx.y * 128;

    float acc[2][8][4];
#pragma unroll
    for (int mt = 0; mt < 2; mt++)
#pragma unroll
        for (int nt = 0; nt < 8; nt++)
#pragma unroll
            for (int c = 0; c < 4; c++) acc[mt][nt][c] = 0.f;

    for (int k0 = 0; k0 < 1024; k0 += 32) {
        // A tile: 128 rows x 32 k  (transpose into As[k][m])
#pragma unroll
        for (int i = 0; i < 4; i++) {
            int idx = tid + i * 256;            // 0..1023 float4 index
            int r = idx >> 3;                   // row 0..127
            int kc = (idx & 7) * 4;             // k offset 0..28
            float4 a4 = *(const float4*)(A + (size_t)(bm + r) * 1024 + k0 + kc);
            As[kc + 0][r] = to_tf32(a4.x);
            As[kc + 1][r] = to_tf32(a4.y);
            As[kc + 2][r] = to_tf32(a4.z);
            As[kc + 3][r] = to_tf32(a4.w);
        }
        // B tile: 32 k rows x 128 n
#pragma unroll
        for (int i = 0; i < 4; i++) {
            int idx = tid + i * 256;
            int kr = idx >> 5;                  // k 0..31
            int nc = (idx & 31) * 4;            // n offset
            float4 b4 = *(const float4*)(W + (size_t)(k0 + kr) * 1024 + bn + nc);
            float4 t4 = make_float4(to_tf32(b4.x), to_tf32(b4.y), to_tf32(b4.z), to_tf32(b4.w));
            *(float4*)(&Bs[kr][nc]) = t4;
        }
        __syncthreads();

#pragma unroll
        for (int kk = 0; kk < 4; kk++) {
            const int kb = kk * 8;
            uint32_t af[2][4];
#pragma unroll
            for (int mt = 0; mt < 2; mt++) {
                int m = warpM + mt * 16;
                af[mt][0] = __float_as_uint(As[kb + tig][m + gid]);
                af[mt][1] = __float_as_uint(As[kb + tig][m + gid + 8]);
                af[mt][2] = __float_as_uint(As[kb + tig + 4][m + gid]);
                af[mt][3] = __float_as_uint(As[kb + tig + 4][m + gid + 8]);
            }
#pragma unroll
            for (int nt = 0; nt < 8; nt++) {
                int n = warpN + nt * 8;
                uint32_t b0 = __float_as_uint(Bs[kb + tig][n + gid]);
                uint32_t b1 = __float_as_uint(Bs[kb + tig + 4][n + gid]);
#pragma unroll
                for (int mt = 0; mt < 2; mt++) {
                    mma_tf32(acc[mt][nt][0], acc[mt][nt][1], acc[mt][nt][2], acc[mt][nt][3],
                             af[mt][0], af[mt][1], af[mt][2], af[mt][3], b0, b1);
                }
            }
        }
        __syncthreads();
    }

    // epilogue: c0,c1 -> (row, col..col+1); c2,c3 -> (row+8, col..col+1)
#pragma unroll
    for (int mt = 0; mt < 2; mt++) {
#pragma unroll
        for (int nt = 0; nt < 8; nt++) {
            int row = bm + warpM + mt * 16 + gid;
            int col = bn + warpN + nt * 8 + tig * 2;
#pragma unroll
            for (int half = 0; half < 2; half++) {
                int r = row + half * 8;
                float v0 = acc[mt][nt][half * 2 + 0];
                float v1 = acc[mt][nt][half * 2 + 1];
                if (doSilu) {
                    v0 = v0 * (1.f / (1.f + expf(-v0)));
                    v1 = v1 * (1.f / (1.f + expf(-v1)));
                }
                if (headOut) {
                    int bb = r >> 12, l = r & 4095;
                    int h = col >> 6, hd = col & 63;
                    float2* dst = (float2*)(C + (((size_t)(bb * Hq + h) * Lq + l) * HDq) + hd);
                    *dst = make_float2(v0, v1);
                } else {
                    *(float2*)(C + (size_t)r * 1024 + col) = make_float2(v0, v1);
                }
            }
        }
    }
}

// ---------------- K2: small projections (5 x [D,16]), M=32 tile -------------
__global__ __launch_bounds__(256) void smallproj_kernel(
    const float* __restrict__ x,
    const float* __restrict__ Wbm, const float* __restrict__ Wfd,
    const float* __restrict__ fdb, const float* __restrict__ Wsd,
    const float* __restrict__ sdb, const float* __restrict__ Wfg,
    const float* __restrict__ Wsg)
{
    __shared__ float xs[64][33];    // [k][m]
    __shared__ float Ws[64][80];
    const int tid = threadIdx.x;
    const int tx = tid & 15;        // 5 outputs each
    const int ty = tid >> 4;        // rows ty, ty+16
    const int m0 = blockIdx.x * 32;

    float acc[2][5];
#pragma unroll
    for (int i = 0; i < 2; i++)
#pragma unroll
        for (int j = 0; j < 5; j++) acc[i][j] = 0.f;

    for (int k0 = 0; k0 < 1024; k0 += 64) {
        // x tile: 32 rows x 64 k -> xs[k][m]
#pragma unroll
        for (int i = 0; i < 2; i++) {
            int idx = tid + i * 256;            // 0..511 float4 idx
            int r = idx >> 4;                   // 0..31
            int kc = (idx & 15) * 4;            // 0..60
            float4 x4 = *(const float4*)(x + (size_t)(m0 + r) * 1024 + k0 + kc);
            xs[kc + 0][r] = x4.x;
            xs[kc + 1][r] = x4.y;
            xs[kc + 2][r] = x4.z;
            xs[kc + 3][r] = x4.w;
        }
        // W tile: 64 k x 80 outputs
        for (int idx = tid; idx < 64 * 80; idx += 256) {
            int kk = idx / 80, n = idx % 80;
            int which = n >> 4, h = n & 15;
            const float* Wp = (which == 0) ? Wbm : (which == 1) ? Wfd
                             : (which == 2) ? Wsd : (which == 3) ? Wfg : Wsg;
            Ws[kk][n] = Wp[(k0 + kk) * 16 + h];
        }
        __syncthreads();
#pragma unroll 8
        for (int kk = 0; kk < 64; kk++) {
            float x0 = xs[kk][ty];
            float x1 = xs[kk][ty + 16];
#pragma unroll
            for (int j = 0; j < 5; j++) {
                float w = Ws[kk][tx * 5 + j];
                acc[0][j] += x0 * w;
                acc[1][j] += x1 * w;
            }
        }
        __syncthreads();
    }

#pragma unroll
    for (int i = 0; i < 2; i++) {
        int m = m0 + ty + i * 16;
        int bb = m >> 12, l = m & 4095;
#pragma unroll
        for (int j = 0; j < 5; j++) {
            int n = tx * 5 + j;
            int which = n >> 4, h = n & 15;
            float s = acc[i][j];
            if (which == 1) s += fdb[h];
            if (which == 2) s += sdb[h];
            float val = sigm(s);
            float* dst = (which == 0) ? g_beta : (which == 1) ? g_fd
                        : (which == 2) ? g_sd : (which == 3) ? g_fg : g_sg;
            dst[(bb * Hq + h) * Lq + l] = val;
        }
    }
}

// ---------------- K3: per-position prep (beta scale, psi, surprise, decays) --
__global__ void prep_kernel()
{
    int gw = (blockIdx.x * blockDim.x + threadIdx.x) >> 5;
    int lane = threadIdx.x & 31;
    if (gw >= BHL) return;
    int p = gw;
    float beta = g_beta[p];
    float2 k2 = ((float2*)g_k)[p * 32 + lane];
    float2 v2 = ((float2*)g_v)[p * 32 + lane];
    k2.x *= beta; k2.y *= beta;
    v2.x *= beta; v2.y *= beta;
    float kk = k2.x * k2.x + k2.y * k2.y;
    float vv = v2.x * v2.x + v2.y * v2.y;
    float kv = k2.x * v2.x + k2.y * v2.y;
#pragma unroll
    for (int off = 16; off; off >>= 1) {
        kk += __shfl_xor_sync(0xffffffffu, kk, off);
        vv += __shfl_xor_sync(0xffffffffu, vv, off);
        kv += __shfl_xor_sync(0xffffffffu, kv, off);
    }
    ((float2*)g_k)[p * 32 + lane] = k2;
    ((float2*)g_v)[p * 32 + lane] = v2;
    if (lane == 0) {
        float kn = sqrtf(kk) + 1e-8f;
        float vn = sqrtf(vv) + 1e-8f;
        float praw = fabsf(kv) / (kn * vn);
        float psi = sigm(3.f * praw);
        float sur = sigm((psi - 0.5f) * 10.f);
        g_psi[p] = psi;
        g_sur[p] = sur;
        g_fdm[p] = g_fd[p] * (1.f - 0.1f * psi);
        g_sdm[p] = g_sd[p] * (1.f - 0.05f * psi);
    }
}

// ---------------- K3b: per-chunk decay means -> g = mean^128 ----------------
__global__ void chunkdecay_kernel()
{
    __shared__ float sf[4], ss[4];
    int bhn = blockIdx.x;
    int t = threadIdx.x;
    int base = (bhn / NCH) * Lq + (bhn % NCH) * CH;
    float f = g_fdm[base + t];
    float s = g_sdm[base + t];
#pragma unroll
    for (int off = 16; off; off >>= 1) {
        f += __shfl_xor_sync(0xffffffffu, f, off);
        s += __shfl_xor_sync(0xffffffffu, s, off);
    }
    int lane = t & 31, wid = t >> 5;
    if (lane == 0) { sf[wid] = f; ss[wid] = s; }
    __syncthreads();
    if (t == 0) {
        float mf = (sf[0] + sf[1] + sf[2] + sf[3]) * (1.f / 128.f);
        float ms = (ss[0] + ss[1] + ss[2] + ss[3]) * (1.f / 128.f);
        float gf = mf, gs = ms;
#pragma unroll
        for (int i = 0; i < 7; i++) { gf *= gf; gs *= gs; }   // mean^128 exact
        g_gf[bhn] = gf;
        g_gs[bhn] = gs;
    }
}

// ---------------- K4: per-chunk outer products (fast + slow fused) ----------
__global__ __launch_bounds__(256) void outer_kernel()
{
    __shared__ float Ks[64 * 64];
    __shared__ float Vs[64 * 64];
    __shared__ float S2[64];
    const int bhn = blockIdx.x;
    const int bh = bhn / NCH, n = bhn % NCH;
    const int t = threadIdx.x;
    const int d0 = (t & 15) * 4;
    const int e0 = (t >> 4) * 4;

    float af[4][4], as_[4][4];
#pragma unroll
    for (int i = 0; i < 4; i++)
#pragma unroll
        for (int j = 0; j < 4; j++) { af[i][j] = 0.f; as_[i][j] = 0.f; }

    for (int half = 0; half < 2; half++) {
        size_t base = ((size_t)bh * Lq + n * CH + half * 64) * HDq;
        for (int i = t; i < 1024; i += 256) {
            ((float4*)Ks)[i] = ((const float4*)(g_k + base))[i];
            ((float4*)Vs)[i] = ((const float4*)(g_v + base))[i];
        }
        if (t < 64) {
            float su = g_sur[bh * Lq + n * CH + half * 64 + t];
            S2[t] = su * su;
        }
        __syncthreads();
#pragma unroll 4
        for (int l = 0; l < 64; l++) {
            float4 vv = *(float4*)&Vs[l * 64 + d0];
            float4 kk = *(float4*)&Ks[l * 64 + e0];
            float s2 = S2[l];
            float v[4] = {vv.x, vv.y, vv.z, vv.w};
            float k[4] = {kk.x, kk.y, kk.z, kk.w};
            float vs[4] = {v[0] * s2, v[1] * s2, v[2] * s2, v[3] * s2};
#pragma unroll
            for (int i = 0; i < 4; i++)
#pragma unroll
                for (int j = 0; j < 4; j++) {
                    af[i][j] += v[i] * k[j];
                    as_[i][j] += vs[i] * k[j];
                }
        }
        __syncthreads();
    }

    size_t abase = (size_t)bhn * 4096;
#pragma unroll
    for (int i = 0; i < 4; i++) {
        *(float4*)&g_Af[abase + (d0 + i) * 64 + e0] =
            make_float4(af[i][0], af[i][1], af[i][2], af[i][3]);
        *(float4*)&g_As[abase + (d0 + i) * 64 + e0] =
            make_float4(as_[i][0], as_[i][1], as_[i][2], as_[i][3]);
    }
}

// ---------------- K5: decayed prefix scan over chunks (in-place) ------------
__global__ void scan_kernel()
{
    int bh = blockIdx.x >> 4;
    int eb = blockIdx.x & 15;
    int entry = eb * 256 + threadIdx.x;
    float sfv = 0.f, ssv = 0.f;
#pragma unroll 1
    for (int n = 0; n < NCH; n++) {
        int bhn = bh * NCH + n;
        float gf = g_gf[bhn], gs = g_gs[bhn];
        size_t idx = (size_t)bhn * 4096 + entry;
        sfv = sfv * gf + g_Af[idx]; g_Af[idx] = sfv;
        ssv = ssv * gs + g_As[idx]; g_As[idx] = ssv;
    }
}

// ---------------- K6: O = Q @ S (fast+slow), gate/alpha mix -> omix ---------
__global__ __launch_bounds__(256) void outmix_kernel()
{
    __shared__ float Sf[4096];
    __shared__ float Ss[4096];
    __shared__ float Qs[32 * 64];
    __shared__ float gA[32], gB[32];
    const int bhn = blockIdx.x;
    const int bh = bhn / NCH, n = bhn % NCH;
    const int b = bh >> 4, h = bh & 15;
    const int t = threadIdx.x;

    size_t abase = (size_t)bhn * 4096;
    for (int i = t; i < 1024; i += 256) {
        ((float4*)Sf)[i] = ((const float4*)(g_Af + abase))[i];
        ((float4*)Ss)[i] = ((const float4*)(g_As + abase))[i];
    }

    const int d = t & 63;
    const int lb = (t >> 6) * 8;

    for (int pass = 0; pass < 4; pass++) {
        int l0 = pass * 32;
        size_t qbase = ((size_t)bh * Lq + n * CH + l0) * HDq;
        for (int i = t; i < 512; i += 256)
            ((float4*)Qs)[i] = ((const float4*)(g_q + qbase))[i];
        if (t < 32) {
            int p = bh * Lq + n * CH + l0 + t;
            float psi = g_psi[p];
            float alpha = 0.5f + 0.3f * psi;
            gA[t] = alpha * g_fg[p];
            gB[t] = (1.f - alpha) * g_sg[p];
        }
        __syncthreads();

        float accf[8], accs[8];
#pragma unroll
        for (int l = 0; l < 8; l++) { accf[l] = 0.f; accs[l] = 0.f; }
#pragma unroll 8
        for (int e = 0; e < 64; e += 2) {
            float sf0 = Sf[e * 64 + d];
            float sf1 = Sf[(e + 1) * 64 + d];
            float ss0 = Ss[e * 64 + d];
            float ss1 = Ss[(e + 1) * 64 + d];
#pragma unroll
            for (int l = 0; l < 8; l++) {
                float2 q2 = *(float2*)&Qs[(lb + l) * 64 + e];
                accf[l] += q2.x * sf0 + q2.y * sf1;
                accs[l] += q2.x * ss0 + q2.y * ss1;
            }
        }
#pragma unroll
        for (int l = 0; l < 8; l++) {
            int ll = lb + l;
            float val = gA[ll] * accf[l] + gB[ll] * accs[l];
            int lglob = n * CH + l0 + ll;
            g_omix[((size_t)b * Lq + lglob) * Dq + h * HDq + d] = val;
        }
        __syncthreads();
    }
}

// ---------------- launch ----------------
extern "C" void kernel_launch(void* const* d_in, const int* in_sizes, int n_in,
                              void* d_out, int out_size)
{
    const float* x   = (const float*)d_in[0];
    const float* Wq  = (const float*)d_in[1];
    const float* Wk  = (const float*)d_in[2];
    const float* Wv  = (const float*)d_in[3];
    const float* Wb  = (const float*)d_in[4];
    const float* Wfd = (const float*)d_in[5];
    const float* fdb = (const float*)d_in[6];
    const float* Wsd = (const float*)d_in[7];
    const float* sdb = (const float*)d_in[8];
    const float* Wfg = (const float*)d_in[9];
    const float* Wsg = (const float*)d_in[10];
    const float* Wo  = (const float*)d_in[11];
    float* out = (float*)d_out;

    void* p_q = nullptr; void* p_k = nullptr; void* p_v = nullptr; void* p_omix = nullptr;
    cudaGetSymbolAddress(&p_q, g_q);
    cudaGetSymbolAddress(&p_k, g_k);
    cudaGetSymbolAddress(&p_v, g_v);
    cudaGetSymbolAddress(&p_omix, g_omix);

    const int M = Bq * Lq;             // 8192
    dim3 gemmGrid(Dq / 128, M / 128);  // (8, 64)

    // K1: q, k, v projections (silu, head layout) — TF32 tensor cores
    sgemm_tf32_kernel<<<gemmGrid, 256>>>(x, Wq, (float*)p_q, 1, 1);
    sgemm_tf32_kernel<<<gemmGrid, 256>>>(x, Wk, (float*)p_k, 1, 1);
    sgemm_tf32_kernel<<<gemmGrid, 256>>>(x, Wv, (float*)p_v, 1, 1);

    // K2: gate projections (256 blocks now)
    smallproj_kernel<<<M / 32, 256>>>(x, Wb, Wfd, fdb, Wsd, sdb, Wfg, Wsg);

    // K3: beta scaling + psi/surprise/decay-mod
    prep_kernel<<<(BHL * 32) / 256, 256>>>();

    // K3b: per-chunk decay factors
    chunkdecay_kernel<<<Bq * Hq * NCH, 128>>>();

    // K4: per-chunk outer products (fast + slow)
    outer_kernel<<<Bq * Hq * NCH, 256>>>();

    // K5: decayed scan across chunks
    scan_kernel<<<Bq * Hq * 16, 256>>>();

    // K6: per-chunk output + gate mixing
    outmix_kernel<<<Bq * Hq * NCH, 256>>>();

    // K7: output projection — TF32 tensor cores
    sgemm_tf32_kernel<<<gemmGrid, 256>>>((const float*)p_omix, Wo, out, 0, 0);
}

// round 3
// speedup vs baseline: 2.3926x; 1.1629x over previous
#include <cuda_runtime.h>
#include <math.h>
#include <stdint.h>

#define Bq 2
#define Lq 4096
#define Dq 1024
#define Hq 16
#define HDq 64
#define NCH 32
#define CH 128
#define BHL (Bq*Hq*Lq)

// ---------------- device scratch (no allocations allowed) ----------------
__device__ float g_q[Bq*Hq*Lq*HDq];
__device__ float g_k[Bq*Hq*Lq*HDq];
__device__ float g_v[Bq*Hq*Lq*HDq];
__device__ float g_beta[BHL];
__device__ float g_fd[BHL];
__device__ float g_sd[BHL];
__device__ float g_fg[BHL];
__device__ float g_sg[BHL];
__device__ float g_psi[BHL];
__device__ float g_sur[BHL];
__device__ float g_fdm[BHL];
__device__ float g_sdm[BHL];
__device__ float g_gf[Bq*Hq*NCH];
__device__ float g_gs[Bq*Hq*NCH];
__device__ float g_Af[Bq*Hq*NCH*HDq*HDq];
__device__ float g_As[Bq*Hq*NCH*HDq*HDq];
__device__ float g_omix[Bq*Lq*Dq];

__device__ __forceinline__ float sigm(float x) { return 1.f / (1.f + expf(-x)); }

__device__ __forceinline__ float to_tf32(float x) {
    uint32_t u;
    asm("cvt.rna.tf32.f32 %0, %1;" : "=r"(u) : "f"(x));
    return __uint_as_float(u);
}

__device__ __forceinline__ void mma_tf32(
    float& c0, float& c1, float& c2, float& c3,
    uint32_t a0, uint32_t a1, uint32_t a2, uint32_t a3,
    uint32_t b0, uint32_t b1)
{
    asm volatile(
        "mma.sync.aligned.m16n8k8.row.col.f32.tf32.tf32.f32 "
        "{%0,%1,%2,%3}, {%4,%5,%6,%7}, {%8,%9}, {%0,%1,%2,%3};"
        : "+f"(c0), "+f"(c1), "+f"(c2), "+f"(c3)
        : "r"(a0), "r"(a1), "r"(a2), "r"(a3), "r"(b0), "r"(b1));
}

// ---------------- K1/K7: TF32 GEMM, 128x128 tile, K-step 16, double-buffered
// A: [M,1024] rm, W: [1024,1024] rm. doSilu: y*sigmoid(y). headOut: [b,h,l,hd].
__global__ __launch_bounds__(256) void sgemm_tf32_kernel(
    const float* __restrict__ A, const float* __restrict__ W,
    float* __restrict__ C, int doSilu, int headOut)
{
    __shared__ float As[2][16][136];   // [buf][k][m]
    __shared__ float Bs[2][16][136];   // [buf][k][n]
    const int tid = threadIdx.x;
    const int lane = tid & 31;
    const int wid = tid >> 5;
    const int gid = lane >> 2;      // 0..7
    const int tig = lane & 3;       // 0..3
    const int warpM = (wid & 3) * 32;
    const int warpN = (wid >> 2) * 64;
    const int bn = blockIdx.x * 128;
    const int bm = blockIdx.y * 128;

    // loader mapping (per 16-k tile):
    // A: 128 rows x 16 k = 512 float4; idx=tid+i*256 -> r=idx>>2, kc=(idx&3)*4
    // B: 16 k x 128 n = 512 float4;   idx -> kr=idx>>5, nc=(idx&31)*4
    const int a_r  = tid >> 2;
    const int a_kc = (tid & 3) * 4;
    const int b_kr = tid >> 5;
    const int b_nc = (tid & 31) * 4;

    float acc[2][8][4];
#pragma unroll
    for (int mt = 0; mt < 2; mt++)
#pragma unroll
        for (int nt = 0; nt < 8; nt++)
#pragma unroll
            for (int c = 0; c < 4; c++) acc[mt][nt][c] = 0.f;

    // prologue: load tile 0 into buffer 0
    {
        float4 ra0 = *(const float4*)(A + (size_t)(bm + a_r) * 1024 + a_kc);
        float4 ra1 = *(const float4*)(A + (size_t)(bm + a_r + 64) * 1024 + a_kc);
        float4 rb0 = *(const float4*)(W + (size_t)b_kr * 1024 + bn + b_nc);
        float4 rb1 = *(const float4*)(W + (size_t)(b_kr + 8) * 1024 + bn + b_nc);
        As[0][a_kc + 0][a_r] = to_tf32(ra0.x);
        As[0][a_kc + 1][a_r] = to_tf32(ra0.y);
        As[0][a_kc + 2][a_r] = to_tf32(ra0.z);
        As[0][a_kc + 3][a_r] = to_tf32(ra0.w);
        As[0][a_kc + 0][a_r + 64] = to_tf32(ra1.x);
        As[0][a_kc + 1][a_r + 64] = to_tf32(ra1.y);
        As[0][a_kc + 2][a_r + 64] = to_tf32(ra1.z);
        As[0][a_kc + 3][a_r + 64] = to_tf32(ra1.w);
        *(float4*)(&Bs[0][b_kr][b_nc]) =
            make_float4(to_tf32(rb0.x), to_tf32(rb0.y), to_tf32(rb0.z), to_tf32(rb0.w));
        *(float4*)(&Bs[0][b_kr + 8][b_nc]) =
            make_float4(to_tf32(rb1.x), to_tf32(rb1.y), to_tf32(rb1.z), to_tf32(rb1.w));
    }
    __syncthreads();

#pragma unroll 1
    for (int t = 0; t < 64; t++) {
        const int cur = t & 1;
        float4 ra0, ra1, rb0, rb1;
        const bool has_next = (t < 63);
        if (has_next) {
            int k0 = (t + 1) * 16;
            ra0 = *(const float4*)(A + (size_t)(bm + a_r) * 1024 + k0 + a_kc);
            ra1 = *(const float4*)(A + (size_t)(bm + a_r + 64) * 1024 + k0 + a_kc);
            rb0 = *(const float4*)(W + (size_t)(k0 + b_kr) * 1024 + bn + b_nc);
            rb1 = *(const float4*)(W + (size_t)(k0 + b_kr + 8) * 1024 + bn + b_nc);
        }

        // compute on buffer cur (16 k = 2 mma k-steps)
#pragma unroll
        for (int kk = 0; kk < 2; kk++) {
            const int kb = kk * 8;
            uint32_t af[2][4];
#pragma unroll
            for (int mt = 0; mt < 2; mt++) {
                int m = warpM + mt * 16;
                af[mt][0] = __float_as_uint(As[cur][kb + tig][m + gid]);
                af[mt][1] = __float_as_uint(As[cur][kb + tig][m + gid + 8]);
                af[mt][2] = __float_as_uint(As[cur][kb + tig + 4][m + gid]);
                af[mt][3] = __float_as_uint(As[cur][kb + tig + 4][m + gid + 8]);
            }
#pragma unroll
            for (int nt = 0; nt < 8; nt++) {
                int n = warpN + nt * 8;
                uint32_t b0 = __float_as_uint(Bs[cur][kb + tig][n + gid]);
                uint32_t b1 = __float_as_uint(Bs[cur][kb + tig + 4][n + gid]);
#pragma unroll
                for (int mt = 0; mt < 2; mt++) {
                    mma_tf32(acc[mt][nt][0], acc[mt][nt][1], acc[mt][nt][2], acc[mt][nt][3],
                             af[mt][0], af[mt][1], af[mt][2], af[mt][3], b0, b1);
                }
            }
        }

        if (has_next) {
            const int nxt = cur ^ 1;
            As[nxt][a_kc + 0][a_r] = to_tf32(ra0.x);
            As[nxt][a_kc + 1][a_r] = to_tf32(ra0.y);
            As[nxt][a_kc + 2][a_r] = to_tf32(ra0.z);
            As[nxt][a_kc + 3][a_r] = to_tf32(ra0.w);
            As[nxt][a_kc + 0][a_r + 64] = to_tf32(ra1.x);
            As[nxt][a_kc + 1][a_r + 64] = to_tf32(ra1.y);
            As[nxt][a_kc + 2][a_r + 64] = to_tf32(ra1.z);
            As[nxt][a_kc + 3][a_r + 64] = to_tf32(ra1.w);
            *(float4*)(&Bs[nxt][b_kr][b_nc]) =
                make_float4(to_tf32(rb0.x), to_tf32(rb0.y), to_tf32(rb0.z), to_tf32(rb0.w));
            *(float4*)(&Bs[nxt][b_kr + 8][b_nc]) =
                make_float4(to_tf32(rb1.x), to_tf32(rb1.y), to_tf32(rb1.z), to_tf32(rb1.w));
        }
        __syncthreads();
    }

    // epilogue
#pragma unroll
    for (int mt = 0; mt < 2; mt++) {
#pragma unroll
        for (int nt = 0; nt < 8; nt++) {
            int row = bm + warpM + mt * 16 + gid;
            int col = bn + warpN + nt * 8 + tig * 2;
#pragma unroll
            for (int half = 0; half < 2; half++) {
                int r = row + half * 8;
                float v0 = acc[mt][nt][half * 2 + 0];
                float v1 = acc[mt][nt][half * 2 + 1];
                if (doSilu) {
                    v0 = v0 * (1.f / (1.f + expf(-v0)));
                    v1 = v1 * (1.f / (1.f + expf(-v1)));
                }
                if (headOut) {
                    int bb = r >> 12, l = r & 4095;
                    int h = col >> 6, hd = col & 63;
                    float2* dst = (float2*)(C + (((size_t)(bb * Hq + h) * Lq + l) * HDq) + hd);
                    *dst = make_float2(v0, v1);
                } else {
                    *(float2*)(C + (size_t)r * 1024 + col) = make_float2(v0, v1);
                }
            }
        }
    }
}

// ---------------- K2: small projections (5 x [D,16]), M=64, float4 LDS ------
__global__ __launch_bounds__(256) void smallproj_kernel(
    const float* __restrict__ x,
    const float* __restrict__ Wbm, const float* __restrict__ Wfd,
    const float* __restrict__ fdb, const float* __restrict__ Wsd,
    const float* __restrict__ sdb, const float* __restrict__ Wfg,
    const float* __restrict__ Wsg)
{
    __shared__ float xs[64][36];    // [m][k]
    __shared__ float Ws[80][36];    // [n][k]
    const int tid = threadIdx.x;
    const int tx = tid & 15;        // 5 outputs each
    const int ty = tid >> 4;        // rows ty + i*16
    const int m0 = blockIdx.x * 64;

    float acc[4][5];
#pragma unroll
    for (int i = 0; i < 4; i++)
#pragma unroll
        for (int j = 0; j < 5; j++) acc[i][j] = 0.f;

    for (int k0 = 0; k0 < 1024; k0 += 32) {
        // x tile: 64 rows x 32 k = 512 float4, 2 per thread
#pragma unroll
        for (int i = 0; i < 2; i++) {
            int idx = tid + i * 256;
            int r = idx >> 3;                   // 0..63
            int kc = (idx & 7) * 4;
            float4 x4 = *(const float4*)(x + (size_t)(m0 + r) * 1024 + k0 + kc);
            *(float4*)&xs[r][kc] = x4;
        }
        // W tile: 80 n x 32 k
#pragma unroll
        for (int i = 0; i < 10; i++) {
            int idx = tid + i * 256;            // 0..2559
            int n = idx >> 5;                   // 0..79
            int kk = idx & 31;
            int which = n >> 4, h = n & 15;
            const float* Wp = (which == 0) ? Wbm : (which == 1) ? Wfd
                             : (which == 2) ? Wsd : (which == 3) ? Wfg : Wsg;
            Ws[n][kk] = Wp[(k0 + kk) * 16 + h];
        }
        __syncthreads();
#pragma unroll
        for (int kc = 0; kc < 32; kc += 4) {
            float4 xv[4];
#pragma unroll
            for (int i = 0; i < 4; i++) xv[i] = *(float4*)&xs[ty + i * 16][kc];
#pragma unroll
            for (int j = 0; j < 5; j++) {
                float4 wv = *(float4*)&Ws[tx * 5 + j][kc];
#pragma unroll
                for (int i = 0; i < 4; i++) {
                    acc[i][j] += xv[i].x * wv.x + xv[i].y * wv.y
                               + xv[i].z * wv.z + xv[i].w * wv.w;
                }
            }
        }
        __syncthreads();
    }

#pragma unroll
    for (int i = 0; i < 4; i++) {
        int m = m0 + ty + i * 16;
        int bb = m >> 12, l = m & 4095;
#pragma unroll
        for (int j = 0; j < 5; j++) {
            int n = tx * 5 + j;
            int which = n >> 4, h = n & 15;
            float s = acc[i][j];
            if (which == 1) s += fdb[h];
            if (which == 2) s += sdb[h];
            float val = sigm(s);
            float* dst = (which == 0) ? g_beta : (which == 1) ? g_fd
                        : (which == 2) ? g_sd : (which == 3) ? g_fg : g_sg;
            dst[(bb * Hq + h) * Lq + l] = val;
        }
    }
}

// ---------------- K3: per-position prep (beta scale, psi, surprise, decays) --
__global__ void prep_kernel()
{
    int gw = (blockIdx.x * blockDim.x + threadIdx.x) >> 5;
    int lane = threadIdx.x & 31;
    if (gw >= BHL) return;
    int p = gw;
    float beta = g_beta[p];
    float2 k2 = ((float2*)g_k)[p * 32 + lane];
    float2 v2 = ((float2*)g_v)[p * 32 + lane];
    k2.x *= beta; k2.y *= beta;
    v2.x *= beta; v2.y *= beta;
    float kk = k2.x * k2.x + k2.y * k2.y;
    float vv = v2.x * v2.x + v2.y * v2.y;
    float kv = k2.x * v2.x + k2.y * v2.y;
#pragma unroll
    for (int off = 16; off; off >>= 1) {
        kk += __shfl_xor_sync(0xffffffffu, kk, off);
        vv += __shfl_xor_sync(0xffffffffu, vv, off);
        kv += __shfl_xor_sync(0xffffffffu, kv, off);
    }
    ((float2*)g_k)[p * 32 + lane] = k2;
    ((float2*)g_v)[p * 32 + lane] = v2;
    if (lane == 0) {
        float kn = sqrtf(kk) + 1e-8f;
        float vn = sqrtf(vv) + 1e-8f;
        float praw = fabsf(kv) / (kn * vn);
        float psi = sigm(3.f * praw);
        float sur = sigm((psi - 0.5f) * 10.f);
        g_psi[p] = psi;
        g_sur[p] = sur;
        g_fdm[p] = g_fd[p] * (1.f - 0.1f * psi);
        g_sdm[p] = g_sd[p] * (1.f - 0.05f * psi);
    }
}

// ---------------- K3b: per-chunk decay means -> g = mean^128 ----------------
__global__ void chunkdecay_kernel()
{
    __shared__ float sf[4], ss[4];
    int bhn = blockIdx.x;
    int t = threadIdx.x;
    int base = (bhn / NCH) * Lq + (bhn % NCH) * CH;
    float f = g_fdm[base + t];
    float s = g_sdm[base + t];
#pragma unroll
    for (int off = 16; off; off >>= 1) {
        f += __shfl_xor_sync(0xffffffffu, f, off);
        s += __shfl_xor_sync(0xffffffffu, s, off);
    }
    int lane = t & 31, wid = t >> 5;
    if (lane == 0) { sf[wid] = f; ss[wid] = s; }
    __syncthreads();
    if (t == 0) {
        float mf = (sf[0] + sf[1] + sf[2] + sf[3]) * (1.f / 128.f);
        float ms = (ss[0] + ss[1] + ss[2] + ss[3]) * (1.f / 128.f);
        float gf = mf, gs = ms;
#pragma unroll
        for (int i = 0; i < 7; i++) { gf *= gf; gs *= gs; }   // mean^128 exact
        g_gf[bhn] = gf;
        g_gs[bhn] = gs;
    }
}

// ---------------- K4: per-chunk outer products (fast + slow fused) ----------
__global__ __launch_bounds__(256) void outer_kernel()
{
    __shared__ float Ks[64 * 64];
    __shared__ float Vs[64 * 64];
    __shared__ float S2[64];
    const int bhn = blockIdx.x;
    const int bh = bhn / NCH, n = bhn % NCH;
    const int t = threadIdx.x;
    const int d0 = (t & 15) * 4;
    const int e0 = (t >> 4) * 4;

    float af[4][4], as_[4][4];
#pragma unroll
    for (int i = 0; i < 4; i++)
#pragma unroll
        for (int j = 0; j < 4; j++) { af[i][j] = 0.f; as_[i][j] = 0.f; }

    for (int half = 0; half < 2; half++) {
        size_t base = ((size_t)bh * Lq + n * CH + half * 64) * HDq;
        for (int i = t; i < 1024; i += 256) {
            ((float4*)Ks)[i] = ((const float4*)(g_k + base))[i];
            ((float4*)Vs)[i] = ((const float4*)(g_v + base))[i];
        }
        if (t < 64) {
            float su = g_sur[bh * Lq + n * CH + half * 64 + t];
            S2[t] = su * su;
        }
        __syncthreads();
#pragma unroll 4
        for (int l = 0; l < 64; l++) {
            float4 vv = *(float4*)&Vs[l * 64 + d0];
            float4 kk = *(float4*)&Ks[l * 64 + e0];
            float s2 = S2[l];
            float v[4] = {vv.x, vv.y, vv.z, vv.w};
            float k[4] = {kk.x, kk.y, kk.z, kk.w};
            float vs[4] = {v[0] * s2, v[1] * s2, v[2] * s2, v[3] * s2};
#pragma unroll
            for (int i = 0; i < 4; i++)
#pragma unroll
                for (int j = 0; j < 4; j++) {
                    af[i][j] += v[i] * k[j];
                    as_[i][j] += vs[i] * k[j];
                }
        }
        __syncthreads();
    }

    size_t abase = (size_t)bhn * 4096;
#pragma unroll
    for (int i = 0; i < 4; i++) {
        *(float4*)&g_Af[abase + (d0 + i) * 64 + e0] =
            make_float4(af[i][0], af[i][1], af[i][2], af[i][3]);
        *(float4*)&g_As[abase + (d0 + i) * 64 + e0] =
            make_float4(as_[i][0], as_[i][1], as_[i][2], as_[i][3]);
    }
}

// ---------------- K5: decayed prefix scan over chunks (in-place) ------------
__global__ void scan_kernel()
{
    int bh = blockIdx.x >> 4;
    int eb = blockIdx.x & 15;
    int entry = eb * 256 + threadIdx.x;
    float sfv = 0.f, ssv = 0.f;
#pragma unroll 1
    for (int n = 0; n < NCH; n++) {
        int bhn = bh * NCH + n;
        float gf = g_gf[bhn], gs = g_gs[bhn];
        size_t idx = (size_t)bhn * 4096 + entry;
        sfv = sfv * gf + g_Af[idx]; g_Af[idx] = sfv;
        ssv = ssv * gs + g_As[idx]; g_As[idx] = ssv;
    }
}

// ---------------- K6: O = Q @ S (fast+slow), gate/alpha mix -> omix ---------
__global__ __launch_bounds__(256) void outmix_kernel()
{
    __shared__ float Sf[4096];
    __shared__ float Ss[4096];
    __shared__ float Qs[32 * 64];
    __shared__ float gA[32], gB[32];
    const int bhn = blockIdx.x;
    const int bh = bhn / NCH, n = bhn % NCH;
    const int b = bh >> 4, h = bh & 15;
    const int t = threadIdx.x;

    size_t abase = (size_t)bhn * 4096;
    for (int i = t; i < 1024; i += 256) {
        ((float4*)Sf)[i] = ((const float4*)(g_Af + abase))[i];
        ((float4*)Ss)[i] = ((const float4*)(g_As + abase))[i];
    }

    const int d = t & 63;
    const int lb = (t >> 6) * 8;

    for (int pass = 0; pass < 4; pass++) {
        int l0 = pass * 32;
        size_t qbase = ((size_t)bh * Lq + n * CH + l0) * HDq;
        for (int i = t; i < 512; i += 256)
            ((float4*)Qs)[i] = ((const float4*)(g_q + qbase))[i];
        if (t < 32) {
            int p = bh * Lq + n * CH + l0 + t;
            float psi = g_psi[p];
            float alpha = 0.5f + 0.3f * psi;
            gA[t] = alpha * g_fg[p];
            gB[t] = (1.f - alpha) * g_sg[p];
        }
        __syncthreads();

        float accf[8], accs[8];
#pragma unroll
        for (int l = 0; l < 8; l++) { accf[l] = 0.f; accs[l] = 0.f; }
#pragma unroll 8
        for (int e = 0; e < 64; e += 2) {
            float sf0 = Sf[e * 64 + d];
            float sf1 = Sf[(e + 1) * 64 + d];
            float ss0 = Ss[e * 64 + d];
            float ss1 = Ss[(e + 1) * 64 + d];
#pragma unroll
            for (int l = 0; l < 8; l++) {
                float2 q2 = *(float2*)&Qs[(lb + l) * 64 + e];
                accf[l] += q2.x * sf0 + q2.y * sf1;
                accs[l] += q2.x * ss0 + q2.y * ss1;
            }
        }
#pragma unroll
        for (int l = 0; l < 8; l++) {
            int ll = lb + l;
            float val = gA[ll] * accf[l] + gB[ll] * accs[l];
            int lglob = n * CH + l0 + ll;
            g_omix[((size_t)b * Lq + lglob) * Dq + h * HDq + d] = val;
        }
        __syncthreads();
    }
}

// ---------------- launch ----------------
extern "C" void kernel_launch(void* const* d_in, const int* in_sizes, int n_in,
                              void* d_out, int out_size)
{
    const float* x   = (const float*)d_in[0];
    const float* Wq  = (const float*)d_in[1];
    const float* Wk  = (const float*)d_in[2];
    const float* Wv  = (const float*)d_in[3];
    const float* Wb  = (const float*)d_in[4];
    const float* Wfd = (const float*)d_in[5];
    const float* fdb = (const float*)d_in[6];
    const float* Wsd = (const float*)d_in[7];
    const float* sdb = (const float*)d_in[8];
    const float* Wfg = (const float*)d_in[9];
    const float* Wsg = (const float*)d_in[10];
    const float* Wo  = (const float*)d_in[11];
    float* out = (float*)d_out;

    void* p_q = nullptr; void* p_k = nullptr; void* p_v = nullptr; void* p_omix = nullptr;
    cudaGetSymbolAddress(&p_q, g_q);
    cudaGetSymbolAddress(&p_k, g_k);
    cudaGetSymbolAddress(&p_v, g_v);
    cudaGetSymbolAddress(&p_omix, g_omix);

    const int M = Bq * Lq;             // 8192
    dim3 gemmGrid(Dq / 128, M / 128);  // (8, 64)

    // K1: q, k, v projections (silu, head layout) — TF32 tensor cores
    sgemm_tf32_kernel<<<gemmGrid, 256>>>(x, Wq, (float*)p_q, 1, 1);
    sgemm_tf32_kernel<<<gemmGrid, 256>>>(x, Wk, (float*)p_k, 1, 1);
    sgemm_tf32_kernel<<<gemmGrid, 256>>>(x, Wv, (float*)p_v, 1, 1);

    // K2: gate projections (128 blocks, M=64)
    smallproj_kernel<<<M / 64, 256>>>(x, Wb, Wfd, fdb, Wsd, sdb, Wfg, Wsg);

    // K3: beta scaling + psi/surprise/decay-mod
    prep_kernel<<<(BHL * 32) / 256, 256>>>();

    // K3b: per-chunk decay factors
    chunkdecay_kernel<<<Bq * Hq * NCH, 128>>>();

    // K4: per-chunk outer products (fast + slow)
    outer_kernel<<<Bq * Hq * NCH, 256>>>();

    // K5: decayed scan across chunks
    scan_kernel<<<Bq * Hq * 16, 256>>>();

    // K6: per-chunk output + gate mixing
    outmix_kernel<<<Bq * Hq * NCH, 256>>>();

    // K7: output projection — TF32 tensor cores
    sgemm_tf32_kernel<<<gemmGrid, 256>>>((const float*)p_omix, Wo, out, 0, 0);
}

// round 4
// speedup vs baseline: 2.5573x; 1.0688x over previous
#include <cuda_runtime.h>
#include <math.h>
#include <stdint.h>

#define Bq 2
#define Lq 4096
#define Dq 1024
#define Hq 16
#define HDq 64
#define NCH 32
#define CH 128
#define BHL (Bq*Hq*Lq)

// GEMM smem geometry (dynamic): As[2][16][136], Bs[2][16][264]
#define ASTRIDE 136
#define BSTRIDE 264
#define ABUF (16*ASTRIDE)
#define BBUF (16*BSTRIDE)
#define SMEM_GEMM ((2*ABUF + 2*BBUF) * 4)

// ---------------- device scratch (no allocations allowed) ----------------
__device__ float g_q[Bq*Hq*Lq*HDq];
__device__ float g_k[Bq*Hq*Lq*HDq];
__device__ float g_v[Bq*Hq*Lq*HDq];
__device__ float g_beta[BHL];
__device__ float g_fd[BHL];
__device__ float g_sd[BHL];
__device__ float g_fg[BHL];
__device__ float g_sg[BHL];
__device__ float g_psi[BHL];
__device__ float g_sur[BHL];
__device__ float g_fdm[BHL];
__device__ float g_sdm[BHL];
__device__ float g_gf[Bq*Hq*NCH];
__device__ float g_gs[Bq*Hq*NCH];
__device__ float g_Af[Bq*Hq*NCH*HDq*HDq];
__device__ float g_As[Bq*Hq*NCH*HDq*HDq];
__device__ float g_omix[Bq*Lq*Dq];

__device__ __forceinline__ float sigm(float x) { return 1.f / (1.f + expf(-x)); }

__device__ __forceinline__ float to_tf32(float x) {
    uint32_t u;
    asm("cvt.rna.tf32.f32 %0, %1;" : "=r"(u) : "f"(x));
    return __uint_as_float(u);
}

__device__ __forceinline__ void mma_tf32(
    float& c0, float& c1, float& c2, float& c3,
    uint32_t a0, uint32_t a1, uint32_t a2, uint32_t a3,
    uint32_t b0, uint32_t b1)
{
    asm volatile(
        "mma.sync.aligned.m16n8k8.row.col.f32.tf32.tf32.f32 "
        "{%0,%1,%2,%3}, {%4,%5,%6,%7}, {%8,%9}, {%0,%1,%2,%3};"
        : "+f"(c0), "+f"(c1), "+f"(c2), "+f"(c3)
        : "r"(a0), "r"(a1), "r"(a2), "r"(a3), "r"(b0), "r"(b1));
}

// ---------------- K1/K7: TF32 GEMM, 128Mx256N tile, warp 64x64, dbuf --------
// z selects (W, C). A:[8192,1024] rm, W:[1024,1024] rm.
__global__ __launch_bounds__(256, 1) void gemm_tf32_kernel(
    const float* __restrict__ A,
    const float* __restrict__ W0, const float* __restrict__ W1, const float* __restrict__ W2,
    float* __restrict__ C0, float* __restrict__ C1, float* __restrict__ C2,
    int doSilu, int headOut)
{
    extern __shared__ float sm[];
    float* As = sm;                 // [2][16][ASTRIDE]
    float* Bs = sm + 2 * ABUF;      // [2][16][BSTRIDE]

    const int z = blockIdx.z;
    const float* W = (z == 0) ? W0 : (z == 1) ? W1 : W2;
    float* C = (z == 0) ? C0 : (z == 1) ? C1 : C2;

    const int tid = threadIdx.x;
    const int lane = tid & 31;
    const int wid = tid >> 5;
    const int gid = lane >> 2;      // 0..7
    const int tig = lane & 3;       // 0..3
    const int warpM = (wid & 1) * 64;
    const int warpN = (wid >> 1) * 64;
    const int bm = blockIdx.y * 128;
    const int bn = blockIdx.x * 256;

    // loader mapping per 16-k tile
    const int a_r  = tid >> 2;          // 0..63 (rows a_r, a_r+64)
    const int a_kc = (tid & 3) * 4;     // 0,4,8,12
    const int b_kr = tid >> 6;          // 0..3 (rows b_kr + 4i)
    const int b_nc = (tid & 63) * 4;    // 0..252

    float acc[4][8][4];
#pragma unroll
    for (int mt = 0; mt < 4; mt++)
#pragma unroll
        for (int nt = 0; nt < 8; nt++)
#pragma unroll
            for (int c = 0; c < 4; c++) acc[mt][nt][c] = 0.f;

    // prologue: tile 0 -> buffer 0
    {
        float4 ra0 = *(const float4*)(A + (size_t)(bm + a_r) * 1024 + a_kc);
        float4 ra1 = *(const float4*)(A + (size_t)(bm + a_r + 64) * 1024 + a_kc);
        float* Asn = As;
        Asn[(a_kc + 0) * ASTRIDE + a_r] = to_tf32(ra0.x);
        Asn[(a_kc + 1) * ASTRIDE + a_r] = to_tf32(ra0.y);
        Asn[(a_kc + 2) * ASTRIDE + a_r] = to_tf32(ra0.z);
        Asn[(a_kc + 3) * ASTRIDE + a_r] = to_tf32(ra0.w);
        Asn[(a_kc + 0) * ASTRIDE + a_r + 64] = to_tf32(ra1.x);
        Asn[(a_kc + 1) * ASTRIDE + a_r + 64] = to_tf32(ra1.y);
        Asn[(a_kc + 2) * ASTRIDE + a_r + 64] = to_tf32(ra1.z);
        Asn[(a_kc + 3) * ASTRIDE + a_r + 64] = to_tf32(ra1.w);
#pragma unroll
        for (int i = 0; i < 4; i++) {
            int kr = b_kr + i * 4;
            float4 rb = *(const float4*)(W + (size_t)kr * 1024 + bn + b_nc);
            *(float4*)&Bs[kr * BSTRIDE + b_nc] =
                make_float4(to_tf32(rb.x), to_tf32(rb.y), to_tf32(rb.z), to_tf32(rb.w));
        }
    }
    __syncthreads();

#pragma unroll 1
    for (int t = 0; t < 64; t++) {
        const int cur = t & 1;
        float4 ra0, ra1, rb[4];
        const bool has_next = (t < 63);
        if (has_next) {
            int k0 = (t + 1) * 16;
            ra0 = *(const float4*)(A + (size_t)(bm + a_r) * 1024 + k0 + a_kc);
            ra1 = *(const float4*)(A + (size_t)(bm + a_r + 64) * 1024 + k0 + a_kc);
#pragma unroll
            for (int i = 0; i < 4; i++)
                rb[i] = *(const float4*)(W + (size_t)(k0 + b_kr + i * 4) * 1024 + bn + b_nc);
        }

        const float* Asc = As + cur * ABUF;
        const float* Bsc = Bs + cur * BBUF;
#pragma unroll
        for (int kk = 0; kk < 2; kk++) {
            const int kb = kk * 8;
            uint32_t af[4][4];
#pragma unroll
            for (int mt = 0; mt < 4; mt++) {
                int m = warpM + mt * 16 + gid;
                af[mt][0] = __float_as_uint(Asc[(kb + tig) * ASTRIDE + m]);
                af[mt][1] = __float_as_uint(Asc[(kb + tig) * ASTRIDE + m + 8]);
                af[mt][2] = __float_as_uint(Asc[(kb + tig + 4) * ASTRIDE + m]);
                af[mt][3] = __float_as_uint(Asc[(kb + tig + 4) * ASTRIDE + m + 8]);
            }
#pragma unroll
            for (int nt = 0; nt < 8; nt++) {
                int n = warpN + nt * 8 + gid;
                uint32_t b0 = __float_as_uint(Bsc[(kb + tig) * BSTRIDE + n]);
                uint32_t b1 = __float_as_uint(Bsc[(kb + tig + 4) * BSTRIDE + n]);
#pragma unroll
                for (int mt = 0; mt < 4; mt++) {
                    mma_tf32(acc[mt][nt][0], acc[mt][nt][1], acc[mt][nt][2], acc[mt][nt][3],
                             af[mt][0], af[mt][1], af[mt][2], af[mt][3], b0, b1);
                }
            }
        }

        if (has_next) {
            const int nxt = cur ^ 1;
            float* Asn = As + nxt * ABUF;
            float* Bsn = Bs + nxt * BBUF;
            Asn[(a_kc + 0) * ASTRIDE + a_r] = to_tf32(ra0.x);
            Asn[(a_kc + 1) * ASTRIDE + a_r] = to_tf32(ra0.y);
            Asn[(a_kc + 2) * ASTRIDE + a_r] = to_tf32(ra0.z);
            Asn[(a_kc + 3) * ASTRIDE + a_r] = to_tf32(ra0.w);
            Asn[(a_kc + 0) * ASTRIDE + a_r + 64] = to_tf32(ra1.x);
            Asn[(a_kc + 1) * ASTRIDE + a_r + 64] = to_tf32(ra1.y);
            Asn[(a_kc + 2) * ASTRIDE + a_r + 64] = to_tf32(ra1.z);
            Asn[(a_kc + 3) * ASTRIDE + a_r + 64] = to_tf32(ra1.w);
#pragma unroll
            for (int i = 0; i < 4; i++) {
                int kr = b_kr + i * 4;
                *(float4*)&Bsn[kr * BSTRIDE + b_nc] =
                    make_float4(to_tf32(rb[i].x), to_tf32(rb[i].y), to_tf32(rb[i].z), to_tf32(rb[i].w));
            }
        }
        __syncthreads();
    }

    // epilogue
#pragma unroll
    for (int mt = 0; mt < 4; mt++) {
#pragma unroll
        for (int nt = 0; nt < 8; nt++) {
            int row = bm + warpM + mt * 16 + gid;
            int col = bn + warpN + nt * 8 + tig * 2;
#pragma unroll
            for (int half = 0; half < 2; half++) {
                int r = row + half * 8;
                float v0 = acc[mt][nt][half * 2 + 0];
                float v1 = acc[mt][nt][half * 2 + 1];
                if (doSilu) {
                    v0 = v0 * (1.f / (1.f + expf(-v0)));
                    v1 = v1 * (1.f / (1.f + expf(-v1)));
                }
                if (headOut) {
                    int bb = r >> 12, l = r & 4095;
                    int h = col >> 6, hd = col & 63;
                    *(float2*)(C + (((size_t)(bb * Hq + h) * Lq + l) * HDq) + hd) =
                        make_float2(v0, v1);
                } else {
                    *(float2*)(C + (size_t)r * 1024 + col) = make_float2(v0, v1);
                }
            }
        }
    }
}

// ---------------- K2: small projections via TF32 mma, 64Mx80N tile ----------
#define XSTRIDE 72
#define WSTRIDE 88
__global__ __launch_bounds__(256) void smallproj_kernel(
    const float* __restrict__ x,
    const float* __restrict__ Wbm, const float* __restrict__ Wfd,
    const float* __restrict__ fdb, const float* __restrict__ Wsd,
    const float* __restrict__ sdb, const float* __restrict__ Wfg,
    const float* __restrict__ Wsg)
{
    __shared__ float Xs[2][16][XSTRIDE];
    __shared__ float Ws[2][16][WSTRIDE];
    const int tid = threadIdx.x;
    const int lane = tid & 31;
    const int wid = tid >> 5;
    const int gid = lane >> 2;
    const int tig = lane & 3;
    const int warpM = (wid & 3) * 16;
    const int warpN = (wid >> 2) * 40;
    const int bm = blockIdx.x * 64;

    const int a_r  = tid >> 2;          // 0..63
    const int a_kc = (tid & 3) * 4;

    float acc[5][4];
#pragma unroll
    for (int nt = 0; nt < 5; nt++)
#pragma unroll
        for (int c = 0; c < 4; c++) acc[nt][c] = 0.f;

    // prologue tile 0
    {
        float4 xa = *(const float4*)(x + (size_t)(bm + a_r) * 1024 + a_kc);
        Xs[0][a_kc + 0][a_r] = to_tf32(xa.x);
        Xs[0][a_kc + 1][a_r] = to_tf32(xa.y);
        Xs[0][a_kc + 2][a_r] = to_tf32(xa.z);
        Xs[0][a_kc + 3][a_r] = to_tf32(xa.w);
#pragma unroll
        for (int i = 0; i < 5; i++) {
            int idx = tid + i * 256;
            int kr = idx / 80, n = idx % 80;
            int which = n >> 4, h = n & 15;
            const float* Wp = (which == 0) ? Wbm : (which == 1) ? Wfd
                             : (which == 2) ? Wsd : (which == 3) ? Wfg : Wsg;
            Ws[0][kr][n] = to_tf32(Wp[kr * 16 + h]);
        }
    }
    __syncthreads();

#pragma unroll 1
    for (int t = 0; t < 64; t++) {
        const int cur = t & 1;
        float4 xa;
        float wreg[5];
        const bool has_next = (t < 63);
        if (has_next) {
            int k0 = (t + 1) * 16;
            xa = *(const float4*)(x + (size_t)(bm + a_r) * 1024 + k0 + a_kc);
#pragma unroll
            for (int i = 0; i < 5; i++) {
                int idx = tid + i * 256;
                int kr = idx / 80, n = idx % 80;
                int which = n >> 4, h = n & 15;
                const float* Wp = (which == 0) ? Wbm : (which == 1) ? Wfd
                                 : (which == 2) ? Wsd : (which == 3) ? Wfg : Wsg;
                wreg[i] = Wp[(k0 + kr) * 16 + h];
            }
        }

#pragma unroll
        for (int kk = 0; kk < 2; kk++) {
            const int kb = kk * 8;
            uint32_t a0 = __float_as_uint(Xs[cur][kb + tig][warpM + gid]);
            uint32_t a1 = __float_as_uint(Xs[cur][kb + tig][warpM + gid + 8]);
            uint32_t a2 = __float_as_uint(Xs[cur][kb + tig + 4][warpM + gid]);
            uint32_t a3 = __float_as_uint(Xs[cur][kb + tig + 4][warpM + gid + 8]);
#pragma unroll
            for (int nt = 0; nt < 5; nt++) {
                int n = warpN + nt * 8 + gid;
                uint32_t b0 = __float_as_uint(Ws[cur][kb + tig][n]);
                uint32_t b1 = __float_as_uint(Ws[cur][kb + tig + 4][n]);
                mma_tf32(acc[nt][0], acc[nt][1], acc[nt][2], acc[nt][3],
                         a0, a1, a2, a3, b0, b1);
            }
        }

        if (has_next) {
            const int nxt = cur ^ 1;
            Xs[nxt][a_kc + 0][a_r] = to_tf32(xa.x);
            Xs[nxt][a_kc + 1][a_r] = to_tf32(xa.y);
            Xs[nxt][a_kc + 2][a_r] = to_tf32(xa.z);
            Xs[nxt][a_kc + 3][a_r] = to_tf32(xa.w);
#pragma unroll
            for (int i = 0; i < 5; i++) {
                int idx = tid + i * 256;
                int kr = idx / 80, n = idx % 80;
                Ws[nxt][kr][n] = to_tf32(wreg[i]);
            }
        }
        __syncthreads();
    }

    // epilogue: sigmoid(+bias) scatter to 5 gate arrays
#pragma unroll
    for (int nt = 0; nt < 5; nt++) {
#pragma unroll
        for (int half = 0; half < 2; half++) {
            int r = bm + warpM + gid + half * 8;
            int bb = r >> 12, l = r & 4095;
#pragma unroll
            for (int cc = 0; cc < 2; cc++) {
                int col = warpN + nt * 8 + tig * 2 + cc;
                int which = col >> 4, h = col & 15;
                float s = acc[nt][half * 2 + cc];
                if (which == 1) s += fdb[h];
                if (which == 2) s += sdb[h];
                float val = sigm(s);
                float* dst = (which == 0) ? g_beta : (which == 1) ? g_fd
                            : (which == 2) ? g_sd : (which == 3) ? g_fg : g_sg;
                dst[(bb * Hq + h) * Lq + l] = val;
            }
        }
    }
}

// ---------------- K3: per-position prep (beta scale, psi, surprise, decays) --
__global__ void prep_kernel()
{
    int gw = (blockIdx.x * blockDim.x + threadIdx.x) >> 5;
    int lane = threadIdx.x & 31;
    if (gw >= BHL) return;
    int p = gw;
    float beta = g_beta[p];
    float2 k2 = ((float2*)g_k)[p * 32 + lane];
    float2 v2 = ((float2*)g_v)[p * 32 + lane];
    k2.x *= beta; k2.y *= beta;
    v2.x *= beta; v2.y *= beta;
    float kk = k2.x * k2.x + k2.y * k2.y;
    float vv = v2.x * v2.x + v2.y * v2.y;
    float kv = k2.x * v2.x + k2.y * v2.y;
#pragma unroll
    for (int off = 16; off; off >>= 1) {
        kk += __shfl_xor_sync(0xffffffffu, kk, off);
        vv += __shfl_xor_sync(0xffffffffu, vv, off);
        kv += __shfl_xor_sync(0xffffffffu, kv, off);
    }
    ((float2*)g_k)[p * 32 + lane] = k2;
    ((float2*)g_v)[p * 32 + lane] = v2;
    if (lane == 0) {
        float kn = sqrtf(kk) + 1e-8f;
        float vn = sqrtf(vv) + 1e-8f;
        float praw = fabsf(kv) / (kn * vn);
        float psi = sigm(3.f * praw);
        float sur = sigm((psi - 0.5f) * 10.f);
        g_psi[p] = psi;
        g_sur[p] = sur;
        g_fdm[p] = g_fd[p] * (1.f - 0.1f * psi);
        g_sdm[p] = g_sd[p] * (1.f - 0.05f * psi);
    }
}

// ---------------- K3b: per-chunk decay means -> g = mean^128 ----------------
__global__ void chunkdecay_kernel()
{
    __shared__ float sf[4], ss[4];
    int bhn = blockIdx.x;
    int t = threadIdx.x;
    int base = (bhn / NCH) * Lq + (bhn % NCH) * CH;
    float f = g_fdm[base + t];
    float s = g_sdm[base + t];
#pragma unroll
    for (int off = 16; off; off >>= 1) {
        f += __shfl_xor_sync(0xffffffffu, f, off);
        s += __shfl_xor_sync(0xffffffffu, s, off);
    }
    int lane = t & 31, wid = t >> 5;
    if (lane == 0) { sf[wid] = f; ss[wid] = s; }
    __syncthreads();
    if (t == 0) {
        float mf = (sf[0] + sf[1] + sf[2] + sf[3]) * (1.f / 128.f);
        float ms = (ss[0] + ss[1] + ss[2] + ss[3]) * (1.f / 128.f);
        float gf = mf, gs = ms;
#pragma unroll
        for (int i = 0; i < 7; i++) { gf *= gf; gs *= gs; }   // mean^128 exact
        g_gf[bhn] = gf;
        g_gs[bhn] = gs;
    }
}

// ---------------- K4: per-chunk outer products (fast + slow fused) ----------
__global__ __launch_bounds__(256) void outer_kernel()
{
    __shared__ float Ks[64 * 64];
    __shared__ float Vs[64 * 64];
    __shared__ float S2[64];
    const int bhn = blockIdx.x;
    const int bh = bhn / NCH, n = bhn % NCH;
    const int t = threadIdx.x;
    const int d0 = (t & 15) * 4;
    const int e0 = (t >> 4) * 4;

    float af[4][4], as_[4][4];
#pragma unroll
    for (int i = 0; i < 4; i++)
#pragma unroll
        for (int j = 0; j < 4; j++) { af[i][j] = 0.f; as_[i][j] = 0.f; }

    for (int half = 0; half < 2; half++) {
        size_t base = ((size_t)bh * Lq + n * CH + half * 64) * HDq;
        for (int i = t; i < 1024; i += 256) {
            ((float4*)Ks)[i] = ((const float4*)(g_k + base))[i];
            ((float4*)Vs)[i] = ((const float4*)(g_v + base))[i];
        }
        if (t < 64) {
            float su = g_sur[bh * Lq + n * CH + half * 64 + t];
            S2[t] = su * su;
        }
        __syncthreads();
#pragma unroll 4
        for (int l = 0; l < 64; l++) {
            float4 vv = *(float4*)&Vs[l * 64 + d0];
            float4 kk = *(float4*)&Ks[l * 64 + e0];
            float s2 = S2[l];
            float v[4] = {vv.x, vv.y, vv.z, vv.w};
            float k[4] = {kk.x, kk.y, kk.z, kk.w};
            float vs[4] = {v[0] * s2, v[1] * s2, v[2] * s2, v[3] * s2};
#pragma unroll
            for (int i = 0; i < 4; i++)
#pragma unroll
                for (int j = 0; j < 4; j++) {
                    af[i][j] += v[i] * k[j];
                    as_[i][j] += vs[i] * k[j];
                }
        }
        __syncthreads();
    }

    size_t abase = (size_t)bhn * 4096;
#pragma unroll
    for (int i = 0; i < 4; i++) {
        *(float4*)&g_Af[abase + (d0 + i) * 64 + e0] =
            make_float4(af[i][0], af[i][1], af[i][2], af[i][3]);
        *(float4*)&g_As[abase + (d0 + i) * 64 + e0] =
            make_float4(as_[i][0], as_[i][1], as_[i][2], as_[i][3]);
    }
}

// ---------------- K5: decayed prefix scan over chunks (in-place) ------------
__global__ void scan_kernel()
{
    int bh = blockIdx.x >> 4;
    int eb = blockIdx.x & 15;
    int entry = eb * 256 + threadIdx.x;
    float sfv = 0.f, ssv = 0.f;
#pragma unroll 1
    for (int n = 0; n < NCH; n++) {
        int bhn = bh * NCH + n;
        float gf = g_gf[bhn], gs = g_gs[bhn];
        size_t idx = (size_t)bhn * 4096 + entry;
        sfv = sfv * gf + g_Af[idx]; g_Af[idx] = sfv;
        ssv = ssv * gs + g_As[idx]; g_As[idx] = ssv;
    }
}

// ---------------- K6: O = Q @ S (fast+slow), gate/alpha mix -> omix ---------
__global__ __launch_bounds__(256) void outmix_kernel()
{
    __shared__ float Sf[4096];
    __shared__ float Ss[4096];
    __shared__ float Qs[32 * 64];
    __shared__ float gA[32], gB[32];
    const int bhn = blockIdx.x;
    const int bh = bhn / NCH, n = bhn % NCH;
    const int b = bh >> 4, h = bh & 15;
    const int t = threadIdx.x;

    size_t abase = (size_t)bhn * 4096;
    for (int i = t; i < 1024; i += 256) {
        ((float4*)Sf)[i] = ((const float4*)(g_Af + abase))[i];
        ((float4*)Ss)[i] = ((const float4*)(g_As + abase))[i];
    }

    const int d = t & 63;
    const int lb = (t >> 6) * 8;

    for (int pass = 0; pass < 4; pass++) {
        int l0 = pass * 32;
        size_t qbase = ((size_t)bh * Lq + n * CH + l0) * HDq;
        for (int i = t; i < 512; i += 256)
            ((float4*)Qs)[i] = ((const float4*)(g_q + qbase))[i];
        if (t < 32) {
            int p = bh * Lq + n * CH + l0 + t;
            float psi = g_psi[p];
            float alpha = 0.5f + 0.3f * psi;
            gA[t] = alpha * g_fg[p];
            gB[t] = (1.f - alpha) * g_sg[p];
        }
        __syncthreads();

        float accf[8], accs[8];
#pragma unroll
        for (int l = 0; l < 8; l++) { accf[l] = 0.f; accs[l] = 0.f; }
#pragma unroll 8
        for (int e = 0; e < 64; e += 2) {
            float sf0 = Sf[e * 64 + d];
            float sf1 = Sf[(e + 1) * 64 + d];
            float ss0 = Ss[e * 64 + d];
            float ss1 = Ss[(e + 1) * 64 + d];
#pragma unroll
            for (int l = 0; l < 8; l++) {
                float2 q2 = *(float2*)&Qs[(lb + l) * 64 + e];
                accf[l] += q2.x * sf0 + q2.y * sf1;
                accs[l] += q2.x * ss0 + q2.y * ss1;
            }
        }
#pragma unroll
        for (int l = 0; l < 8; l++) {
            int ll = lb + l;
            float val = gA[ll] * accf[l] + gB[ll] * accs[l];
            int lglob = n * CH + l0 + ll;
            g_omix[((size_t)b * Lq + lglob) * Dq + h * HDq + d] = val;
        }
        __syncthreads();
    }
}

// ---------------- launch ----------------
extern "C" void kernel_launch(void* const* d_in, const int* in_sizes, int n_in,
                              void* d_out, int out_size)
{
    const float* x   = (const float*)d_in[0];
    const float* Wq  = (const float*)d_in[1];
    const float* Wk  = (const float*)d_in[2];
    const float* Wv  = (const float*)d_in[3];
    const float* Wb  = (const float*)d_in[4];
    const float* Wfd = (const float*)d_in[5];
    const float* fdb = (const float*)d_in[6];
    const float* Wsd = (const float*)d_in[7];
    const float* sdb = (const float*)d_in[8];
    const float* Wfg = (const float*)d_in[9];
    const float* Wsg = (const float*)d_in[10];
    const float* Wo  = (const float*)d_in[11];
    float* out = (float*)d_out;

    void* p_q = nullptr; void* p_k = nullptr; void* p_v = nullptr; void* p_omix = nullptr;
    cudaGetSymbolAddress(&p_q, g_q);
    cudaGetSymbolAddress(&p_k, g_k);
    cudaGetSymbolAddress(&p_v, g_v);
    cudaGetSymbolAddress(&p_omix, g_omix);

    cudaFuncSetAttribute(gemm_tf32_kernel,
                         cudaFuncAttributeMaxDynamicSharedMemorySize, SMEM_GEMM);

    // K1: fused q,k,v projections (silu, head layout) — TF32 tensor cores
    gemm_tf32_kernel<<<dim3(4, 64, 3), 256, SMEM_GEMM>>>(
        x, Wq, Wk, Wv, (float*)p_q, (float*)p_k, (float*)p_v, 1, 1);

    // K2: gate projections — TF32 tensor cores
    smallproj_kernel<<<128, 256>>>(x, Wb, Wfd, fdb, Wsd, sdb, Wfg, Wsg);

    // K3: beta scaling + psi/surprise/decay-mod
    prep_kernel<<<(BHL * 32) / 256, 256>>>();

    // K3b: per-chunk decay factors
    chunkdecay_kernel<<<Bq * Hq * NCH, 128>>>();

    // K4: per-chunk outer products (fast + slow)
    outer_kernel<<<Bq * Hq * NCH, 256>>>();

    // K5: decayed scan across chunks
    scan_kernel<<<Bq * Hq * 16, 256>>>();

    // K6: per-chunk output + gate mixing
    outmix_kernel<<<Bq * Hq * NCH, 256>>>();

    // K7: output projection — TF32 tensor cores
    gemm_tf32_kernel<<<dim3(4, 64, 1), 256, SMEM_GEMM>>>(
        (const float*)p_omix, Wo, Wo, Wo, out, out, out, 0, 0);
}

// round 5
// speedup vs baseline: 2.5682x; 1.0042x over previous
#include <cuda_runtime.h>
#include <math.h>
#include <stdint.h>

#define Bq 2
#define Lq 4096
#define Dq 1024
#define Hq 16
#define HDq 64
#define NCH 32
#define CH 128
#define BHL (Bq*Hq*Lq)

// ---- cp.async GEMM geometry ----
#define GSTG 4
#define GASTRIDE 20                 // A smem row stride (floats), 16 data + 4 pad
#define GBSTRIDE 136                // B smem row stride
#define GABUF (128*GASTRIDE)        // floats per A stage
#define GBBUF (16*GBSTRIDE)         // floats per B stage
#define GSMEM ((GSTG*(GABUF+GBBUF))*4)

// ---------------- device scratch (no allocations allowed) ----------------
__device__ float g_xt[Bq*Lq*Dq];          // tf32-rounded x
__device__ float g_wt[4*Dq*Dq];           // tf32-rounded Wq,Wk,Wv,Wo
__device__ float g_q[Bq*Hq*Lq*HDq];
__device__ float g_k[Bq*Hq*Lq*HDq];
__device__ float g_v[Bq*Hq*Lq*HDq];
__device__ float g_beta[BHL];
__device__ float g_fd[BHL];
__device__ float g_sd[BHL];
__device__ float g_fg[BHL];
__device__ float g_sg[BHL];
__device__ float g_psi[BHL];
__device__ float g_sur[BHL];
__device__ float g_fdm[BHL];
__device__ float g_sdm[BHL];
__device__ float g_gf[Bq*Hq*NCH];
__device__ float g_gs[Bq*Hq*NCH];
__device__ float g_Af[Bq*Hq*NCH*HDq*HDq];
__device__ float g_As[Bq*Hq*NCH*HDq*HDq];
__device__ float g_omix[Bq*Lq*Dq];

__device__ __forceinline__ float sigm(float x) { return 1.f / (1.f + expf(-x)); }

__device__ __forceinline__ float to_tf32(float x) {
    uint32_t u;
    asm("cvt.rna.tf32.f32 %0, %1;" : "=r"(u) : "f"(x));
    return __uint_as_float(u);
}

__device__ __forceinline__ void cp16(float* dst, const float* src) {
    uint32_t d = (uint32_t)__cvta_generic_to_shared(dst);
    asm volatile("cp.async.ca.shared.global [%0], [%1], 16;" :: "r"(d), "l"(src));
}

__device__ __forceinline__ void mma_tf32(
    float& c0, float& c1, float& c2, float& c3,
    uint32_t a0, uint32_t a1, uint32_t a2, uint32_t a3,
    uint32_t b0, uint32_t b1)
{
    asm volatile(
        "mma.sync.aligned.m16n8k8.row.col.f32.tf32.tf32.f32 "
        "{%0,%1,%2,%3}, {%4,%5,%6,%7}, {%8,%9}, {%0,%1,%2,%3};"
        : "+f"(c0), "+f"(c1), "+f"(c2), "+f"(c3)
        : "r"(a0), "r"(a1), "r"(a2), "r"(a3), "r"(b0), "r"(b1));
}

// ---------------- K0: round x and big W's to tf32 (rna) once ----------------
__global__ __launch_bounds__(256) void round_kernel(
    const float* __restrict__ x, const float* __restrict__ Wq,
    const float* __restrict__ Wk, const float* __restrict__ Wv,
    const float* __restrict__ Wo)
{
    size_t i = (size_t)blockIdx.x * 256 + threadIdx.x;   // float4 index
    const float* src; float* dst; size_t off;
    if (i < 2097152) { src = x; dst = g_xt; off = i; }
    else {
        size_t j = i - 2097152;
        int ws = (int)(j >> 18);                          // 0..3
        off = j & 262143;
        src = (ws == 0) ? Wq : (ws == 1) ? Wk : (ws == 2) ? Wv : Wo;
        dst = g_wt + (size_t)ws * (Dq * Dq);
    }
    float4 v = ((const float4*)src)[off];
    ((float4*)dst)[off] = make_float4(to_tf32(v.x), to_tf32(v.y), to_tf32(v.z), to_tf32(v.w));
}

// ---------------- K1/K7: cp.async 4-stage TF32 GEMM, 128x128 tile -----------
// Inputs must be pre-rounded to tf32. z selects (W, C).
__global__ __launch_bounds__(256, 2) void gemm_tf32_kernel(
    const float* __restrict__ A,
    const float* __restrict__ W0, const float* __restrict__ W1, const float* __restrict__ W2,
    float* __restrict__ C0, float* __restrict__ C1, float* __restrict__ C2,
    int doSilu, int headOut)
{
    extern __shared__ float sm[];
    float* As = sm;                     // [GSTG][128][GASTRIDE]
    float* Bs = sm + GSTG * GABUF;      // [GSTG][16][GBSTRIDE]

    const int z = blockIdx.z;
    const float* W = (z == 0) ? W0 : (z == 1) ? W1 : W2;
    float* C = (z == 0) ? C0 : (z == 1) ? C1 : C2;

    const int tid = threadIdx.x;
    const int lane = tid & 31;
    const int wid = tid >> 5;
    const int gid = lane >> 2;          // 0..7
    const int tig = lane & 3;           // 0..3
    const int warpM = (wid & 1) * 64;   // 2 x 4 warp grid, warp tile 64x32
    const int warpN = (wid >> 1) * 32;
    const int bm = blockIdx.y * 128;
    const int bn = blockIdx.x * 128;

    const int a_r = tid >> 1;           // 0..127
    const int a_h = (tid & 1) * 8;      // 0 or 8

    float acc[4][4][4];
#pragma unroll
    for (int mt = 0; mt < 4; mt++)
#pragma unroll
        for (int nt = 0; nt < 4; nt++)
#pragma unroll
            for (int c = 0; c < 4; c++) acc[mt][nt][c] = 0.f;

    const float* Abase = A + (size_t)(bm + a_r) * 1024 + a_h;
    float* AsRow = As + a_r * GASTRIDE + a_h;

    // prologue: stages 0..2
#pragma unroll
    for (int s = 0; s < GSTG - 1; s++) {
        int k0 = s * 16;
        float* ad = AsRow + s * GABUF;
        cp16(ad, Abase + k0);
        cp16(ad + 4, Abase + k0 + 4);
        float* bd = Bs + s * GBBUF;
#pragma unroll
        for (int i = 0; i < 2; i++) {
            int u = tid * 2 + i;
            int kr = u >> 5, nc = (u & 31) * 4;
            cp16(bd + kr * GBSTRIDE + nc, W + (size_t)(k0 + kr) * 1024 + bn + nc);
        }
        asm volatile("cp.async.commit_group;");
    }

#pragma unroll 1
    for (int t = 0; t < 64; t++) {
        asm volatile("cp.async.wait_group 2;");
        __syncthreads();

        // issue loads for tile t+3 into stage (t+3)&3  (overwrites stage used by t-1)
        if (t + 3 < 64) {
            int s = (t + 3) & 3;
            int k0 = (t + 3) * 16;
            float* ad = AsRow + s * GABUF;
            cp16(ad, Abase + k0);
            cp16(ad + 4, Abase + k0 + 4);
            float* bd = Bs + s * GBBUF;
#pragma unroll
            for (int i = 0; i < 2; i++) {
                int u = tid * 2 + i;
                int kr = u >> 5, nc = (u & 31) * 4;
                cp16(bd + kr * GBSTRIDE + nc, W + (size_t)(k0 + kr) * 1024 + bn + nc);
            }
        }
        asm volatile("cp.async.commit_group;");

        // compute tile t from stage t&3
        const float* Asc = As + (t & 3) * GABUF;
        const float* Bsc = Bs + (t & 3) * GBBUF;
#pragma unroll
        for (int kk = 0; kk < 2; kk++) {
            const int kb = kk * 8;
            uint32_t af[4][4];
#pragma unroll
            for (int mt = 0; mt < 4; mt++) {
                int m = warpM + mt * 16 + gid;
                af[mt][0] = __float_as_uint(Asc[m * GASTRIDE + kb + tig]);
                af[mt][1] = __float_as_uint(Asc[(m + 8) * GASTRIDE + kb + tig]);
                af[mt][2] = __float_as_uint(Asc[m * GASTRIDE + kb + tig + 4]);
                af[mt][3] = __float_as_uint(Asc[(m + 8) * GASTRIDE + kb + tig + 4]);
            }
#pragma unroll
            for (int nt = 0; nt < 4; nt++) {
                int n = warpN + nt * 8 + gid;
                uint32_t b0 = __float_as_uint(Bsc[(kb + tig) * GBSTRIDE + n]);
                uint32_t b1 = __float_as_uint(Bsc[(kb + tig + 4) * GBSTRIDE + n]);
#pragma unroll
                for (int mt = 0; mt < 4; mt++) {
                    mma_tf32(acc[mt][nt][0], acc[mt][nt][1], acc[mt][nt][2], acc[mt][nt][3],
                             af[mt][0], af[mt][1], af[mt][2], af[mt][3], b0, b1);
                }
            }
        }
    }

    // epilogue
#pragma unroll
    for (int mt = 0; mt < 4; mt++) {
#pragma unroll
        for (int nt = 0; nt < 4; nt++) {
            int row = bm + warpM + mt * 16 + gid;
            int col = bn + warpN + nt * 8 + tig * 2;
#pragma unroll
            for (int half = 0; half < 2; half++) {
                int r = row + half * 8;
                float v0 = acc[mt][nt][half * 2 + 0];
                float v1 = acc[mt][nt][half * 2 + 1];
                if (doSilu) {
                    v0 = v0 * (1.f / (1.f + expf(-v0)));
                    v1 = v1 * (1.f / (1.f + expf(-v1)));
                }
                if (headOut) {
                    int bb = r >> 12, l = r & 4095;
                    int h = col >> 6, hd = col & 63;
                    *(float2*)(C + (((size_t)(bb * Hq + h) * Lq + l) * HDq) + hd) =
                        make_float2(v0, v1);
                } else {
                    *(float2*)(C + (size_t)r * 1024 + col) = make_float2(v0, v1);
                }
            }
        }
    }
}

// ---------------- K2: small projections via TF32 mma, 64Mx80N tile ----------
#define XSTRIDE 72
#define WSTRIDE 88
__global__ __launch_bounds__(256) void smallproj_kernel(
    const float* __restrict__ x,
    const float* __restrict__ Wbm, const float* __restrict__ Wfd,
    const float* __restrict__ fdb, const float* __restrict__ Wsd,
    const float* __restrict__ sdb, const float* __restrict__ Wfg,
    const float* __restrict__ Wsg)
{
    __shared__ float Xs[2][16][XSTRIDE];
    __shared__ float Ws[2][16][WSTRIDE];
    const int tid = threadIdx.x;
    const int lane = tid & 31;
    const int wid = tid >> 5;
    const int gid = lane >> 2;
    const int tig = lane & 3;
    const int warpM = (wid & 3) * 16;
    const int warpN = (wid >> 2) * 40;
    const int bm = blockIdx.x * 64;

    const int a_r  = tid >> 2;          // 0..63
    const int a_kc = (tid & 3) * 4;

    float acc[5][4];
#pragma unroll
    for (int nt = 0; nt < 5; nt++)
#pragma unroll
        for (int c = 0; c < 4; c++) acc[nt][c] = 0.f;

    {
        float4 xa = *(const float4*)(x + (size_t)(bm + a_r) * 1024 + a_kc);
        Xs[0][a_kc + 0][a_r] = to_tf32(xa.x);
        Xs[0][a_kc + 1][a_r] = to_tf32(xa.y);
        Xs[0][a_kc + 2][a_r] = to_tf32(xa.z);
        Xs[0][a_kc + 3][a_r] = to_tf32(xa.w);
#pragma unroll
        for (int i = 0; i < 5; i++) {
            int idx = tid + i * 256;
            int kr = idx / 80, n = idx % 80;
            int which = n >> 4, h = n & 15;
            const float* Wp = (which == 0) ? Wbm : (which == 1) ? Wfd
                             : (which == 2) ? Wsd : (which == 3) ? Wfg : Wsg;
            Ws[0][kr][n] = to_tf32(Wp[kr * 16 + h]);
        }
    }
    __syncthreads();

#pragma unroll 1
    for (int t = 0; t < 64; t++) {
        const int cur = t & 1;
        float4 xa;
        float wreg[5];
        const bool has_next = (t < 63);
        if (has_next) {
            int k0 = (t + 1) * 16;
            xa = *(const float4*)(x + (size_t)(bm + a_r) * 1024 + k0 + a_kc);
#pragma unroll
            for (int i = 0; i < 5; i++) {
                int idx = tid + i * 256;
                int kr = idx / 80, n = idx % 80;
                int which = n >> 4, h = n & 15;
                const float* Wp = (which == 0) ? Wbm : (which == 1) ? Wfd
                                 : (which == 2) ? Wsd : (which == 3) ? Wfg : Wsg;
                wreg[i] = Wp[(k0 + kr) * 16 + h];
            }
        }

#pragma unroll
        for (int kk = 0; kk < 2; kk++) {
            const int kb = kk * 8;
            uint32_t a0 = __float_as_uint(Xs[cur][kb + tig][warpM + gid]);
            uint32_t a1 = __float_as_uint(Xs[cur][kb + tig][warpM + gid + 8]);
            uint32_t a2 = __float_as_uint(Xs[cur][kb + tig + 4][warpM + gid]);
            uint32_t a3 = __float_as_uint(Xs[cur][kb + tig + 4][warpM + gid + 8]);
#pragma unroll
            for (int nt = 0; nt < 5; nt++) {
                int n = warpN + nt * 8 + gid;
                uint32_t b0 = __float_as_uint(Ws[cur][kb + tig][n]);
                uint32_t b1 = __float_as_uint(Ws[cur][kb + tig + 4][n]);
                mma_tf32(acc[nt][0], acc[nt][1], acc[nt][2], acc[nt][3],
                         a0, a1, a2, a3, b0, b1);
            }
        }

        if (has_next) {
            const int nxt = cur ^ 1;
            Xs[nxt][a_kc + 0][a_r] = to_tf32(xa.x);
            Xs[nxt][a_kc + 1][a_r] = to_tf32(xa.y);
            Xs[nxt][a_kc + 2][a_r] = to_tf32(xa.z);
            Xs[nxt][a_kc + 3][a_r] = to_tf32(xa.w);
#pragma unroll
            for (int i = 0; i < 5; i++) {
                int idx = tid + i * 256;
                int kr = idx / 80, n = idx % 80;
                Ws[nxt][kr][n] = to_tf32(wreg[i]);
            }
        }
        __syncthreads();
    }

#pragma unroll
    for (int nt = 0; nt < 5; nt++) {
#pragma unroll
        for (int half = 0; half < 2; half++) {
            int r = bm + warpM + gid + half * 8;
            int bb = r >> 12, l = r & 4095;
#pragma unroll
            for (int cc = 0; cc < 2; cc++) {
                int col = warpN + nt * 8 + tig * 2 + cc;
                int which = col >> 4, h = col & 15;
                float s = acc[nt][half * 2 + cc];
                if (which == 1) s += fdb[h];
                if (which == 2) s += sdb[h];
                float val = sigm(s);
                float* dst = (which == 0) ? g_beta : (which == 1) ? g_fd
                            : (which == 2) ? g_sd : (which == 3) ? g_fg : g_sg;
                dst[(bb * Hq + h) * Lq + l] = val;
            }
        }
    }
}

// ---------------- K3: per-position prep ----------------
__global__ void prep_kernel()
{
    int gw = (blockIdx.x * blockDim.x + threadIdx.x) >> 5;
    int lane = threadIdx.x & 31;
    if (gw >= BHL) return;
    int p = gw;
    float beta = g_beta[p];
    float2 k2 = ((float2*)g_k)[p * 32 + lane];
    float2 v2 = ((float2*)g_v)[p * 32 + lane];
    k2.x *= beta; k2.y *= beta;
    v2.x *= beta; v2.y *= beta;
    float kk = k2.x * k2.x + k2.y * k2.y;
    float vv = v2.x * v2.x + v2.y * v2.y;
    float kv = k2.x * v2.x + k2.y * v2.y;
#pragma unroll
    for (int off = 16; off; off >>= 1) {
        kk += __shfl_xor_sync(0xffffffffu, kk, off);
        vv += __shfl_xor_sync(0xffffffffu, vv, off);
        kv += __shfl_xor_sync(0xffffffffu, kv, off);
    }
    ((float2*)g_k)[p * 32 + lane] = k2;
    ((float2*)g_v)[p * 32 + lane] = v2;
    if (lane == 0) {
        float kn = sqrtf(kk) + 1e-8f;
        float vn = sqrtf(vv) + 1e-8f;
        float praw = fabsf(kv) / (kn * vn);
        float psi = sigm(3.f * praw);
        float sur = sigm((psi - 0.5f) * 10.f);
        g_psi[p] = psi;
        g_sur[p] = sur;
        g_fdm[p] = g_fd[p] * (1.f - 0.1f * psi);
        g_sdm[p] = g_sd[p] * (1.f - 0.05f * psi);
    }
}

// ---------------- K3b: per-chunk decay means -> g = mean^128 ----------------
__global__ void chunkdecay_kernel()
{
    __shared__ float sf[4], ss[4];
    int bhn = blockIdx.x;
    int t = threadIdx.x;
    int base = (bhn / NCH) * Lq + (bhn % NCH) * CH;
    float f = g_fdm[base + t];
    float s = g_sdm[base + t];
#pragma unroll
    for (int off = 16; off; off >>= 1) {
        f += __shfl_xor_sync(0xffffffffu, f, off);
        s += __shfl_xor_sync(0xffffffffu, s, off);
    }
    int lane = t & 31, wid = t >> 5;
    if (lane == 0) { sf[wid] = f; ss[wid] = s; }
    __syncthreads();
    if (t == 0) {
        float mf = (sf[0] + sf[1] + sf[2] + sf[3]) * (1.f / 128.f);
        float ms = (ss[0] + ss[1] + ss[2] + ss[3]) * (1.f / 128.f);
        float gf = mf, gs = ms;
#pragma unroll
        for (int i = 0; i < 7; i++) { gf *= gf; gs *= gs; }
        g_gf[bhn] = gf;
        g_gs[bhn] = gs;
    }
}

// ---------------- K4: per-chunk outer products (fast + slow fused) ----------
__global__ __launch_bounds__(256) void outer_kernel()
{
    __shared__ float Ks[64 * 64];
    __shared__ float Vs[64 * 64];
    __shared__ float S2[64];
    const int bhn = blockIdx.x;
    const int bh = bhn / NCH, n = bhn % NCH;
    const int t = threadIdx.x;
    const int d0 = (t & 15) * 4;
    const int e0 = (t >> 4) * 4;

    float af[4][4], as_[4][4];
#pragma unroll
    for (int i = 0; i < 4; i++)
#pragma unroll
        for (int j = 0; j < 4; j++) { af[i][j] = 0.f; as_[i][j] = 0.f; }

    for (int half = 0; half < 2; half++) {
        size_t base = ((size_t)bh * Lq + n * CH + half * 64) * HDq;
        for (int i = t; i < 1024; i += 256) {
            ((float4*)Ks)[i] = ((const float4*)(g_k + base))[i];
            ((float4*)Vs)[i] = ((const float4*)(g_v + base))[i];
        }
        if (t < 64) {
            float su = g_sur[bh * Lq + n * CH + half * 64 + t];
            S2[t] = su * su;
        }
        __syncthreads();
#pragma unroll 4
        for (int l = 0; l < 64; l++) {
            float4 vv = *(float4*)&Vs[l * 64 + d0];
            float4 kk = *(float4*)&Ks[l * 64 + e0];
            float s2 = S2[l];
            float v[4] = {vv.x, vv.y, vv.z, vv.w};
            float k[4] = {kk.x, kk.y, kk.z, kk.w};
            float vs[4] = {v[0] * s2, v[1] * s2, v[2] * s2, v[3] * s2};
#pragma unroll
            for (int i = 0; i < 4; i++)
#pragma unroll
                for (int j = 0; j < 4; j++) {
                    af[i][j] += v[i] * k[j];
                    as_[i][j] += vs[i] * k[j];
                }
        }
        __syncthreads();
    }

    size_t abase = (size_t)bhn * 4096;
#pragma unroll
    for (int i = 0; i < 4; i++) {
        *(float4*)&g_Af[abase + (d0 + i) * 64 + e0] =
            make_float4(af[i][0], af[i][1], af[i][2], af[i][3]);
        *(float4*)&g_As[abase + (d0 + i) * 64 + e0] =
            make_float4(as_[i][0], as_[i][1], as_[i][2], as_[i][3]);
    }
}

// ---------------- K5: decayed prefix scan over chunks (in-place) ------------
__global__ void scan_kernel()
{
    int bh = blockIdx.x >> 4;
    int eb = blockIdx.x & 15;
    int entry = eb * 256 + threadIdx.x;
    float sfv = 0.f, ssv = 0.f;
#pragma unroll 1
    for (int n = 0; n < NCH; n++) {
        int bhn = bh * NCH + n;
        float gf = g_gf[bhn], gs = g_gs[bhn];
        size_t idx = (size_t)bhn * 4096 + entry;
        sfv = sfv * gf + g_Af[idx]; g_Af[idx] = sfv;
        ssv = ssv * gs + g_As[idx]; g_As[idx] = ssv;
    }
}

// ---------------- K6: O = Q @ S (fast+slow), gate/alpha mix -> omix ---------
__global__ __launch_bounds__(256) void outmix_kernel()
{
    __shared__ float Sf[4096];
    __shared__ float Ss[4096];
    __shared__ float Qs[32 * 64];
    __shared__ float gA[32], gB[32];
    const int bhn = blockIdx.x;
    const int bh = bhn / NCH, n = bhn % NCH;
    const int b = bh >> 4, h = bh & 15;
    const int t = threadIdx.x;

    size_t abase = (size_t)bhn * 4096;
    for (int i = t; i < 1024; i += 256) {
        ((float4*)Sf)[i] = ((const float4*)(g_Af + abase))[i];
        ((float4*)Ss)[i] = ((const float4*)(g_As + abase))[i];
    }

    const int d = t & 63;
    const int lb = (t >> 6) * 8;

    for (int pass = 0; pass < 4; pass++) {
        int l0 = pass * 32;
        size_t qbase = ((size_t)bh * Lq + n * CH + l0) * HDq;
        for (int i = t; i < 512; i += 256)
            ((float4*)Qs)[i] = ((const float4*)(g_q + qbase))[i];
        if (t < 32) {
            int p = bh * Lq + n * CH + l0 + t;
            float psi = g_psi[p];
            float alpha = 0.5f + 0.3f * psi;
            gA[t] = alpha * g_fg[p];
            gB[t] = (1.f - alpha) * g_sg[p];
        }
        __syncthreads();

        float accf[8], accs[8];
#pragma unroll
        for (int l = 0; l < 8; l++) { accf[l] = 0.f; accs[l] = 0.f; }
#pragma unroll 8
        for (int e = 0; e < 64; e += 2) {
            float sf0 = Sf[e * 64 + d];
            float sf1 = Sf[(e + 1) * 64 + d];
            float ss0 = Ss[e * 64 + d];
            float ss1 = Ss[(e + 1) * 64 + d];
#pragma unroll
            for (int l = 0; l < 8; l++) {
                float2 q2 = *(float2*)&Qs[(lb + l) * 64 + e];
                accf[l] += q2.x * sf0 + q2.y * sf1;
                accs[l] += q2.x * ss0 + q2.y * ss1;
            }
        }
#pragma unroll
        for (int l = 0; l < 8; l++) {
            int ll = lb + l;
            float val = gA[ll] * accf[l] + gB[ll] * accs[l];
            int lglob = n * CH + l0 + ll;
            // tf32-round at source so K7 can consume raw (rna-equivalent accuracy)
            g_omix[((size_t)b * Lq + lglob) * Dq + h * HDq + d] = to_tf32(val);
        }
        __syncthreads();
    }
}

// ---------------- launch ----------------
extern "C" void kernel_launch(void* const* d_in, const int* in_sizes, int n_in,
                              void* d_out, int out_size)
{
    const float* x   = (const float*)d_in[0];
    const float* Wq  = (const float*)d_in[1];
    const float* Wk  = (const float*)d_in[2];
    const float* Wv  = (const float*)d_in[3];
    const float* Wb  = (const float*)d_in[4];
    const float* Wfd = (const float*)d_in[5];
    const float* fdb = (const float*)d_in[6];
    const float* Wsd = (const float*)d_in[7];
    const float* sdb = (const float*)d_in[8];
    const float* Wfg = (const float*)d_in[9];
    const float* Wsg = (const float*)d_in[10];
    const float* Wo  = (const float*)d_in[11];
    float* out = (float*)d_out;

    void *p_q = nullptr, *p_k = nullptr, *p_v = nullptr, *p_omix = nullptr;
    void *p_xt = nullptr, *p_wt = nullptr;
    cudaGetSymbolAddress(&p_q, g_q);
    cudaGetSymbolAddress(&p_k, g_k);
    cudaGetSymbolAddress(&p_v, g_v);
    cudaGetSymbolAddress(&p_omix, g_omix);
    cudaGetSymbolAddress(&p_xt, g_xt);
    cudaGetSymbolAddress(&p_wt, g_wt);
    const float* xt = (const float*)p_xt;
    const float* wt = (const float*)p_wt;

    cudaFuncSetAttribute(gemm_tf32_kernel,
                         cudaFuncAttributeMaxDynamicSharedMemorySize, GSMEM);

    // K0: tf32-round x and the 4 big weight matrices
    round_kernel<<<12288, 256>>>(x, Wq, Wk, Wv, Wo);

    // K1: fused q,k,v projections (silu, head layout)
    gemm_tf32_kernel<<<dim3(8, 64, 3), 256, GSMEM>>>(
        xt, wt, wt + Dq*Dq, wt + 2*Dq*Dq,
        (float*)p_q, (float*)p_k, (float*)p_v, 1, 1);

    // K2: gate projections
    smallproj_kernel<<<128, 256>>>(x, Wb, Wfd, fdb, Wsd, sdb, Wfg, Wsg);

    // K3: beta scaling + psi/surprise/decay-mod
    prep_kernel<<<(BHL * 32) / 256, 256>>>();

    // K3b: per-chunk decay factors
    chunkdecay_kernel<<<Bq * Hq * NCH, 128>>>();

    // K4: per-chunk outer products (fast + slow)
    outer_kernel<<<Bq * Hq * NCH, 256>>>();

    // K5: decayed scan across chunks
    scan_kernel<<<Bq * Hq * 16, 256>>>();

    // K6: per-chunk output + gate mixing (writes tf32-rounded omix)
    outmix_kernel<<<Bq * Hq * NCH, 256>>>();

    // K7: output projection
    gemm_tf32_kernel<<<dim3(8, 64, 1), 256, GSMEM>>>(
        (const float*)p_omix, wt + 3*Dq*Dq, wt + 3*Dq*Dq, wt + 3*Dq*Dq,
        out, out, out, 0, 0);
}

// round 6
// speedup vs baseline: 3.8707x; 1.5072x over previous
#include <cuda_runtime.h>
#include <cuda_fp16.h>
#include <math.h>
#include <stdint.h>

#define Bq 2
#define Lq 4096
#define Dq 1024
#define Hq 16
#define HDq 64
#define NCH 32
#define CH 128
#define BHL (Bq*Hq*Lq)

// ---- fp16 cp.async GEMM geometry ----
#define HSTG 4
#define HBK 32                     // k halves per stage
#define HASTR 40                   // smem row stride in halves (32 data + 8 pad)
#define HSTAGE (128*HASTR)         // halves per stage (A or B)
#define HSMEM (HSTG*2*HSTAGE*2)    // bytes = 81920

// ---------------- device scratch (no allocations allowed) ----------------
__device__ __half g_xh[Bq*Lq*Dq];         // half x, row-major [8192][1024]
__device__ __half g_wh[4*Dq*Dq];          // half W^T: [n][k] for Wq,Wk,Wv,Wo
__device__ __half g_omixh[Bq*Lq*Dq];      // half omix
__device__ float g_q[Bq*Hq*Lq*HDq];
__device__ float g_k[Bq*Hq*Lq*HDq];
__device__ float g_v[Bq*Hq*Lq*HDq];
__device__ float g_beta[BHL];
__device__ float g_fd[BHL];
__device__ float g_sd[BHL];
__device__ float g_fg[BHL];
__device__ float g_sg[BHL];
__device__ float g_psi[BHL];
__device__ float g_sur[BHL];
__device__ float g_fdm[BHL];
__device__ float g_sdm[BHL];
__device__ float g_gf[Bq*Hq*NCH];
__device__ float g_gs[Bq*Hq*NCH];
__device__ float g_Af[Bq*Hq*NCH*HDq*HDq];
__device__ float g_As[Bq*Hq*NCH*HDq*HDq];

__device__ __forceinline__ float sigm(float x) { return 1.f / (1.f + expf(-x)); }

__device__ __forceinline__ float to_tf32(float x) {
    uint32_t u;
    asm("cvt.rna.tf32.f32 %0, %1;" : "=r"(u) : "f"(x));
    return __uint_as_float(u);
}

__device__ __forceinline__ void cp16h(__half* dst, const __half* src) {
    uint32_t d = (uint32_t)__cvta_generic_to_shared(dst);
    asm volatile("cp.async.ca.shared.global [%0], [%1], 16;" :: "r"(d), "l"(src));
}

// tf32 k8 mma (used by smallproj only)
__device__ __forceinline__ void mma_tf32(
    float& c0, float& c1, float& c2, float& c3,
    uint32_t a0, uint32_t a1, uint32_t a2, uint32_t a3,
    uint32_t b0, uint32_t b1)
{
    asm volatile(
        "mma.sync.aligned.m16n8k8.row.col.f32.tf32.tf32.f32 "
        "{%0,%1,%2,%3}, {%4,%5,%6,%7}, {%8,%9}, {%0,%1,%2,%3};"
        : "+f"(c0), "+f"(c1), "+f"(c2), "+f"(c3)
        : "r"(a0), "r"(a1), "r"(a2), "r"(a3), "r"(b0), "r"(b1));
}

// fp16 k16 mma, f32 accum
__device__ __forceinline__ void mma_f16(
    float& c0, float& c1, float& c2, float& c3,
    uint32_t a0, uint32_t a1, uint32_t a2, uint32_t a3,
    uint32_t b0, uint32_t b1)
{
    asm volatile(
        "mma.sync.aligned.m16n8k16.row.col.f32.f16.f16.f32 "
        "{%0,%1,%2,%3}, {%4,%5,%6,%7}, {%8,%9}, {%0,%1,%2,%3};"
        : "+f"(c0), "+f"(c1), "+f"(c2), "+f"(c3)
        : "r"(a0), "r"(a1), "r"(a2), "r"(a3), "r"(b0), "r"(b1));
}

// ---------------- K0a: x -> half ----------------
__global__ __launch_bounds__(256) void xhalf_kernel(const float* __restrict__ x)
{
    size_t i = (size_t)blockIdx.x * 256 + threadIdx.x;    // 8 halves per thread
    const float4* s = (const float4*)x;
    float4 v0 = s[i * 2], v1 = s[i * 2 + 1];
    __half2 h0 = __floats2half2_rn(v0.x, v0.y);
    __half2 h1 = __floats2half2_rn(v0.z, v0.w);
    __half2 h2 = __floats2half2_rn(v1.x, v1.y);
    __half2 h3 = __floats2half2_rn(v1.z, v1.w);
    uint4 o;
    o.x = *(uint32_t*)&h0; o.y = *(uint32_t*)&h1;
    o.z = *(uint32_t*)&h2; o.w = *(uint32_t*)&h3;
    ((uint4*)g_xh)[i] = o;
}

// ---------------- K0b: W -> half, transposed to [n][k] ----------------
__global__ void wtrans_kernel(
    const float* __restrict__ Wq, const float* __restrict__ Wk,
    const float* __restrict__ Wv, const float* __restrict__ Wo)
{
    __shared__ __half tile[32][33];
    const int z = blockIdx.z;
    const float* W = (z == 0) ? Wq : (z == 1) ? Wk : (z == 2) ? Wv : Wo;
    __half* WT = g_wh + (size_t)z * Dq * Dq;
    const int x0 = blockIdx.x * 32;     // n
    const int y0 = blockIdx.y * 32;     // k
    const int tx = threadIdx.x, ty = threadIdx.y;
#pragma unroll
    for (int i = 0; i < 4; i++)
        tile[ty + 8 * i][tx] = __float2half_rn(W[(size_t)(y0 + ty + 8 * i) * 1024 + x0 + tx]);
    __syncthreads();
#pragma unroll
    for (int i = 0; i < 4; i++)
        WT[(size_t)(x0 + ty + 8 * i) * 1024 + y0 + tx] = tile[tx][ty + 8 * i];
}

// ---------------- K1/K7: fp16 cp.async 4-stage GEMM, 128x128 tile -----------
// A: half [8192][1024] row-major. WT: half [1024 n][1024 k]. z selects W/C.
__global__ __launch_bounds__(256, 2) void gemm_f16_kernel(
    const __half* __restrict__ A, const __half* __restrict__ WTbase,
    float* __restrict__ C0, float* __restrict__ C1, float* __restrict__ C2,
    int doSilu, int headOut)
{
    extern __shared__ __half smh[];
    __half* As = smh;                    // [HSTG][128][HASTR]
    __half* Bs = smh + HSTG * HSTAGE;    // [HSTG][128][HASTR]

    const int z = blockIdx.z;
    const __half* WT = WTbase + (size_t)z * Dq * Dq;
    float* C = (z == 0) ? C0 : (z == 1) ? C1 : C2;

    const int tid = threadIdx.x;
    const int lane = tid & 31;
    const int wid = tid >> 5;
    const int gid = lane >> 2;          // 0..7
    const int tig = lane & 3;           // 0..3
    const int warpM = (wid & 1) * 64;   // warp tile 64x32
    const int warpN = (wid >> 1) * 32;
    const int bm = blockIdx.y * 128;
    const int bn = blockIdx.x * 128;

    // loader: 512 x 16B per stage per operand; thread covers u = tid, tid+256
    const int l_r = tid >> 2;            // row 0..63 (and +64)
    const int l_c = (tid & 3) * 8;       // halves offset 0,8,16,24

    float acc[4][4][4];
#pragma unroll
    for (int mt = 0; mt < 4; mt++)
#pragma unroll
        for (int nt = 0; nt < 4; nt++)
#pragma unroll
            for (int c = 0; c < 4; c++) acc[mt][nt][c] = 0.f;

    const __half* Ab0 = A + (size_t)(bm + l_r) * 1024 + l_c;
    const __half* Ab1 = A + (size_t)(bm + l_r + 64) * 1024 + l_c;
    const __half* Bb0 = WT + (size_t)(bn + l_r) * 1024 + l_c;
    const __half* Bb1 = WT + (size_t)(bn + l_r + 64) * 1024 + l_c;
    __half* AsD0 = As + l_r * HASTR + l_c;
    __half* AsD1 = As + (l_r + 64) * HASTR + l_c;
    __half* BsD0 = Bs + l_r * HASTR + l_c;
    __half* BsD1 = Bs + (l_r + 64) * HASTR + l_c;

    // prologue: stages 0..2
#pragma unroll
    for (int s = 0; s < HSTG - 1; s++) {
        int k0 = s * HBK;
        cp16h(AsD0 + s * HSTAGE, Ab0 + k0);
        cp16h(AsD1 + s * HSTAGE, Ab1 + k0);
        cp16h(BsD0 + s * HSTAGE, Bb0 + k0);
        cp16h(BsD1 + s * HSTAGE, Bb1 + k0);
        asm volatile("cp.async.commit_group;");
    }

#pragma unroll 1
    for (int t = 0; t < 32; t++) {
        asm volatile("cp.async.wait_group 2;");
        __syncthreads();

        if (t + 3 < 32) {
            int s = (t + 3) & 3;
            int k0 = (t + 3) * HBK;
            cp16h(AsD0 + s * HSTAGE, Ab0 + k0);
            cp16h(AsD1 + s * HSTAGE, Ab1 + k0);
            cp16h(BsD0 + s * HSTAGE, Bb0 + k0);
            cp16h(BsD1 + s * HSTAGE, Bb1 + k0);
        }
        asm volatile("cp.async.commit_group;");

        const __half* Asc = As + (t & 3) * HSTAGE;
        const __half* Bsc = Bs + (t & 3) * HSTAGE;
#pragma unroll
        for (int ks = 0; ks < 2; ks++) {
            const int kb = ks * 16;
            uint32_t af[4][4];
#pragma unroll
            for (int mt = 0; mt < 4; mt++) {
                int m = warpM + mt * 16 + gid;
                af[mt][0] = *(const uint32_t*)&Asc[m * HASTR + kb + 2 * tig];
                af[mt][1] = *(const uint32_t*)&Asc[(m + 8) * HASTR + kb + 2 * tig];
                af[mt][2] = *(const uint32_t*)&Asc[m * HASTR + kb + 2 * tig + 8];
                af[mt][3] = *(const uint32_t*)&Asc[(m + 8) * HASTR + kb + 2 * tig + 8];
            }
#pragma unroll
            for (int nt = 0; nt < 4; nt++) {
                int n = warpN + nt * 8 + gid;
                uint32_t b0 = *(const uint32_t*)&Bsc[n * HASTR + kb + 2 * tig];
                uint32_t b1 = *(const uint32_t*)&Bsc[n * HASTR + kb + 2 * tig + 8];
#pragma unroll
                for (int mt = 0; mt < 4; mt++) {
                    mma_f16(acc[mt][nt][0], acc[mt][nt][1], acc[mt][nt][2], acc[mt][nt][3],
                            af[mt][0], af[mt][1], af[mt][2], af[mt][3], b0, b1);
                }
            }
        }
    }

    // epilogue
#pragma unroll
    for (int mt = 0; mt < 4; mt++) {
#pragma unroll
        for (int nt = 0; nt < 4; nt++) {
            int row = bm + warpM + mt * 16 + gid;
            int col = bn + warpN + nt * 8 + tig * 2;
#pragma unroll
            for (int half_ = 0; half_ < 2; half_++) {
                int r = row + half_ * 8;
                float v0 = acc[mt][nt][half_ * 2 + 0];
                float v1 = acc[mt][nt][half_ * 2 + 1];
                if (doSilu) {
                    v0 = v0 * (1.f / (1.f + expf(-v0)));
                    v1 = v1 * (1.f / (1.f + expf(-v1)));
                }
                if (headOut) {
                    int bb = r >> 12, l = r & 4095;
                    int h = col >> 6, hd = col & 63;
                    *(float2*)(C + (((size_t)(bb * Hq + h) * Lq + l) * HDq) + hd) =
                        make_float2(v0, v1);
                } else {
                    *(float2*)(C + (size_t)r * 1024 + col) = make_float2(v0, v1);
                }
            }
        }
    }
}

// ---------------- K2: small projections via TF32 mma, 64Mx80N tile ----------
#define XSTRIDE 72
#define WSTRIDE 88
__global__ __launch_bounds__(256) void smallproj_kernel(
    const float* __restrict__ x,
    const float* __restrict__ Wbm, const float* __restrict__ Wfd,
    const float* __restrict__ fdb, const float* __restrict__ Wsd,
    const float* __restrict__ sdb, const float* __restrict__ Wfg,
    const float* __restrict__ Wsg)
{
    __shared__ float Xs[2][16][XSTRIDE];
    __shared__ float Ws[2][16][WSTRIDE];
    const int tid = threadIdx.x;
    const int lane = tid & 31;
    const int wid = tid >> 5;
    const int gid = lane >> 2;
    const int tig = lane & 3;
    const int warpM = (wid & 3) * 16;
    const int warpN = (wid >> 2) * 40;
    const int bm = blockIdx.x * 64;

    const int a_r  = tid >> 2;
    const int a_kc = (tid & 3) * 4;

    float acc[5][4];
#pragma unroll
    for (int nt = 0; nt < 5; nt++)
#pragma unroll
        for (int c = 0; c < 4; c++) acc[nt][c] = 0.f;

    {
        float4 xa = *(const float4*)(x + (size_t)(bm + a_r) * 1024 + a_kc);
        Xs[0][a_kc + 0][a_r] = to_tf32(xa.x);
        Xs[0][a_kc + 1][a_r] = to_tf32(xa.y);
        Xs[0][a_kc + 2][a_r] = to_tf32(xa.z);
        Xs[0][a_kc + 3][a_r] = to_tf32(xa.w);
#pragma unroll
        for (int i = 0; i < 5; i++) {
            int idx = tid + i * 256;
            int kr = idx / 80, n = idx % 80;
            int which = n >> 4, h = n & 15;
            const float* Wp = (which == 0) ? Wbm : (which == 1) ? Wfd
                             : (which == 2) ? Wsd : (which == 3) ? Wfg : Wsg;
            Ws[0][kr][n] = to_tf32(Wp[kr * 16 + h]);
        }
    }
    __syncthreads();

#pragma unroll 1
    for (int t = 0; t < 64; t++) {
        const int cur = t & 1;
        float4 xa;
        float wreg[5];
        const bool has_next = (t < 63);
        if (has_next) {
            int k0 = (t + 1) * 16;
            xa = *(const float4*)(x + (size_t)(bm + a_r) * 1024 + k0 + a_kc);
#pragma unroll
            for (int i = 0; i < 5; i++) {
                int idx = tid + i * 256;
                int kr = idx / 80, n = idx % 80;
                int which = n >> 4, h = n & 15;
                const float* Wp = (which == 0) ? Wbm : (which == 1) ? Wfd
                                 : (which == 2) ? Wsd : (which == 3) ? Wfg : Wsg;
                wreg[i] = Wp[(k0 + kr) * 16 + h];
            }
        }

#pragma unroll
        for (int kk = 0; kk < 2; kk++) {
            const int kb = kk * 8;
            uint32_t a0 = __float_as_uint(Xs[cur][kb + tig][warpM + gid]);
            uint32_t a1 = __float_as_uint(Xs[cur][kb + tig][warpM + gid + 8]);
            uint32_t a2 = __float_as_uint(Xs[cur][kb + tig + 4][warpM + gid]);
            uint32_t a3 = __float_as_uint(Xs[cur][kb + tig + 4][warpM + gid + 8]);
#pragma unroll
            for (int nt = 0; nt < 5; nt++) {
                int n = warpN + nt * 8 + gid;
                uint32_t b0 = __float_as_uint(Ws[cur][kb + tig][n]);
                uint32_t b1 = __float_as_uint(Ws[cur][kb + tig + 4][n]);
                mma_tf32(acc[nt][0], acc[nt][1], acc[nt][2], acc[nt][3],
                         a0, a1, a2, a3, b0, b1);
            }
        }

        if (has_next) {
            const int nxt = cur ^ 1;
            Xs[nxt][a_kc + 0][a_r] = to_tf32(xa.x);
            Xs[nxt][a_kc + 1][a_r] = to_tf32(xa.y);
            Xs[nxt][a_kc + 2][a_r] = to_tf32(xa.z);
            Xs[nxt][a_kc + 3][a_r] = to_tf32(xa.w);
#pragma unroll
            for (int i = 0; i < 5; i++) {
                int idx = tid + i * 256;
                int kr = idx / 80, n = idx % 80;
                Ws[nxt][kr][n] = to_tf32(wreg[i]);
            }
        }
        __syncthreads();
    }

#pragma unroll
    for (int nt = 0; nt < 5; nt++) {
#pragma unroll
        for (int half_ = 0; half_ < 2; half_++) {
            int r = bm + warpM + gid + half_ * 8;
            int bb = r >> 12, l = r & 4095;
#pragma unroll
            for (int cc = 0; cc < 2; cc++) {
                int col = warpN + nt * 8 + tig * 2 + cc;
                int which = col >> 4, h = col & 15;
                float s = acc[nt][half_ * 2 + cc];
                if (which == 1) s += fdb[h];
                if (which == 2) s += sdb[h];
                float val = sigm(s);
                float* dst = (which == 0) ? g_beta : (which == 1) ? g_fd
                            : (which == 2) ? g_sd : (which == 3) ? g_fg : g_sg;
                dst[(bb * Hq + h) * Lq + l] = val;
            }
        }
    }
}

// ---------------- K3: per-position prep ----------------
__global__ void prep_kernel()
{
    int gw = (blockIdx.x * blockDim.x + threadIdx.x) >> 5;
    int lane = threadIdx.x & 31;
    if (gw >= BHL) return;
    int p = gw;
    float beta = g_beta[p];
    float2 k2 = ((float2*)g_k)[p * 32 + lane];
    float2 v2 = ((float2*)g_v)[p * 32 + lane];
    k2.x *= beta; k2.y *= beta;
    v2.x *= beta; v2.y *= beta;
    float kk = k2.x * k2.x + k2.y * k2.y;
    float vv = v2.x * v2.x + v2.y * v2.y;
    float kv = k2.x * v2.x + k2.y * v2.y;
#pragma unroll
    for (int off = 16; off; off >>= 1) {
        kk += __shfl_xor_sync(0xffffffffu, kk, off);
        vv += __shfl_xor_sync(0xffffffffu, vv, off);
        kv += __shfl_xor_sync(0xffffffffu, kv, off);
    }
    ((float2*)g_k)[p * 32 + lane] = k2;
    ((float2*)g_v)[p * 32 + lane] = v2;
    if (lane == 0) {
        float kn = sqrtf(kk) + 1e-8f;
        float vn = sqrtf(vv) + 1e-8f;
        float praw = fabsf(kv) / (kn * vn);
        float psi = sigm(3.f * praw);
        float sur = sigm((psi - 0.5f) * 10.f);
        g_psi[p] = psi;
        g_sur[p] = sur;
        g_fdm[p] = g_fd[p] * (1.f - 0.1f * psi);
        g_sdm[p] = g_sd[p] * (1.f - 0.05f * psi);
    }
}

// ---------------- K3b: per-chunk decay means -> g = mean^128 ----------------
__global__ void chunkdecay_kernel()
{
    __shared__ float sf[4], ss[4];
    int bhn = blockIdx.x;
    int t = threadIdx.x;
    int base = (bhn / NCH) * Lq + (bhn % NCH) * CH;
    float f = g_fdm[base + t];
    float s = g_sdm[base + t];
#pragma unroll
    for (int off = 16; off; off >>= 1) {
        f += __shfl_xor_sync(0xffffffffu, f, off);
        s += __shfl_xor_sync(0xffffffffu, s, off);
    }
    int lane = t & 31, wid = t >> 5;
    if (lane == 0) { sf[wid] = f; ss[wid] = s; }
    __syncthreads();
    if (t == 0) {
        float mf = (sf[0] + sf[1] + sf[2] + sf[3]) * (1.f / 128.f);
        float ms = (ss[0] + ss[1] + ss[2] + ss[3]) * (1.f / 128.f);
        float gf = mf, gs = ms;
#pragma unroll
        for (int i = 0; i < 7; i++) { gf *= gf; gs *= gs; }
        g_gf[bhn] = gf;
        g_gs[bhn] = gs;
    }
}

// ---------------- K4: per-chunk outer products (fast + slow fused) ----------
__global__ __launch_bounds__(256) void outer_kernel()
{
    __shared__ float Ks[64 * 64];
    __shared__ float Vs[64 * 64];
    __shared__ float S2[64];
    const int bhn = blockIdx.x;
    const int bh = bhn / NCH, n = bhn % NCH;
    const int t = threadIdx.x;
    const int d0 = (t & 15) * 4;
    const int e0 = (t >> 4) * 4;

    float af[4][4], as_[4][4];
#pragma unroll
    for (int i = 0; i < 4; i++)
#pragma unroll
        for (int j = 0; j < 4; j++) { af[i][j] = 0.f; as_[i][j] = 0.f; }

    for (int half_ = 0; half_ < 2; half_++) {
        size_t base = ((size_t)bh * Lq + n * CH + half_ * 64) * HDq;
        for (int i = t; i < 1024; i += 256) {
            ((float4*)Ks)[i] = ((const float4*)(g_k + base))[i];
            ((float4*)Vs)[i] = ((const float4*)(g_v + base))[i];
        }
        if (t < 64) {
            float su = g_sur[bh * Lq + n * CH + half_ * 64 + t];
            S2[t] = su * su;
        }
        __syncthreads();
#pragma unroll 4
        for (int l = 0; l < 64; l++) {
            float4 vv = *(float4*)&Vs[l * 64 + d0];
            float4 kk = *(float4*)&Ks[l * 64 + e0];
            float s2 = S2[l];
            float v[4] = {vv.x, vv.y, vv.z, vv.w};
            float k[4] = {kk.x, kk.y, kk.z, kk.w};
            float vs[4] = {v[0] * s2, v[1] * s2, v[2] * s2, v[3] * s2};
#pragma unroll
            for (int i = 0; i < 4; i++)
#pragma unroll
                for (int j = 0; j < 4; j++) {
                    af[i][j] += v[i] * k[j];
                    as_[i][j] += vs[i] * k[j];
                }
        }
        __syncthreads();
    }

    size_t abase = (size_t)bhn * 4096;
#pragma unroll
    for (int i = 0; i < 4; i++) {
        *(float4*)&g_Af[abase + (d0 + i) * 64 + e0] =
            make_float4(af[i][0], af[i][1], af[i][2], af[i][3]);
        *(float4*)&g_As[abase + (d0 + i) * 64 + e0] =
            make_float4(as_[i][0], as_[i][1], as_[i][2], as_[i][3]);
    }
}

// ---------------- K5: decayed prefix scan over chunks (in-place) ------------
__global__ void scan_kernel()
{
    int bh = blockIdx.x >> 4;
    int eb = blockIdx.x & 15;
    int entry = eb * 256 + threadIdx.x;
    float sfv = 0.f, ssv = 0.f;
#pragma unroll 1
    for (int n = 0; n < NCH; n++) {
        int bhn = bh * NCH + n;
        float gf = g_gf[bhn], gs = g_gs[bhn];
        size_t idx = (size_t)bhn * 4096 + entry;
        sfv = sfv * gf + g_Af[idx]; g_Af[idx] = sfv;
        ssv = ssv * gs + g_As[idx]; g_As[idx] = ssv;
    }
}

// ---------------- K6: O = Q @ S (fast+slow), gate/alpha mix -> omix (half) --
__global__ __launch_bounds__(256) void outmix_kernel()
{
    __shared__ float Sf[4096];
    __shared__ float Ss[4096];
    __shared__ float Qs[32 * 64];
    __shared__ float gA[32], gB[32];
    const int bhn = blockIdx.x;
    const int bh = bhn / NCH, n = bhn % NCH;
    const int b = bh >> 4, h = bh & 15;
    const int t = threadIdx.x;

    size_t abase = (size_t)bhn * 4096;
    for (int i = t; i < 1024; i += 256) {
        ((float4*)Sf)[i] = ((const float4*)(g_Af + abase))[i];
        ((float4*)Ss)[i] = ((const float4*)(g_As + abase))[i];
    }

    const int d = t & 63;
    const int lb = (t >> 6) * 8;

    for (int pass = 0; pass < 4; pass++) {
        int l0 = pass * 32;
        size_t qbase = ((size_t)bh * Lq + n * CH + l0) * HDq;
        for (int i = t; i < 512; i += 256)
            ((float4*)Qs)[i] = ((const float4*)(g_q + qbase))[i];
        if (t < 32) {
            int p = bh * Lq + n * CH + l0 + t;
            float psi = g_psi[p];
            float alpha = 0.5f + 0.3f * psi;
            gA[t] = alpha * g_fg[p];
            gB[t] = (1.f - alpha) * g_sg[p];
        }
        __syncthreads();

        float accf[8], accs[8];
#pragma unroll
        for (int l = 0; l < 8; l++) { accf[l] = 0.f; accs[l] = 0.f; }
#pragma unroll 8
        for (int e = 0; e < 64; e += 2) {
            float sf0 = Sf[e * 64 + d];
            float sf1 = Sf[(e + 1) * 64 + d];
            float ss0 = Ss[e * 64 + d];
            float ss1 = Ss[(e + 1) * 64 + d];
#pragma unroll
            for (int l = 0; l < 8; l++) {
                float2 q2 = *(float2*)&Qs[(lb + l) * 64 + e];
                accf[l] += q2.x * sf0 + q2.y * sf1;
                accs[l] += q2.x * ss0 + q2.y * ss1;
            }
        }
#pragma unroll
        for (int l = 0; l < 8; l++) {
            int ll = lb + l;
            float val = gA[ll] * accf[l] + gB[ll] * accs[l];
            int lglob = n * CH + l0 + ll;
            g_omixh[((size_t)b * Lq + lglob) * Dq + h * HDq + d] = __float2half_rn(val);
        }
        __syncthreads();
    }
}

// ---------------- launch ----------------
extern "C" void kernel_launch(void* const* d_in, const int* in_sizes, int n_in,
                              void* d_out, int out_size)
{
    const float* x   = (const float*)d_in[0];
    const float* Wq  = (const float*)d_in[1];
    const float* Wk  = (const float*)d_in[2];
    const float* Wv  = (const float*)d_in[3];
    const float* Wb  = (const float*)d_in[4];
    const float* Wfd = (const float*)d_in[5];
    const float* fdb = (const float*)d_in[6];
    const float* Wsd = (const float*)d_in[7];
    const float* sdb = (const float*)d_in[8];
    const float* Wfg = (const float*)d_in[9];
    const float* Wsg = (const float*)d_in[10];
    const float* Wo  = (const float*)d_in[11];
    float* out = (float*)d_out;

    void *p_q = nullptr, *p_k = nullptr, *p_v = nullptr;
    void *p_xh = nullptr, *p_wh = nullptr, *p_oh = nullptr;
    cudaGetSymbolAddress(&p_q, g_q);
    cudaGetSymbolAddress(&p_k, g_k);
    cudaGetSymbolAddress(&p_v, g_v);
    cudaGetSymbolAddress(&p_xh, g_xh);
    cudaGetSymbolAddress(&p_wh, g_wh);
    cudaGetSymbolAddress(&p_oh, g_omixh);

    cudaFuncSetAttribute(gemm_f16_kernel,
                         cudaFuncAttributeMaxDynamicSharedMemorySize, HSMEM);

    // K0: convert x -> half; W -> half transposed
    xhalf_kernel<<<4096, 256>>>(x);
    wtrans_kernel<<<dim3(32, 32, 4), dim3(32, 8)>>>(Wq, Wk, Wv, Wo);

    // K1: fused q,k,v projections (silu, head layout), fp16 tensor cores
    gemm_f16_kernel<<<dim3(8, 64, 3), 256, HSMEM>>>(
        (const __half*)p_xh, (const __half*)p_wh,
        (float*)p_q, (float*)p_k, (float*)p_v, 1, 1);

    // K2: gate projections
    smallproj_kernel<<<128, 256>>>(x, Wb, Wfd, fdb, Wsd, sdb, Wfg, Wsg);

    // K3: beta scaling + psi/surprise/decay-mod
    prep_kernel<<<(BHL * 32) / 256, 256>>>();

    // K3b: per-chunk decay factors
    chunkdecay_kernel<<<Bq * Hq * NCH, 128>>>();

    // K4: per-chunk outer products (fast + slow)
    outer_kernel<<<Bq * Hq * NCH, 256>>>();

    // K5: decayed scan across chunks
    scan_kernel<<<Bq * Hq * 16, 256>>>();

    // K6: per-chunk output + gate mixing (writes half omix)
    outmix_kernel<<<Bq * Hq * NCH, 256>>>();

    // K7: output projection, fp16 tensor cores (Wo is wt slot 3)
    gemm_f16_kernel<<<dim3(8, 64, 1), 256, HSMEM>>>(
        (const __half*)p_oh, (const __half*)p_wh + (size_t)3 * Dq * Dq,
        out, out, out, 0, 0);
}

// round 7
// speedup vs baseline: 4.1727x; 1.0780x over previous
#include <cuda_runtime.h>
#include <cuda_fp16.h>
#include <math.h>
#include <stdint.h>

#define Bq 2
#define Lq 4096
#define Dq 1024
#define Hq 16
#define HDq 64
#define NCH 32
#define CH 128
#define BHL (Bq*Hq*Lq)

// ---- fp16 cp.async GEMM geometry ----
#define HSTG 4
#define HBK 32                     // k halves per stage
#define HASTR 40                   // smem row stride in halves (32 data + 8 pad)
#define HSTAGE (128*HASTR)         // halves per stage (A or B)
#define HSMEM (HSTG*2*HSTAGE*2)    // bytes = 81920

// ---------------- device scratch (no allocations allowed) ----------------
__device__ __half g_xh[Bq*Lq*Dq];         // half x, row-major [8192][1024]
__device__ __half g_wh[4*Dq*Dq];          // half W^T: [n][k] for Wq,Wk,Wv,Wo
__device__ __half g_gwh[128*Dq];          // packed gate weights^T [128 n][1024 k]
__device__ __half g_omixh[Bq*Lq*Dq];      // half omix
__device__ float g_q[Bq*Hq*Lq*HDq];
__device__ float g_k[Bq*Hq*Lq*HDq];
__device__ float g_v[Bq*Hq*Lq*HDq];
__device__ float g_beta[BHL];
__device__ float g_fd[BHL];
__device__ float g_sd[BHL];
__device__ float g_fg[BHL];
__device__ float g_sg[BHL];
__device__ float g_psi[BHL];
__device__ float g_sur[BHL];
__device__ float g_fdm[BHL];
__device__ float g_sdm[BHL];
__device__ float g_gf[Bq*Hq*NCH];
__device__ float g_gs[Bq*Hq*NCH];
__device__ float g_Af[Bq*Hq*NCH*HDq*HDq];
__device__ float g_As[Bq*Hq*NCH*HDq*HDq];

__device__ __forceinline__ float sigm(float x) { return 1.f / (1.f + expf(-x)); }

__device__ __forceinline__ void cp16h(__half* dst, const __half* src) {
    uint32_t d = (uint32_t)__cvta_generic_to_shared(dst);
    asm volatile("cp.async.ca.shared.global [%0], [%1], 16;" :: "r"(d), "l"(src));
}

// fp16 k16 mma, f32 accum
__device__ __forceinline__ void mma_f16(
    float& c0, float& c1, float& c2, float& c3,
    uint32_t a0, uint32_t a1, uint32_t a2, uint32_t a3,
    uint32_t b0, uint32_t b1)
{
    asm volatile(
        "mma.sync.aligned.m16n8k16.row.col.f32.f16.f16.f32 "
        "{%0,%1,%2,%3}, {%4,%5,%6,%7}, {%8,%9}, {%0,%1,%2,%3};"
        : "+f"(c0), "+f"(c1), "+f"(c2), "+f"(c3)
        : "r"(a0), "r"(a1), "r"(a2), "r"(a3), "r"(b0), "r"(b1));
}

// ---------------- K0a: x -> half ----------------
__global__ __launch_bounds__(256) void xhalf_kernel(const float* __restrict__ x)
{
    size_t i = (size_t)blockIdx.x * 256 + threadIdx.x;    // 8 halves per thread
    const float4* s = (const float4*)x;
    float4 v0 = s[i * 2], v1 = s[i * 2 + 1];
    __half2 h0 = __floats2half2_rn(v0.x, v0.y);
    __half2 h1 = __floats2half2_rn(v0.z, v0.w);
    __half2 h2 = __floats2half2_rn(v1.x, v1.y);
    __half2 h3 = __floats2half2_rn(v1.z, v1.w);
    uint4 o;
    o.x = *(uint32_t*)&h0; o.y = *(uint32_t*)&h1;
    o.z = *(uint32_t*)&h2; o.w = *(uint32_t*)&h3;
    ((uint4*)g_xh)[i] = o;
}

// ---------------- K0b: W -> half, transposed to [n][k] ----------------
__global__ void wtrans_kernel(
    const float* __restrict__ Wq, const float* __restrict__ Wk,
    const float* __restrict__ Wv, const float* __restrict__ Wo)
{
    __shared__ __half tile[32][33];
    const int z = blockIdx.z;
    const float* W = (z == 0) ? Wq : (z == 1) ? Wk : (z == 2) ? Wv : Wo;
    __half* WT = g_wh + (size_t)z * Dq * Dq;
    const int x0 = blockIdx.x * 32;     // n
    const int y0 = blockIdx.y * 32;     // k
    const int tx = threadIdx.x, ty = threadIdx.y;
#pragma unroll
    for (int i = 0; i < 4; i++)
        tile[ty + 8 * i][tx] = __float2half_rn(W[(size_t)(y0 + ty + 8 * i) * 1024 + x0 + tx]);
    __syncthreads();
#pragma unroll
    for (int i = 0; i < 4; i++)
        WT[(size_t)(x0 + ty + 8 * i) * 1024 + y0 + tx] = tile[tx][ty + 8 * i];
}

// ---------------- K0c: pack 5 gate weights -> [128 n][1024 k] half ---------
__global__ __launch_bounds__(256) void gwpack_kernel(
    const float* __restrict__ Wbm, const float* __restrict__ Wfd,
    const float* __restrict__ Wsd, const float* __restrict__ Wfg,
    const float* __restrict__ Wsg)
{
    int idx = blockIdx.x * 256 + threadIdx.x;   // 0..131071
    int n = idx >> 10, k = idx & 1023;
    __half val = __float2half_rn(0.f);
    if (n < 80) {
        int which = n >> 4, h = n & 15;
        const float* Wp = (which == 0) ? Wbm : (which == 1) ? Wfd
                         : (which == 2) ? Wsd : (which == 3) ? Wfg : Wsg;
        val = __float2half_rn(Wp[k * 16 + h]);
    }
    g_gwh[n * 1024 + k] = val;
}

// ---------------- K1/K2/K7: fp16 cp.async 4-stage GEMM, 128x128 tile --------
// A: half [8192][1024] rm. WT: half [N][1024] (n-major). mode:
//   0 = plain fp32 C (row*1024+col)          (K7)
//   1 = silu + head layout; z>=1 also *beta  (QKV; z selects W slice & q/k/v)
//   3 = gate epilogue: bias+sigmoid, scatter to g_beta/g_fd/g_sd/g_fg/g_sg
__global__ __launch_bounds__(256, 2) void gemm_f16_kernel(
    const __half* __restrict__ A, const __half* __restrict__ WTbase,
    float* __restrict__ C0, float* __restrict__ C1, float* __restrict__ C2,
    const float* __restrict__ fdb, const float* __restrict__ sdb,
    int mode)
{
    extern __shared__ __half smh[];
    __half* As = smh;                    // [HSTG][128][HASTR]
    __half* Bs = smh + HSTG * HSTAGE;    // [HSTG][128][HASTR]

    const int z = blockIdx.z;
    const __half* WT = WTbase + (size_t)z * Dq * Dq;
    float* C = (z == 0) ? C0 : (z == 1) ? C1 : C2;

    const int tid = threadIdx.x;
    const int lane = tid & 31;
    const int wid = tid >> 5;
    const int gid = lane >> 2;          // 0..7
    const int tig = lane & 3;           // 0..3
    const int warpM = (wid & 1) * 64;   // warp tile 64x32
    const int warpN = (wid >> 1) * 32;
    const int bm = blockIdx.y * 128;
    const int bn = blockIdx.x * 128;

    const int l_r = tid >> 2;            // row 0..63 (and +64)
    const int l_c = (tid & 3) * 8;       // halves offset 0,8,16,24

    float acc[4][4][4];
#pragma unroll
    for (int mt = 0; mt < 4; mt++)
#pragma unroll
        for (int nt = 0; nt < 4; nt++)
#pragma unroll
            for (int c = 0; c < 4; c++) acc[mt][nt][c] = 0.f;

    const __half* Ab0 = A + (size_t)(bm + l_r) * 1024 + l_c;
    const __half* Ab1 = A + (size_t)(bm + l_r + 64) * 1024 + l_c;
    const __half* Bb0 = WT + (size_t)(bn + l_r) * 1024 + l_c;
    const __half* Bb1 = WT + (size_t)(bn + l_r + 64) * 1024 + l_c;
    __half* AsD0 = As + l_r * HASTR + l_c;
    __half* AsD1 = As + (l_r + 64) * HASTR + l_c;
    __half* BsD0 = Bs + l_r * HASTR + l_c;
    __half* BsD1 = Bs + (l_r + 64) * HASTR + l_c;

#pragma unroll
    for (int s = 0; s < HSTG - 1; s++) {
        int k0 = s * HBK;
        cp16h(AsD0 + s * HSTAGE, Ab0 + k0);
        cp16h(AsD1 + s * HSTAGE, Ab1 + k0);
        cp16h(BsD0 + s * HSTAGE, Bb0 + k0);
        cp16h(BsD1 + s * HSTAGE, Bb1 + k0);
        asm volatile("cp.async.commit_group;");
    }

#pragma unroll 1
    for (int t = 0; t < 32; t++) {
        asm volatile("cp.async.wait_group 2;");
        __syncthreads();

        if (t + 3 < 32) {
            int s = (t + 3) & 3;
            int k0 = (t + 3) * HBK;
            cp16h(AsD0 + s * HSTAGE, Ab0 + k0);
            cp16h(AsD1 + s * HSTAGE, Ab1 + k0);
            cp16h(BsD0 + s * HSTAGE, Bb0 + k0);
            cp16h(BsD1 + s * HSTAGE, Bb1 + k0);
        }
        asm volatile("cp.async.commit_group;");

        const __half* Asc = As + (t & 3) * HSTAGE;
        const __half* Bsc = Bs + (t & 3) * HSTAGE;
#pragma unroll
        for (int ks = 0; ks < 2; ks++) {
            const int kb = ks * 16;
            uint32_t af[4][4];
#pragma unroll
            for (int mt = 0; mt < 4; mt++) {
                int m = warpM + mt * 16 + gid;
                af[mt][0] = *(const uint32_t*)&Asc[m * HASTR + kb + 2 * tig];
                af[mt][1] = *(const uint32_t*)&Asc[(m + 8) * HASTR + kb + 2 * tig];
                af[mt][2] = *(const uint32_t*)&Asc[m * HASTR + kb + 2 * tig + 8];
                af[mt][3] = *(const uint32_t*)&Asc[(m + 8) * HASTR + kb + 2 * tig + 8];
            }
#pragma unroll
            for (int nt = 0; nt < 4; nt++) {
                int n = warpN + nt * 8 + gid;
                uint32_t b0 = *(const uint32_t*)&Bsc[n * HASTR + kb + 2 * tig];
                uint32_t b1 = *(const uint32_t*)&Bsc[n * HASTR + kb + 2 * tig + 8];
#pragma unroll
                for (int mt = 0; mt < 4; mt++) {
                    mma_f16(acc[mt][nt][0], acc[mt][nt][1], acc[mt][nt][2], acc[mt][nt][3],
                            af[mt][0], af[mt][1], af[mt][2], af[mt][3], b0, b1);
                }
            }
        }
    }

    // epilogue
#pragma unroll
    for (int mt = 0; mt < 4; mt++) {
#pragma unroll
        for (int nt = 0; nt < 4; nt++) {
            int row = bm + warpM + mt * 16 + gid;
            int col = bn + warpN + nt * 8 + tig * 2;
#pragma unroll
            for (int half_ = 0; half_ < 2; half_++) {
                int r = row + half_ * 8;
                float v0 = acc[mt][nt][half_ * 2 + 0];
                float v1 = acc[mt][nt][half_ * 2 + 1];
                int bb = r >> 12, l = r & 4095;
                if (mode == 1) {
                    v0 = v0 * (1.f / (1.f + expf(-v0)));
                    v1 = v1 * (1.f / (1.f + expf(-v1)));
                    int h = col >> 6, hd = col & 63;
                    if (z >= 1) {
                        float b = g_beta[(bb * Hq + h) * Lq + l];
                        v0 *= b; v1 *= b;
                    }
                    *(float2*)(C + (((size_t)(bb * Hq + h) * Lq + l) * HDq) + hd) =
                        make_float2(v0, v1);
                } else if (mode == 3) {
#pragma unroll
                    for (int cc = 0; cc < 2; cc++) {
                        int cl = col + cc;
                        if (cl < 80) {
                            int which = cl >> 4, h = cl & 15;
                            float s = (cc == 0) ? v0 : v1;
                            if (which == 1) s += fdb[h];
                            if (which == 2) s += sdb[h];
                            float val = sigm(s);
                            float* dst = (which == 0) ? g_beta : (which == 1) ? g_fd
                                        : (which == 2) ? g_sd : (which == 3) ? g_fg : g_sg;
                            dst[(bb * Hq + h) * Lq + l] = val;
                        }
                    }
                } else {
                    *(float2*)(C + (size_t)r * 1024 + col) = make_float2(v0, v1);
                }
            }
        }
    }
}

// ---------------- K3: per-position prep (read-only k,v; psi/sur/decays) -----
__global__ void prep_kernel()
{
    int gw = (blockIdx.x * blockDim.x + threadIdx.x) >> 5;
    int lane = threadIdx.x & 31;
    if (gw >= BHL) return;
    int p = gw;
    float2 k2 = ((const float2*)g_k)[p * 32 + lane];
    float2 v2 = ((const float2*)g_v)[p * 32 + lane];
    float kk = k2.x * k2.x + k2.y * k2.y;
    float vv = v2.x * v2.x + v2.y * v2.y;
    float kv = k2.x * v2.x + k2.y * v2.y;
#pragma unroll
    for (int off = 16; off; off >>= 1) {
        kk += __shfl_xor_sync(0xffffffffu, kk, off);
        vv += __shfl_xor_sync(0xffffffffu, vv, off);
        kv += __shfl_xor_sync(0xffffffffu, kv, off);
    }
    if (lane == 0) {
        float kn = sqrtf(kk) + 1e-8f;
        float vn = sqrtf(vv) + 1e-8f;
        float praw = fabsf(kv) / (kn * vn);
        float psi = sigm(3.f * praw);
        float sur = sigm((psi - 0.5f) * 10.f);
        g_psi[p] = psi;
        g_sur[p] = sur;
        g_fdm[p] = g_fd[p] * (1.f - 0.1f * psi);
        g_sdm[p] = g_sd[p] * (1.f - 0.05f * psi);
    }
}

// ---------------- K3b: per-chunk decay means -> g = mean^128 ----------------
__global__ void chunkdecay_kernel()
{
    __shared__ float sf[4], ss[4];
    int bhn = blockIdx.x;
    int t = threadIdx.x;
    int base = (bhn / NCH) * Lq + (bhn % NCH) * CH;
    float f = g_fdm[base + t];
    float s = g_sdm[base + t];
#pragma unroll
    for (int off = 16; off; off >>= 1) {
        f += __shfl_xor_sync(0xffffffffu, f, off);
        s += __shfl_xor_sync(0xffffffffu, s, off);
    }
    int lane = t & 31, wid = t >> 5;
    if (lane == 0) { sf[wid] = f; ss[wid] = s; }
    __syncthreads();
    if (t == 0) {
        float mf = (sf[0] + sf[1] + sf[2] + sf[3]) * (1.f / 128.f);
        float ms = (ss[0] + ss[1] + ss[2] + ss[3]) * (1.f / 128.f);
        float gf = mf, gs = ms;
#pragma unroll
        for (int i = 0; i < 7; i++) { gf *= gf; gs *= gs; }
        g_gf[bhn] = gf;
        g_gs[bhn] = gs;
    }
}

// ---------------- K4: per-chunk outer products (fast + slow fused) ----------
__global__ __launch_bounds__(256) void outer_kernel()
{
    __shared__ float Ks[64 * 64];
    __shared__ float Vs[64 * 64];
    __shared__ float S2[64];
    const int bhn = blockIdx.x;
    const int bh = bhn / NCH, n = bhn % NCH;
    const int t = threadIdx.x;
    const int d0 = (t & 15) * 4;
    const int e0 = (t >> 4) * 4;

    float af[4][4], as_[4][4];
#pragma unroll
    for (int i = 0; i < 4; i++)
#pragma unroll
        for (int j = 0; j < 4; j++) { af[i][j] = 0.f; as_[i][j] = 0.f; }

    for (int half_ = 0; half_ < 2; half_++) {
        size_t base = ((size_t)bh * Lq + n * CH + half_ * 64) * HDq;
        for (int i = t; i < 1024; i += 256) {
            ((float4*)Ks)[i] = ((const float4*)(g_k + base))[i];
            ((float4*)Vs)[i] = ((const float4*)(g_v + base))[i];
        }
        if (t < 64) {
            float su = g_sur[bh * Lq + n * CH + half_ * 64 + t];
            S2[t] = su * su;
        }
        __syncthreads();
#pragma unroll 4
        for (int l = 0; l < 64; l++) {
            float4 vv = *(float4*)&Vs[l * 64 + d0];
            float4 kk = *(float4*)&Ks[l * 64 + e0];
            float s2 = S2[l];
            float v[4] = {vv.x, vv.y, vv.z, vv.w};
            float k[4] = {kk.x, kk.y, kk.z, kk.w};
            float vs[4] = {v[0] * s2, v[1] * s2, v[2] * s2, v[3] * s2};
#pragma unroll
            for (int i = 0; i < 4; i++)
#pragma unroll
                for (int j = 0; j < 4; j++) {
                    af[i][j] += v[i] * k[j];
                    as_[i][j] += vs[i] * k[j];
                }
        }
        __syncthreads();
    }

    size_t abase = (size_t)bhn * 4096;
#pragma unroll
    for (int i = 0; i < 4; i++) {
        *(float4*)&g_Af[abase + (d0 + i) * 64 + e0] =
            make_float4(af[i][0], af[i][1], af[i][2], af[i][3]);
        *(float4*)&g_As[abase + (d0 + i) * 64 + e0] =
            make_float4(as_[i][0], as_[i][1], as_[i][2], as_[i][3]);
    }
}

// ---------------- K5: decayed prefix scan over chunks (in-place) ------------
__global__ void scan_kernel()
{
    int bh = blockIdx.x >> 4;
    int eb = blockIdx.x & 15;
    int entry = eb * 256 + threadIdx.x;
    float sfv = 0.f, ssv = 0.f;
#pragma unroll 1
    for (int n = 0; n < NCH; n++) {
        int bhn = bh * NCH + n;
        float gf = g_gf[bhn], gs = g_gs[bhn];
        size_t idx = (size_t)bhn * 4096 + entry;
        sfv = sfv * gf + g_Af[idx]; g_Af[idx] = sfv;
        ssv = ssv * gs + g_As[idx]; g_As[idx] = ssv;
    }
}

// ---------------- K6: O = Q @ S (fast+slow), gate/alpha mix -> omix (half) --
__global__ __launch_bounds__(256) void outmix_kernel()
{
    __shared__ float Sf[4096];
    __shared__ float Ss[4096];
    __shared__ float Qs[32 * 64];
    __shared__ float gA[32], gB[32];
    const int bhn = blockIdx.x;
    const int bh = bhn / NCH, n = bhn % NCH;
    const int b = bh >> 4, h = bh & 15;
    const int t = threadIdx.x;

    size_t abase = (size_t)bhn * 4096;
    for (int i = t; i < 1024; i += 256) {
        ((float4*)Sf)[i] = ((const float4*)(g_Af + abase))[i];
        ((float4*)Ss)[i] = ((const float4*)(g_As + abase))[i];
    }

    const int d = t & 63;
    const int lb = (t >> 6) * 8;

    for (int pass = 0; pass < 4; pass++) {
        int l0 = pass * 32;
        size_t qbase = ((size_t)bh * Lq + n * CH + l0) * HDq;
        for (int i = t; i < 512; i += 256)
            ((float4*)Qs)[i] = ((const float4*)(g_q + qbase))[i];
        if (t < 32) {
            int p = bh * Lq + n * CH + l0 + t;
            float psi = g_psi[p];
            float alpha = 0.5f + 0.3f * psi;
            gA[t] = alpha * g_fg[p];
            gB[t] = (1.f - alpha) * g_sg[p];
        }
        __syncthreads();

        float accf[8], accs[8];
#pragma unroll
        for (int l = 0; l < 8; l++) { accf[l] = 0.f; accs[l] = 0.f; }
#pragma unroll 8
        for (int e = 0; e < 64; e += 2) {
            float sf0 = Sf[e * 64 + d];
            float sf1 = Sf[(e + 1) * 64 + d];
            float ss0 = Ss[e * 64 + d];
            float ss1 = Ss[(e + 1) * 64 + d];
#pragma unroll
            for (int l = 0; l < 8; l++) {
                float2 q2 = *(float2*)&Qs[(lb + l) * 64 + e];
                accf[l] += q2.x * sf0 + q2.y * sf1;
                accs[l] += q2.x * ss0 + q2.y * ss1;
            }
        }
#pragma unroll
        for (int l = 0; l < 8; l++) {
            int ll = lb + l;
            float val = gA[ll] * accf[l] + gB[ll] * accs[l];
            int lglob = n * CH + l0 + ll;
            g_omixh[((size_t)b * Lq + lglob) * Dq + h * HDq + d] = __float2half_rn(val);
        }
        __syncthreads();
    }
}

// ---------------- launch ----------------
extern "C" void kernel_launch(void* const* d_in, const int* in_sizes, int n_in,
                              void* d_out, int out_size)
{
    const float* x   = (const float*)d_in[0];
    const float* Wq  = (const float*)d_in[1];
    const float* Wk  = (const float*)d_in[2];
    const float* Wv  = (const float*)d_in[3];
    const float* Wb  = (const float*)d_in[4];
    const float* Wfd = (const float*)d_in[5];
    const float* fdb = (const float*)d_in[6];
    const float* Wsd = (const float*)d_in[7];
    const float* sdb = (const float*)d_in[8];
    const float* Wfg = (const float*)d_in[9];
    const float* Wsg = (const float*)d_in[10];
    const float* Wo  = (const float*)d_in[11];
    float* out = (float*)d_out;

    void *p_q = nullptr, *p_k = nullptr, *p_v = nullptr;
    void *p_xh = nullptr, *p_wh = nullptr, *p_gwh = nullptr, *p_oh = nullptr;
    cudaGetSymbolAddress(&p_q, g_q);
    cudaGetSymbolAddress(&p_k, g_k);
    cudaGetSymbolAddress(&p_v, g_v);
    cudaGetSymbolAddress(&p_xh, g_xh);
    cudaGetSymbolAddress(&p_wh, g_wh);
    cudaGetSymbolAddress(&p_gwh, g_gwh);
    cudaGetSymbolAddress(&p_oh, g_omixh);

    cudaFuncSetAttribute(gemm_f16_kernel,
                         cudaFuncAttributeMaxDynamicSharedMemorySize, HSMEM);

    // K0: conversions & packing
    xhalf_kernel<<<4096, 256>>>(x);
    wtrans_kernel<<<dim3(32, 32, 4), dim3(32, 8)>>>(Wq, Wk, Wv, Wo);
    gwpack_kernel<<<512, 256>>>(Wb, Wfd, Wsd, Wfg, Wsg);

    // K2: gate projections via fp16 GEMM (mode 3: sigmoid scatter)
    gemm_f16_kernel<<<dim3(1, 64, 1), 256, HSMEM>>>(
        (const __half*)p_xh, (const __half*)p_gwh,
        nullptr, nullptr, nullptr, fdb, sdb, 3);

    // K1: fused q,k,v projections (silu + head layout; k,v also *beta)
    gemm_f16_kernel<<<dim3(8, 64, 3), 256, HSMEM>>>(
        (const __half*)p_xh, (const __half*)p_wh,
        (float*)p_q, (float*)p_k, (float*)p_v, fdb, sdb, 1);

    // K3: psi/surprise/decay-mod (read-only k,v)
    prep_kernel<<<(BHL * 32) / 256, 256>>>();

    // K3b: per-chunk decay factors
    chunkdecay_kernel<<<Bq * Hq * NCH, 128>>>();

    // K4: per-chunk outer products (fast + slow)
    outer_kernel<<<Bq * Hq * NCH, 256>>>();

    // K5: decayed scan across chunks
    scan_kernel<<<Bq * Hq * 16, 256>>>();

    // K6: per-chunk output + gate mixing (writes half omix)
    outmix_kernel<<<Bq * Hq * NCH, 256>>>();

    // K7: output projection (mode 0)
    gemm_f16_kernel<<<dim3(8, 64, 1), 256, HSMEM>>>(
        (const __half*)p_oh, (const __half*)p_wh + (size_t)3 * Dq * Dq,
        out, out, out, fdb, sdb, 0);
}

// round 9
// speedup vs baseline: 4.4920x; 1.0765x over previous
#include <cuda_runtime.h>
#include <cuda_fp16.h>
#include <math.h>
#include <stdint.h>

#define Bq 2
#define Lq 4096
#define Dq 1024
#define Hq 16
#define HDq 64
#define NCH 32
#define CH 128
#define BHL (Bq*Hq*Lq)

// ---- fp16 cp.async GEMM geometry ----
#define HSTG 4
#define HBK 32
#define HASTR 40
#define HSTAGE (128*HASTR)
#define HSMEM (HSTG*2*HSTAGE*2)

// ---------------- device scratch (no allocations allowed) ----------------
__device__ __half g_xh[Bq*Lq*Dq];         // half x [8192][1024]
__device__ __half g_wh[4*Dq*Dq];          // W^T [n][k] for Wq,Wk,Wv,Wo
__device__ __half g_gwh[128*Dq];          // packed gate weights^T
__device__ __half g_omixh[Bq*Lq*Dq];
__device__ float g_q[Bq*Hq*Lq*HDq];
__device__ float g_k[Bq*Hq*Lq*HDq];       // silu only (no beta)
__device__ float g_v[Bq*Hq*Lq*HDq];       // silu only (no beta)
__device__ float g_beta[BHL];
__device__ float g_fd[BHL];
__device__ float g_sd[BHL];
__device__ float g_fg[BHL];
__device__ float g_sg[BHL];
__device__ float g_psi[BHL];
__device__ float g_gf[Bq*Hq*NCH];
__device__ float g_gs[Bq*Hq*NCH];
__device__ float g_Af[Bq*Hq*NCH*HDq*HDq];
__device__ float g_As[Bq*Hq*NCH*HDq*HDq];

__device__ __forceinline__ float sigm(float x) { return 1.f / (1.f + expf(-x)); }

__device__ __forceinline__ void cp16h(__half* dst, const __half* src) {
    uint32_t d = (uint32_t)__cvta_generic_to_shared(dst);
    asm volatile("cp.async.ca.shared.global [%0], [%1], 16;" :: "r"(d), "l"(src));
}

// fp16 k16 mma, f32 accum
__device__ __forceinline__ void mma_f16(
    float& c0, float& c1, float& c2, float& c3,
    uint32_t a0, uint32_t a1, uint32_t a2, uint32_t a3,
    uint32_t b0, uint32_t b1)
{
    asm volatile(
        "mma.sync.aligned.m16n8k16.row.col.f32.f16.f16.f32 "
        "{%0,%1,%2,%3}, {%4,%5,%6,%7}, {%8,%9}, {%0,%1,%2,%3};"
        : "+f"(c0), "+f"(c1), "+f"(c2), "+f"(c3)
        : "r"(a0), "r"(a1), "r"(a2), "r"(a3), "r"(b0), "r"(b1));
}

// ---------------- K0a: x -> half ----------------
__global__ __launch_bounds__(256) void xhalf_kernel(const float* __restrict__ x)
{
    size_t i = (size_t)blockIdx.x * 256 + threadIdx.x;
    const float4* s = (const float4*)x;
    float4 v0 = s[i * 2], v1 = s[i * 2 + 1];
    __half2 h0 = __floats2half2_rn(v0.x, v0.y);
    __half2 h1 = __floats2half2_rn(v0.z, v0.w);
    __half2 h2 = __floats2half2_rn(v1.x, v1.y);
    __half2 h3 = __floats2half2_rn(v1.z, v1.w);
    uint4 o;
    o.x = *(uint32_t*)&h0; o.y = *(uint32_t*)&h1;
    o.z = *(uint32_t*)&h2; o.w = *(uint32_t*)&h3;
    ((uint4*)g_xh)[i] = o;
}

// ---------------- K0b: W -> half, transposed to [n][k] ----------------
__global__ void wtrans_kernel(
    const float* __restrict__ Wq, const float* __restrict__ Wk,
    const float* __restrict__ Wv, const float* __restrict__ Wo)
{
    __shared__ __half tile[32][33];
    const int z = blockIdx.z;
    const float* W = (z == 0) ? Wq : (z == 1) ? Wk : (z == 2) ? Wv : Wo;
    __half* WT = g_wh + (size_t)z * Dq * Dq;
    const int x0 = blockIdx.x * 32;
    const int y0 = blockIdx.y * 32;
    const int tx = threadIdx.x, ty = threadIdx.y;
#pragma unroll
    for (int i = 0; i < 4; i++)
        tile[ty + 8 * i][tx] = __float2half_rn(W[(size_t)(y0 + ty + 8 * i) * 1024 + x0 + tx]);
    __syncthreads();
#pragma unroll
    for (int i = 0; i < 4; i++)
        WT[(size_t)(x0 + ty + 8 * i) * 1024 + y0 + tx] = tile[tx][ty + 8 * i];
}

// ---------------- K0c: pack 5 gate weights -> [128 n][1024 k] half ---------
__global__ __launch_bounds__(256) void gwpack_kernel(
    const float* __restrict__ Wbm, const float* __restrict__ Wfd,
    const float* __restrict__ Wsd, const float* __restrict__ Wfg,
    const float* __restrict__ Wsg)
{
    int idx = blockIdx.x * 256 + threadIdx.x;
    int n = idx >> 10, k = idx & 1023;
    __half val = __float2half_rn(0.f);
    if (n < 80) {
        int which = n >> 4, h = n & 15;
        const float* Wp = (which == 0) ? Wbm : (which == 1) ? Wfd
                         : (which == 2) ? Wsd : (which == 3) ? Wfg : Wsg;
        val = __float2half_rn(Wp[k * 16 + h]);
    }
    g_gwh[n * 1024 + k] = val;
}

// ---------------- K1(+K2)/K7: fp16 cp.async GEMM, 128x128 tile --------------
// phase 0: 1D grid 1600 — blocks [0,1536) QKV (z=bid>>9, silu+head layout),
//          blocks [1536,1600) gate projection (sigmoid scatter, WTg).
// phase 1: 1D grid 512 — K7 plain fp32 output to C0 with WTq slice.
__global__ __launch_bounds__(256, 2) void gemm_f16_kernel(
    const __half* __restrict__ A, const __half* __restrict__ WTq,
    const __half* __restrict__ WTg,
    float* __restrict__ C0, float* __restrict__ C1, float* __restrict__ C2,
    const float* __restrict__ fdb, const float* __restrict__ sdb,
    int phase)
{
    extern __shared__ __half smh[];
    __half* As = smh;
    __half* Bs = smh + HSTG * HSTAGE;

    const int bid = blockIdx.x;
    int mode, bm, bn, z = 0;
    const __half* WT;
    float* C = C0;
    if (phase == 0) {
        if (bid < 1536) {
            z = bid >> 9;
            int idx = bid & 511;
            bn = (idx & 7) * 128;
            bm = (idx >> 3) * 128;
            mode = 1;
            WT = WTq + (size_t)z * Dq * Dq;
            C = (z == 0) ? C0 : (z == 1) ? C1 : C2;
        } else {
            bm = (bid - 1536) * 128;
            bn = 0;
            mode = 3;
            WT = WTg;
        }
    } else {
        bn = (bid & 7) * 128;
        bm = (bid >> 3) * 128;
        mode = 0;
        WT = WTq;
    }

    const int tid = threadIdx.x;
    const int lane = tid & 31;
    const int wid = tid >> 5;
    const int gid = lane >> 2;
    const int tig = lane & 3;
    const int warpM = (wid & 1) * 64;
    const int warpN = (wid >> 1) * 32;

    const int l_r = tid >> 2;
    const int l_c = (tid & 3) * 8;

    float acc[4][4][4];
#pragma unroll
    for (int mt = 0; mt < 4; mt++)
#pragma unroll
        for (int nt = 0; nt < 4; nt++)
#pragma unroll
            for (int c = 0; c < 4; c++) acc[mt][nt][c] = 0.f;

    const __half* Ab0 = A + (size_t)(bm + l_r) * 1024 + l_c;
    const __half* Ab1 = A + (size_t)(bm + l_r + 64) * 1024 + l_c;
    const __half* Bb0 = WT + (size_t)(bn + l_r) * 1024 + l_c;
    const __half* Bb1 = WT + (size_t)(bn + l_r + 64) * 1024 + l_c;
    __half* AsD0 = As + l_r * HASTR + l_c;
    __half* AsD1 = As + (l_r + 64) * HASTR + l_c;
    __half* BsD0 = Bs + l_r * HASTR + l_c;
    __half* BsD1 = Bs + (l_r + 64) * HASTR + l_c;

#pragma unroll
    for (int s = 0; s < HSTG - 1; s++) {
        int k0 = s * HBK;
        cp16h(AsD0 + s * HSTAGE, Ab0 + k0);
        cp16h(AsD1 + s * HSTAGE, Ab1 + k0);
        cp16h(BsD0 + s * HSTAGE, Bb0 + k0);
        cp16h(BsD1 + s * HSTAGE, Bb1 + k0);
        asm volatile("cp.async.commit_group;");
    }

#pragma unroll 1
    for (int t = 0; t < 32; t++) {
        asm volatile("cp.async.wait_group 2;");
        __syncthreads();

        if (t + 3 < 32) {
            int s = (t + 3) & 3;
            int k0 = (t + 3) * HBK;
            cp16h(AsD0 + s * HSTAGE, Ab0 + k0);
            cp16h(AsD1 + s * HSTAGE, Ab1 + k0);
            cp16h(BsD0 + s * HSTAGE, Bb0 + k0);
            cp16h(BsD1 + s * HSTAGE, Bb1 + k0);
        }
        asm volatile("cp.async.commit_group;");

        const __half* Asc = As + (t & 3) * HSTAGE;
        const __half* Bsc = Bs + (t & 3) * HSTAGE;
#pragma unroll
        for (int ks = 0; ks < 2; ks++) {
            const int kb = ks * 16;
            uint32_t af[4][4];
#pragma unroll
            for (int mt = 0; mt < 4; mt++) {
                int m = warpM + mt * 16 + gid;
                af[mt][0] = *(const uint32_t*)&Asc[m * HASTR + kb + 2 * tig];
                af[mt][1] = *(const uint32_t*)&Asc[(m + 8) * HASTR + kb + 2 * tig];
                af[mt][2] = *(const uint32_t*)&Asc[m * HASTR + kb + 2 * tig + 8];
                af[mt][3] = *(const uint32_t*)&Asc[(m + 8) * HASTR + kb + 2 * tig + 8];
            }
#pragma unroll
            for (int nt = 0; nt < 4; nt++) {
                int n = warpN + nt * 8 + gid;
                uint32_t b0 = *(const uint32_t*)&Bsc[n * HASTR + kb + 2 * tig];
                uint32_t b1 = *(const uint32_t*)&Bsc[n * HASTR + kb + 2 * tig + 8];
#pragma unroll
                for (int mt = 0; mt < 4; mt++) {
                    mma_f16(acc[mt][nt][0], acc[mt][nt][1], acc[mt][nt][2], acc[mt][nt][3],
                            af[mt][0], af[mt][1], af[mt][2], af[mt][3], b0, b1);
                }
            }
        }
    }

    // epilogue
#pragma unroll
    for (int mt = 0; mt < 4; mt++) {
#pragma unroll
        for (int nt = 0; nt < 4; nt++) {
            int row = bm + warpM + mt * 16 + gid;
            int col = bn + warpN + nt * 8 + tig * 2;
#pragma unroll
            for (int half_ = 0; half_ < 2; half_++) {
                int r = row + half_ * 8;
                float v0 = acc[mt][nt][half_ * 2 + 0];
                float v1 = acc[mt][nt][half_ * 2 + 1];
                int bb = r >> 12, l = r & 4095;
                if (mode == 1) {
                    v0 = v0 * (1.f / (1.f + expf(-v0)));
                    v1 = v1 * (1.f / (1.f + expf(-v1)));
                    int h = col >> 6, hd = col & 63;
                    *(float2*)(C + (((size_t)(bb * Hq + h) * Lq + l) * HDq) + hd) =
                        make_float2(v0, v1);
                } else if (mode == 3) {
#pragma unroll
                    for (int cc = 0; cc < 2; cc++) {
                        int cl = col + cc;
                        if (cl < 80) {
                            int which = cl >> 4, h = cl & 15;
                            float s = (cc == 0) ? v0 : v1;
                            if (which == 1) s += fdb[h];
                            if (which == 2) s += sdb[h];
                            float val = sigm(s);
                            float* dst = (which == 0) ? g_beta : (which == 1) ? g_fd
                                        : (which == 2) ? g_sd : (which == 3) ? g_fg : g_sg;
                            dst[(bb * Hq + h) * Lq + l] = val;
                        }
                    }
                } else {
                    *(float2*)(C + (size_t)r * 1024 + col) = make_float2(v0, v1);
                }
            }
        }
    }
}

// ---------------- K4: outer products + psi/surprise + chunk decay (fused) ---
__global__ __launch_bounds__(256) void outer_kernel()
{
    __shared__ float Ks[64 * 64];
    __shared__ float Vs[64 * 64];
    __shared__ float S2[64];
    __shared__ float fdm_s[128];
    __shared__ float sdm_s[128];
    const int bhn = blockIdx.x;
    const int bh = bhn / NCH, n = bhn % NCH;
    const int t = threadIdx.x;
    const int d0 = (t & 15) * 4;
    const int e0 = (t >> 4) * 4;
    const int posbase = bh * Lq + n * CH;

    float af[4][4], as_[4][4];
#pragma unroll
    for (int i = 0; i < 4; i++)
#pragma unroll
        for (int j = 0; j < 4; j++) { af[i][j] = 0.f; as_[i][j] = 0.f; }

    for (int half_ = 0; half_ < 2; half_++) {
        size_t base = ((size_t)(posbase + half_ * 64)) * HDq;
        // fill smem with beta-scaled k,v
        for (int i = t; i < 1024; i += 256) {
            int row = i >> 4;
            float b = g_beta[posbase + half_ * 64 + row];
            float4 k4 = ((const float4*)(g_k + base))[i];
            float4 v4 = ((const float4*)(g_v + base))[i];
            k4.x *= b; k4.y *= b; k4.z *= b; k4.w *= b;
            v4.x *= b; v4.y *= b; v4.z *= b; v4.w *= b;
            ((float4*)Ks)[i] = k4;
            ((float4*)Vs)[i] = v4;
        }
        __syncthreads();

        // per-row psi/surprise: 4 threads per row
        {
            int r = t >> 2, q = t & 3;
            const float4* krow = (const float4*)&Ks[r * 64 + q * 16];
            const float4* vrow = (const float4*)&Vs[r * 64 + q * 16];
            float kk = 0.f, vv = 0.f, kv = 0.f;
#pragma unroll
            for (int j = 0; j < 4; j++) {
                float4 a = krow[j], b = vrow[j];
                kk += a.x * a.x + a.y * a.y + a.z * a.z + a.w * a.w;
                vv += b.x * b.x + b.y * b.y + b.z * b.z + b.w * b.w;
                kv += a.x * b.x + a.y * b.y + a.z * b.z + a.w * b.w;
            }
            kk += __shfl_xor_sync(0xffffffffu, kk, 1);
            kk += __shfl_xor_sync(0xffffffffu, kk, 2);
            vv += __shfl_xor_sync(0xffffffffu, vv, 1);
            vv += __shfl_xor_sync(0xffffffffu, vv, 2);
            kv += __shfl_xor_sync(0xffffffffu, kv, 1);
            kv += __shfl_xor_sync(0xffffffffu, kv, 2);
            if (q == 0) {
                float kn = sqrtf(kk) + 1e-8f;
                float vn = sqrtf(vv) + 1e-8f;
                float praw = fabsf(kv) / (kn * vn);
                float psi = sigm(3.f * praw);
                float sur = sigm((psi - 0.5f) * 10.f);
                S2[r] = sur * sur;
                int p = posbase + half_ * 64 + r;
                g_psi[p] = psi;
                fdm_s[half_ * 64 + r] = g_fd[p] * (1.f - 0.1f * psi);
                sdm_s[half_ * 64 + r] = g_sd[p] * (1.f - 0.05f * psi);
            }
        }
        __syncthreads();

#pragma unroll 4
        for (int l = 0; l < 64; l++) {
            float4 vv4 = *(float4*)&Vs[l * 64 + d0];
            float4 kk4 = *(float4*)&Ks[l * 64 + e0];
            float s2 = S2[l];
            float v[4] = {vv4.x, vv4.y, vv4.z, vv4.w};
            float k[4] = {kk4.x, kk4.y, kk4.z, kk4.w};
            float vs[4] = {v[0] * s2, v[1] * s2, v[2] * s2, v[3] * s2};
#pragma unroll
            for (int i = 0; i < 4; i++)
#pragma unroll
                for (int j = 0; j < 4; j++) {
                    af[i][j] += v[i] * k[j];
                    as_[i][j] += vs[i] * k[j];
                }
        }
        __syncthreads();
    }

    // chunk decay means -> mean^128 (warp 0)
    if (t < 32) {
        float f = 0.f, s = 0.f;
#pragma unroll
        for (int j = t; j < 128; j += 32) { f += fdm_s[j]; s += sdm_s[j]; }
#pragma unroll
        for (int off = 16; off; off >>= 1) {
            f += __shfl_xor_sync(0xffffffffu, f, off);
            s += __shfl_xor_sync(0xffffffffu, s, off);
        }
        if (t == 0) {
            float gf = f * (1.f / 128.f), gs = s * (1.f / 128.f);
#pragma unroll
            for (int i = 0; i < 7; i++) { gf *= gf; gs *= gs; }
            g_gf[bhn] = gf;
            g_gs[bhn] = gs;
        }
    }

    size_t abase = (size_t)bhn * 4096;
#pragma unroll
    for (int i = 0; i < 4; i++) {
        *(float4*)&g_Af[abase + (d0 + i) * 64 + e0] =
            make_float4(af[i][0], af[i][1], af[i][2], af[i][3]);
        *(float4*)&g_As[abase + (d0 + i) * 64 + e0] =
            make_float4(as_[i][0], as_[i][1], as_[i][2], as_[i][3]);
    }
}

// ---------------- K5: decayed prefix scan over chunks (in-place) ------------
__global__ void scan_kernel()
{
    int bh = blockIdx.x >> 4;
    int eb = blockIdx.x & 15;
    int entry = eb * 256 + threadIdx.x;
    float sfv = 0.f, ssv = 0.f;
#pragma unroll 1
    for (int n = 0; n < NCH; n++) {
        int bhn = bh * NCH + n;
        float gf = g_gf[bhn], gs = g_gs[bhn];
        size_t idx = (size_t)bhn * 4096 + entry;
        sfv = sfv * gf + g_Af[idx]; g_Af[idx] = sfv;
        ssv = ssv * gs + g_As[idx]; g_As[idx] = ssv;
    }
}

// ---------------- K6: O = Q @ S (fast+slow), gate/alpha mix -> omix (half) --
__global__ __launch_bounds__(256) void outmix_kernel()
{
    __shared__ float Sf[4096];
    __shared__ float Ss[4096];
    __shared__ float Qs[32 * 64];
    __shared__ float gA[32], gB[32];
    const int bhn = blockIdx.x;
    const int bh = bhn / NCH, n = bhn % NCH;
    const int b = bh >> 4, h = bh & 15;
    const int t = threadIdx.x;

    size_t abase = (size_t)bhn * 4096;
    for (int i = t; i < 1024; i += 256) {
        ((float4*)Sf)[i] = ((const float4*)(g_Af + abase))[i];
        ((float4*)Ss)[i] = ((const float4*)(g_As + abase))[i];
    }

    const int d = t & 63;
    const int lb = (t >> 6) * 8;

    for (int pass = 0; pass < 4; pass++) {
        int l0 = pass * 32;
        size_t qbase = ((size_t)bh * Lq + n * CH + l0) * HDq;
        for (int i = t; i < 512; i += 256)
            ((float4*)Qs)[i] = ((const float4*)(g_q + qbase))[i];
        if (t < 32) {
            int p = bh * Lq + n * CH + l0 + t;
            float psi = g_psi[p];
            float alpha = 0.5f + 0.3f * psi;
            gA[t] = alpha * g_fg[p];
            gB[t] = (1.f - alpha) * g_sg[p];
        }
        __syncthreads();

        float accf[8], accs[8];
#pragma unroll
        for (int l = 0; l < 8; l++) { accf[l] = 0.f; accs[l] = 0.f; }
#pragma unroll 8
        for (int e = 0; e < 64; e += 2) {
            float sf0 = Sf[e * 64 + d];
            float sf1 = Sf[(e + 1) * 64 + d];
            float ss0 = Ss[e * 64 + d];
            float ss1 = Ss[(e + 1) * 64 + d];
#pragma unroll
            for (int l = 0; l < 8; l++) {
                float2 q2 = *(float2*)&Qs[(lb + l) * 64 + e];
                accf[l] += q2.x * sf0 + q2.y * sf1;
                accs[l] += q2.x * ss0 + q2.y * ss1;
            }
        }
#pragma unroll
        for (int l = 0; l < 8; l++) {
            int ll = lb + l;
            float val = gA[ll] * accf[l] + gB[ll] * accs[l];
            int lglob = n * CH + l0 + ll;
            g_omixh[((size_t)b * Lq + lglob) * Dq + h * HDq + d] = __float2half_rn(val);
        }
        __syncthreads();
    }
}

// ---------------- launch ----------------
extern "C" void kernel_launch(void* const* d_in, const int* in_sizes, int n_in,
                              void* d_out, int out_size)
{
    const float* x   = (const float*)d_in[0];
    const float* Wq  = (const float*)d_in[1];
    const float* Wk  = (const float*)d_in[2];
    const float* Wv  = (const float*)d_in[3];
    const float* Wb  = (const float*)d_in[4];
    const float* Wfd = (const float*)d_in[5];
    const float* fdb = (const float*)d_in[6];
    const float* Wsd = (const float*)d_in[7];
    const float* sdb = (const float*)d_in[8];
    const float* Wfg = (const float*)d_in[9];
    const float* Wsg = (const float*)d_in[10];
    const float* Wo  = (const float*)d_in[11];
    float* out = (float*)d_out;

    void *p_q = nullptr, *p_k = nullptr, *p_v = nullptr;
    void *p_xh = nullptr, *p_wh = nullptr, *p_gwh = nullptr, *p_oh = nullptr;
    cudaGetSymbolAddress(&p_q, g_q);
    cudaGetSymbolAddress(&p_k, g_k);
    cudaGetSymbolAddress(&p_v, g_v);
    cudaGetSymbolAddress(&p_xh, g_xh);
    cudaGetSymbolAddress(&p_wh, g_wh);
    cudaGetSymbolAddress(&p_gwh, g_gwh);
    cudaGetSymbolAddress(&p_oh, g_omixh);

    cudaFuncSetAttribute(gemm_f16_kernel,
                         cudaFuncAttributeMaxDynamicSharedMemorySize, HSMEM);

    // K0: conversions & packing
    xhalf_kernel<<<4096, 256>>>(x);
    wtrans_kernel<<<dim3(32, 32, 4), dim3(32, 8)>>>(Wq, Wk, Wv, Wo);
    gwpack_kernel<<<512, 256>>>(Wb, Wfd, Wsd, Wfg, Wsg);

    // K1+K2: fused QKV + gate projections (1600 blocks)
    gemm_f16_kernel<<<1600, 256, HSMEM>>>(
        (const __half*)p_xh, (const __half*)p_wh, (const __half*)p_gwh,
        (float*)p_q, (float*)p_k, (float*)p_v, fdb, sdb, 0);

    // K4: fused outer products + psi/surprise + chunk decay
    outer_kernel<<<Bq * Hq * NCH, 256>>>();

    // K5: decayed scan across chunks
    scan_kernel<<<Bq * Hq * 16, 256>>>();

    // K6: per-chunk output + gate mixing (half omix)
    outmix_kernel<<<Bq * Hq * NCH, 256>>>();

    // K7: output projection (512 blocks, plain epilogue)
    gemm_f16_kernel<<<512, 256, HSMEM>>>(
        (const __half*)p_oh, (const __half*)p_wh + (size_t)3 * Dq * Dq,
        (const __half*)p_gwh, out, out, out, fdb, sdb, 1);
}

// round 10
// speedup vs baseline: 4.9777x; 1.1081x over previous
#include <cuda_runtime.h>
#include <cuda_fp16.h>
#include <math.h>
#include <stdint.h>

#define Bq 2
#define Lq 4096
#define Dq 1024
#define Hq 16
#define HDq 64
#define NCH 32
#define CH 128
#define BHL (Bq*Hq*Lq)

// ---- fp16 cp.async GEMM geometry ----
#define HSTG 4
#define HBK 32
#define HASTR 40
#define HSTAGE (128*HASTR)
#define HSMEM (HSTG*2*HSTAGE*2)

// ---------------- device scratch (no allocations allowed) ----------------
__device__ __half g_xh[Bq*Lq*Dq];         // half x [8192][1024]
__device__ __half g_wh[4*Dq*Dq];          // W^T [n][k] for Wq,Wk,Wv,Wo
__device__ __half g_gwh[128*Dq];          // packed gate weights^T
__device__ __half g_omixh[Bq*Lq*Dq];
__device__ float g_q[Bq*Hq*Lq*HDq];
__device__ float g_k[Bq*Hq*Lq*HDq];       // silu only (no beta)
__device__ float g_v[Bq*Hq*Lq*HDq];       // silu only (no beta)
__device__ float g_beta[BHL];
__device__ float g_fd[BHL];
__device__ float g_sd[BHL];
__device__ float g_fg[BHL];
__device__ float g_sg[BHL];
__device__ float g_psi[BHL];
__device__ float g_gf[Bq*Hq*NCH];
__device__ float g_gs[Bq*Hq*NCH];
__device__ float g_Af[Bq*Hq*NCH*HDq*HDq];
__device__ float g_As[Bq*Hq*NCH*HDq*HDq];

__device__ __forceinline__ float sigm(float x) { return 1.f / (1.f + expf(-x)); }

__device__ __forceinline__ uint32_t smem_u32(const void* p) {
    return (uint32_t)__cvta_generic_to_shared(p);
}

__device__ __forceinline__ void cp16h(__half* dst, const __half* src) {
    uint32_t d = (uint32_t)__cvta_generic_to_shared(dst);
    asm volatile("cp.async.ca.shared.global [%0], [%1], 16;" :: "r"(d), "l"(src));
}

__device__ __forceinline__ void ldsm_x4(
    uint32_t& r0, uint32_t& r1, uint32_t& r2, uint32_t& r3, uint32_t addr)
{
    asm volatile("ldmatrix.sync.aligned.m8n8.x4.shared.b16 {%0,%1,%2,%3}, [%4];"
        : "=r"(r0), "=r"(r1), "=r"(r2), "=r"(r3) : "r"(addr));
}

// fp16 k16 mma, f32 accum
__device__ __forceinline__ void mma_f16(
    float& c0, float& c1, float& c2, float& c3,
    uint32_t a0, uint32_t a1, uint32_t a2, uint32_t a3,
    uint32_t b0, uint32_t b1)
{
    asm volatile(
        "mma.sync.aligned.m16n8k16.row.col.f32.f16.f16.f32 "
        "{%0,%1,%2,%3}, {%4,%5,%6,%7}, {%8,%9}, {%0,%1,%2,%3};"
        : "+f"(c0), "+f"(c1), "+f"(c2), "+f"(c3)
        : "r"(a0), "r"(a1), "r"(a2), "r"(a3), "r"(b0), "r"(b1));
}

// ---------------- K0a: x -> half ----------------
__global__ __launch_bounds__(256) void xhalf_kernel(const float* __restrict__ x)
{
    size_t i = (size_t)blockIdx.x * 256 + threadIdx.x;
    const float4* s = (const float4*)x;
    float4 v0 = s[i * 2], v1 = s[i * 2 + 1];
    __half2 h0 = __floats2half2_rn(v0.x, v0.y);
    __half2 h1 = __floats2half2_rn(v0.z, v0.w);
    __half2 h2 = __floats2half2_rn(v1.x, v1.y);
    __half2 h3 = __floats2half2_rn(v1.z, v1.w);
    uint4 o;
    o.x = *(uint32_t*)&h0; o.y = *(uint32_t*)&h1;
    o.z = *(uint32_t*)&h2; o.w = *(uint32_t*)&h3;
    ((uint4*)g_xh)[i] = o;
}

// ---------------- K0b: W -> half, transposed to [n][k] ----------------
__global__ void wtrans_kernel(
    const float* __restrict__ Wq, const float* __restrict__ Wk,
    const float* __restrict__ Wv, const float* __restrict__ Wo)
{
    __shared__ __half tile[32][33];
    const int z = blockIdx.z;
    const float* W = (z == 0) ? Wq : (z == 1) ? Wk : (z == 2) ? Wv : Wo;
    __half* WT = g_wh + (size_t)z * Dq * Dq;
    const int x0 = blockIdx.x * 32;
    const int y0 = blockIdx.y * 32;
    const int tx = threadIdx.x, ty = threadIdx.y;
#pragma unroll
    for (int i = 0; i < 4; i++)
        tile[ty + 8 * i][tx] = __float2half_rn(W[(size_t)(y0 + ty + 8 * i) * 1024 + x0 + tx]);
    __syncthreads();
#pragma unroll
    for (int i = 0; i < 4; i++)
        WT[(size_t)(x0 + ty + 8 * i) * 1024 + y0 + tx] = tile[tx][ty + 8 * i];
}

// ---------------- K0c: pack 5 gate weights -> [128 n][1024 k] half ---------
__global__ __launch_bounds__(256) void gwpack_kernel(
    const float* __restrict__ Wbm, const float* __restrict__ Wfd,
    const float* __restrict__ Wsd, const float* __restrict__ Wfg,
    const float* __restrict__ Wsg)
{
    int idx = blockIdx.x * 256 + threadIdx.x;
    int n = idx >> 10, k = idx & 1023;
    __half val = __float2half_rn(0.f);
    if (n < 80) {
        int which = n >> 4, h = n & 15;
        const float* Wp = (which == 0) ? Wbm : (which == 1) ? Wfd
                         : (which == 2) ? Wsd : (which == 3) ? Wfg : Wsg;
        val = __float2half_rn(Wp[k * 16 + h]);
    }
    g_gwh[n * 1024 + k] = val;
}

// ---------------- K1(+K2)/K7: fp16 cp.async GEMM, ldmatrix fragments --------
// phase 0: 1600 blocks — [0,1536) QKV (silu+head), [1536,1600) gates.
// phase 1: 512 blocks — K7 plain fp32 C0.
__global__ __launch_bounds__(256, 2) void gemm_f16_kernel(
    const __half* __restrict__ A, const __half* __restrict__ WTq,
    const __half* __restrict__ WTg,
    float* __restrict__ C0, float* __restrict__ C1, float* __restrict__ C2,
    const float* __restrict__ fdb, const float* __restrict__ sdb,
    int phase)
{
    extern __shared__ __half smh[];
    __half* As = smh;
    __half* Bs = smh + HSTG * HSTAGE;

    const int bid = blockIdx.x;
    int mode, bm, bn, z = 0;
    const __half* WT;
    float* C = C0;
    if (phase == 0) {
        if (bid < 1536) {
            z = bid >> 9;
            int idx = bid & 511;
            bn = (idx & 7) * 128;
            bm = (idx >> 3) * 128;
            mode = 1;
            WT = WTq + (size_t)z * Dq * Dq;
            C = (z == 0) ? C0 : (z == 1) ? C1 : C2;
        } else {
            bm = (bid - 1536) * 128;
            bn = 0;
            mode = 3;
            WT = WTg;
        }
    } else {
        bn = (bid & 7) * 128;
        bm = (bid >> 3) * 128;
        mode = 0;
        WT = WTq;
    }

    const int tid = threadIdx.x;
    const int lane = tid & 31;
    const int wid = tid >> 5;
    const int gid = lane >> 2;
    const int tig = lane & 3;
    const int warpM = (wid & 1) * 64;
    const int warpN = (wid >> 1) * 32;

    const int l_r = tid >> 2;
    const int l_c = (tid & 3) * 8;

    // ldmatrix per-lane address offsets (in halves)
    const int a_lrow = lane & 15;               // row within 16-row tile
    const int a_lcol = (lane >> 4) * 8;         // k offset 0/8
    const int b_lrow = ((lane >> 4) & 1) * 8 + (lane & 7);
    const int b_lcol = ((lane >> 3) & 1) * 8;

    float acc[4][4][4];
#pragma unroll
    for (int mt = 0; mt < 4; mt++)
#pragma unroll
        for (int nt = 0; nt < 4; nt++)
#pragma unroll
            for (int c = 0; c < 4; c++) acc[mt][nt][c] = 0.f;

    const __half* Ab0 = A + (size_t)(bm + l_r) * 1024 + l_c;
    const __half* Ab1 = A + (size_t)(bm + l_r + 64) * 1024 + l_c;
    const __half* Bb0 = WT + (size_t)(bn + l_r) * 1024 + l_c;
    const __half* Bb1 = WT + (size_t)(bn + l_r + 64) * 1024 + l_c;
    __half* AsD0 = As + l_r * HASTR + l_c;
    __half* AsD1 = As + (l_r + 64) * HASTR + l_c;
    __half* BsD0 = Bs + l_r * HASTR + l_c;
    __half* BsD1 = Bs + (l_r + 64) * HASTR + l_c;

    const uint32_t AsU = smem_u32(As);
    const uint32_t BsU = smem_u32(Bs);

#pragma unroll
    for (int s = 0; s < HSTG - 1; s++) {
        int k0 = s * HBK;
        cp16h(AsD0 + s * HSTAGE, Ab0 + k0);
        cp16h(AsD1 + s * HSTAGE, Ab1 + k0);
        cp16h(BsD0 + s * HSTAGE, Bb0 + k0);
        cp16h(BsD1 + s * HSTAGE, Bb1 + k0);
        asm volatile("cp.async.commit_group;");
    }

#pragma unroll 1
    for (int t = 0; t < 32; t++) {
        asm volatile("cp.async.wait_group 2;");
        __syncthreads();

        if (t + 3 < 32) {
            int s = (t + 3) & 3;
            int k0 = (t + 3) * HBK;
            cp16h(AsD0 + s * HSTAGE, Ab0 + k0);
            cp16h(AsD1 + s * HSTAGE, Ab1 + k0);
            cp16h(BsD0 + s * HSTAGE, Bb0 + k0);
            cp16h(BsD1 + s * HSTAGE, Bb1 + k0);
        }
        asm volatile("cp.async.commit_group;");

        const uint32_t AscU = AsU + (uint32_t)((t & 3) * HSTAGE) * 2u;
        const uint32_t BscU = BsU + (uint32_t)((t & 3) * HSTAGE) * 2u;
#pragma unroll
        for (int ks = 0; ks < 2; ks++) {
            const int kb = ks * 16;
            uint32_t af[4][4];
#pragma unroll
            for (int mt = 0; mt < 4; mt++) {
                uint32_t addr = AscU +
                    (uint32_t)((warpM + mt * 16 + a_lrow) * HASTR + kb + a_lcol) * 2u;
                ldsm_x4(af[mt][0], af[mt][1], af[mt][2], af[mt][3], addr);
            }
            uint32_t br[2][4];
#pragma unroll
            for (int np = 0; np < 2; np++) {
                uint32_t addr = BscU +
                    (uint32_t)((warpN + np * 16 + b_lrow) * HASTR + kb + b_lcol) * 2u;
                ldsm_x4(br[np][0], br[np][1], br[np][2], br[np][3], addr);
            }
#pragma unroll
            for (int nt = 0; nt < 4; nt++) {
                uint32_t b0 = br[nt >> 1][(nt & 1) * 2 + 0];
                uint32_t b1 = br[nt >> 1][(nt & 1) * 2 + 1];
#pragma unroll
                for (int mt = 0; mt < 4; mt++) {
                    mma_f16(acc[mt][nt][0], acc[mt][nt][1], acc[mt][nt][2], acc[mt][nt][3],
                            af[mt][0], af[mt][1], af[mt][2], af[mt][3], b0, b1);
                }
            }
        }
    }

    // epilogue
#pragma unroll
    for (int mt = 0; mt < 4; mt++) {
#pragma unroll
        for (int nt = 0; nt < 4; nt++) {
            int row = bm + warpM + mt * 16 + gid;
            int col = bn + warpN + nt * 8 + tig * 2;
#pragma unroll
            for (int half_ = 0; half_ < 2; half_++) {
                int r = row + half_ * 8;
                float v0 = acc[mt][nt][half_ * 2 + 0];
                float v1 = acc[mt][nt][half_ * 2 + 1];
                int bb = r >> 12, l = r & 4095;
                if (mode == 1) {
                    v0 = v0 * (1.f / (1.f + expf(-v0)));
                    v1 = v1 * (1.f / (1.f + expf(-v1)));
                    int h = col >> 6, hd = col & 63;
                    *(float2*)(C + (((size_t)(bb * Hq + h) * Lq + l) * HDq) + hd) =
                        make_float2(v0, v1);
                } else if (mode == 3) {
#pragma unroll
                    for (int cc = 0; cc < 2; cc++) {
                        int cl = col + cc;
                        if (cl < 80) {
                            int which = cl >> 4, h = cl & 15;
                            float s = (cc == 0) ? v0 : v1;
                            if (which == 1) s += fdb[h];
                            if (which == 2) s += sdb[h];
                            float val = sigm(s);
                            float* dst = (which == 0) ? g_beta : (which == 1) ? g_fd
                                        : (which == 2) ? g_sd : (which == 3) ? g_fg : g_sg;
                            dst[(bb * Hq + h) * Lq + l] = val;
                        }
                    }
                } else {
                    *(float2*)(C + (size_t)r * 1024 + col) = make_float2(v0, v1);
                }
            }
        }
    }
}

// ---------------- K4: outer products + psi/surprise + chunk decay (fused) ---
__global__ __launch_bounds__(256) void outer_kernel()
{
    __shared__ float Ks[64 * 64];
    __shared__ float Vs[64 * 64];
    __shared__ float S2[64];
    __shared__ float fdm_s[128];
    __shared__ float sdm_s[128];
    const int bhn = blockIdx.x;
    const int bh = bhn / NCH, n = bhn % NCH;
    const int t = threadIdx.x;
    const int d0 = (t & 15) * 4;
    const int e0 = (t >> 4) * 4;
    const int posbase = bh * Lq + n * CH;

    float af[4][4], as_[4][4];
#pragma unroll
    for (int i = 0; i < 4; i++)
#pragma unroll
        for (int j = 0; j < 4; j++) { af[i][j] = 0.f; as_[i][j] = 0.f; }

    for (int half_ = 0; half_ < 2; half_++) {
        size_t base = ((size_t)(posbase + half_ * 64)) * HDq;
        for (int i = t; i < 1024; i += 256) {
            int row = i >> 4;
            float b = g_beta[posbase + half_ * 64 + row];
            float4 k4 = ((const float4*)(g_k + base))[i];
            float4 v4 = ((const float4*)(g_v + base))[i];
            k4.x *= b; k4.y *= b; k4.z *= b; k4.w *= b;
            v4.x *= b; v4.y *= b; v4.z *= b; v4.w *= b;
            ((float4*)Ks)[i] = k4;
            ((float4*)Vs)[i] = v4;
        }
        __syncthreads();

        {
            int r = t >> 2, q = t & 3;
            const float4* krow = (const float4*)&Ks[r * 64 + q * 16];
            const float4* vrow = (const float4*)&Vs[r * 64 + q * 16];
            float kk = 0.f, vv = 0.f, kv = 0.f;
#pragma unroll
            for (int j = 0; j < 4; j++) {
                float4 a = krow[j], b = vrow[j];
                kk += a.x * a.x + a.y * a.y + a.z * a.z + a.w * a.w;
                vv += b.x * b.x + b.y * b.y + b.z * b.z + b.w * b.w;
                kv += a.x * b.x + a.y * b.y + a.z * b.z + a.w * b.w;
            }
            kk += __shfl_xor_sync(0xffffffffu, kk, 1);
            kk += __shfl_xor_sync(0xffffffffu, kk, 2);
            vv += __shfl_xor_sync(0xffffffffu, vv, 1);
            vv += __shfl_xor_sync(0xffffffffu, vv, 2);
            kv += __shfl_xor_sync(0xffffffffu, kv, 1);
            kv += __shfl_xor_sync(0xffffffffu, kv, 2);
            if (q == 0) {
                float kn = sqrtf(kk) + 1e-8f;
                float vn = sqrtf(vv) + 1e-8f;
                float praw = fabsf(kv) / (kn * vn);
                float psi = sigm(3.f * praw);
                float sur = sigm((psi - 0.5f) * 10.f);
                S2[r] = sur * sur;
                int p = posbase + half_ * 64 + r;
                g_psi[p] = psi;
                fdm_s[half_ * 64 + r] = g_fd[p] * (1.f - 0.1f * psi);
                sdm_s[half_ * 64 + r] = g_sd[p] * (1.f - 0.05f * psi);
            }
        }
        __syncthreads();

#pragma unroll 4
        for (int l = 0; l < 64; l++) {
            float4 vv4 = *(float4*)&Vs[l * 64 + d0];
            float4 kk4 = *(float4*)&Ks[l * 64 + e0];
            float s2 = S2[l];
            float v[4] = {vv4.x, vv4.y, vv4.z, vv4.w};
            float k[4] = {kk4.x, kk4.y, kk4.z, kk4.w};
            float vs[4] = {v[0] * s2, v[1] * s2, v[2] * s2, v[3] * s2};
#pragma unroll
            for (int i = 0; i < 4; i++)
#pragma unroll
                for (int j = 0; j < 4; j++) {
                    af[i][j] += v[i] * k[j];
                    as_[i][j] += vs[i] * k[j];
                }
        }
        __syncthreads();
    }

    if (t < 32) {
        float f = 0.f, s = 0.f;
#pragma unroll
        for (int j = t; j < 128; j += 32) { f += fdm_s[j]; s += sdm_s[j]; }
#pragma unroll
        for (int off = 16; off; off >>= 1) {
            f += __shfl_xor_sync(0xffffffffu, f, off);
            s += __shfl_xor_sync(0xffffffffu, s, off);
        }
        if (t == 0) {
            float gf = f * (1.f / 128.f), gs = s * (1.f / 128.f);
#pragma unroll
            for (int i = 0; i < 7; i++) { gf *= gf; gs *= gs; }
            g_gf[bhn] = gf;
            g_gs[bhn] = gs;
        }
    }

    size_t abase = (size_t)bhn * 4096;
#pragma unroll
    for (int i = 0; i < 4; i++) {
        *(float4*)&g_Af[abase + (d0 + i) * 64 + e0] =
            make_float4(af[i][0], af[i][1], af[i][2], af[i][3]);
        *(float4*)&g_As[abase + (d0 + i) * 64 + e0] =
            make_float4(as_[i][0], as_[i][1], as_[i][2], as_[i][3]);
    }
}

// ---------------- K5: decayed prefix scan over chunks (in-place) ------------
__global__ void scan_kernel()
{
    int bh = blockIdx.x >> 4;
    int eb = blockIdx.x & 15;
    int entry = eb * 256 + threadIdx.x;
    float sfv = 0.f, ssv = 0.f;
#pragma unroll 1
    for (int n = 0; n < NCH; n++) {
        int bhn = bh * NCH + n;
        float gf = g_gf[bhn], gs = g_gs[bhn];
        size_t idx = (size_t)bhn * 4096 + entry;
        sfv = sfv * gf + g_Af[idx]; g_Af[idx] = sfv;
        ssv = ssv * gs + g_As[idx]; g_As[idx] = ssv;
    }
}

// ---------------- K6: O = Q @ S (fast+slow), gate/alpha mix -> omix (half) --
__global__ __launch_bounds__(256) void outmix_kernel()
{
    __shared__ float Sf[4096];
    __shared__ float Ss[4096];
    __shared__ float Qs[32 * 64];
    __shared__ float gA[32], gB[32];
    const int bhn = blockIdx.x;
    const int bh = bhn / NCH, n = bhn % NCH;
    const int b = bh >> 4, h = bh & 15;
    const int t = threadIdx.x;

    size_t abase = (size_t)bhn * 4096;
    for (int i = t; i < 1024; i += 256) {
        ((float4*)Sf)[i] = ((const float4*)(g_Af + abase))[i];
        ((float4*)Ss)[i] = ((const float4*)(g_As + abase))[i];
    }

    const int d = t & 63;
    const int lb = (t >> 6) * 8;

    for (int pass = 0; pass < 4; pass++) {
        int l0 = pass * 32;
        size_t qbase = ((size_t)bh * Lq + n * CH + l0) * HDq;
        for (int i = t; i < 512; i += 256)
            ((float4*)Qs)[i] = ((const float4*)(g_q + qbase))[i];
        if (t < 32) {
            int p = bh * Lq + n * CH + l0 + t;
            float psi = g_psi[p];
            float alpha = 0.5f + 0.3f * psi;
            gA[t] = alpha * g_fg[p];
            gB[t] = (1.f - alpha) * g_sg[p];
        }
        __syncthreads();

        float accf[8], accs[8];
#pragma unroll
        for (int l = 0; l < 8; l++) { accf[l] = 0.f; accs[l] = 0.f; }
#pragma unroll 8
        for (int e = 0; e < 64; e += 2) {
            float sf0 = Sf[e * 64 + d];
            float sf1 = Sf[(e + 1) * 64 + d];
            float ss0 = Ss[e * 64 + d];
            float ss1 = Ss[(e + 1) * 64 + d];
#pragma unroll
            for (int l = 0; l < 8; l++) {
                float2 q2 = *(float2*)&Qs[(lb + l) * 64 + e];
                accf[l] += q2.x * sf0 + q2.y * sf1;
                accs[l] += q2.x * ss0 + q2.y * ss1;
            }
        }
#pragma unroll
        for (int l = 0; l < 8; l++) {
            int ll = lb + l;
            float val = gA[ll] * accf[l] + gB[ll] * accs[l];
            int lglob = n * CH + l0 + ll;
            g_omixh[((size_t)b * Lq + lglob) * Dq + h * HDq + d] = __float2half_rn(val);
        }
        __syncthreads();
    }
}

// ---------------- launch ----------------
extern "C" void kernel_launch(void* const* d_in, const int* in_sizes, int n_in,
                              void* d_out, int out_size)
{
    const float* x   = (const float*)d_in[0];
    const float* Wq  = (const float*)d_in[1];
    const float* Wk  = (const float*)d_in[2];
    const float* Wv  = (const float*)d_in[3];
    const float* Wb  = (const float*)d_in[4];
    const float* Wfd = (const float*)d_in[5];
    const float* fdb = (const float*)d_in[6];
    const float* Wsd = (const float*)d_in[7];
    const float* sdb = (const float*)d_in[8];
    const float* Wfg = (const float*)d_in[9];
    const float* Wsg = (const float*)d_in[10];
    const float* Wo  = (const float*)d_in[11];
    float* out = (float*)d_out;

    void *p_q = nullptr, *p_k = nullptr, *p_v = nullptr;
    void *p_xh = nullptr, *p_wh = nullptr, *p_gwh = nullptr, *p_oh = nullptr;
    cudaGetSymbolAddress(&p_q, g_q);
    cudaGetSymbolAddress(&p_k, g_k);
    cudaGetSymbolAddress(&p_v, g_v);
    cudaGetSymbolAddress(&p_xh, g_xh);
    cudaGetSymbolAddress(&p_wh, g_wh);
    cudaGetSymbolAddress(&p_gwh, g_gwh);
    cudaGetSymbolAddress(&p_oh, g_omixh);

    cudaFuncSetAttribute(gemm_f16_kernel,
                         cudaFuncAttributeMaxDynamicSharedMemorySize, HSMEM);

    // K0: conversions & packing
    xhalf_kernel<<<4096, 256>>>(x);
    wtrans_kernel<<<dim3(32, 32, 4), dim3(32, 8)>>>(Wq, Wk, Wv, Wo);
    gwpack_kernel<<<512, 256>>>(Wb, Wfd, Wsd, Wfg, Wsg);

    // K1+K2: fused QKV + gate projections (1600 blocks)
    gemm_f16_kernel<<<1600, 256, HSMEM>>>(
        (const __half*)p_xh, (const __half*)p_wh, (const __half*)p_gwh,
        (float*)p_q, (float*)p_k, (float*)p_v, fdb, sdb, 0);

    // K4: fused outer products + psi/surprise + chunk decay
    outer_kernel<<<Bq * Hq * NCH, 256>>>();

    // K5: decayed scan across chunks
    scan_kernel<<<Bq * Hq * 16, 256>>>();

    // K6: per-chunk output + gate mixing (half omix)
    outmix_kernel<<<Bq * Hq * NCH, 256>>>();

    // K7: output projection (512 blocks, plain epilogue)
    gemm_f16_kernel<<<512, 256, HSMEM>>>(
        (const __half*)p_oh, (const __half*)p_wh + (size_t)3 * Dq * Dq,
        (const __half*)p_gwh, out, out, out, fdb, sdb, 1);
}